// round 11
// baseline (speedup 1.0000x reference)
#include <cuda_runtime.h>
#include <cuda_bf16.h>
#include <cuda_fp16.h>
#include <stdint.h>
#include <math.h>

#define NN 50000
#define EE 1600000
#define HH 128
#define BB 64
#define TT 4
#define GG 10
#define TAB 384
#define D_MAX 8.6603f
#define SCAN_B 1024
#define NBLK ((NN + SCAN_B - 1) / SCAN_B)

// scratch (static device globals — no runtime allocation)
static __device__ float g_table[2 * TAB * HH];
static __device__ float g_h[NN * HH];
static __device__ __half g_hh[NN * HH];      // fp16 shadow of h (GEMM A operand)
static __device__ __half g_xjh[NN * HH];
static __device__ float g_agg[NN * HH];
static __device__ float g_pooled[BB * HH];
static __device__ __half g_wt[7 * 16384];    // transposed fp16 weights
// CSR (dst-major)
static __device__ int  g_deg[NN];
static __device__ int  g_ptr[NN + 1];
static __device__ int  g_work[NN];
static __device__ int  g_bsum[NBLK];
static __device__ int2 g_csr[EE];            // {src | i0<<16, half2(f,f) bits}

#define WT_LIN1(i)  ((size_t)(i) * 16384)
#define WT_LIN2(i)  ((size_t)(32768) + (size_t)(i) * 16384)
#define WT_LIN(i)   ((size_t)(65536) + (size_t)(i) * 16384)
#define WT_OUT1     ((size_t)98304)
#define WT_OUT2     ((size_t)106496)

__device__ __forceinline__ float sspf(float x) {
    float ax = fabsf(x);
    return fmaxf(x, 0.0f) + log1pf(__expf(-ax)) - 0.6931471805599453f;
}

#define SWZ(off) ((off) ^ (((off) >> 3) & 0x70))

__device__ __forceinline__ unsigned smem_u32(const void* p) {
    return (unsigned)__cvta_generic_to_shared(p);
}
__device__ __forceinline__ void ldsm_x4(unsigned* r, unsigned addr) {
    asm volatile("ldmatrix.sync.aligned.m8n8.x4.shared.b16 {%0,%1,%2,%3}, [%4];"
                 : "=r"(r[0]), "=r"(r[1]), "=r"(r[2]), "=r"(r[3]) : "r"(addr));
}
__device__ __forceinline__ void ldsm_x2(unsigned* r, unsigned addr) {
    asm volatile("ldmatrix.sync.aligned.m8n8.x2.shared.b16 {%0,%1}, [%2];"
                 : "=r"(r[0]), "=r"(r[1]) : "r"(addr));
}
__device__ __forceinline__ void mma_fp16(float* d, const unsigned* a, const unsigned* b) {
    asm volatile("mma.sync.aligned.m16n8k16.row.col.f32.f16.f16.f32 "
                 "{%0,%1,%2,%3}, {%4,%5,%6,%7}, {%8,%9}, {%0,%1,%2,%3};"
                 : "+f"(d[0]), "+f"(d[1]), "+f"(d[2]), "+f"(d[3])
                 : "r"(a[0]), "r"(a[1]), "r"(a[2]), "r"(a[3]), "r"(b[0]), "r"(b[1]));
}

// ---------------------------------------------------------------------------
// Build filter table
// ---------------------------------------------------------------------------
__global__ void build_table_kernel(const float* __restrict__ w1, const float* __restrict__ b1,
                                   const float* __restrict__ w2, const float* __restrict__ b2) {
    int row = blockIdx.x;
    int inter = blockIdx.y;
    int tid = threadIdx.x;
    float d = row * (D_MAX / (float)(TAB - 1));

    __shared__ float hid[HH];
    const float* w1i = w1 + (size_t)inter * GG * HH;
    const float* b1i = b1 + (size_t)inter * HH;
    const float* w2i = w2 + (size_t)inter * HH * HH;
    const float* b2i = b2 + (size_t)inter * HH;

    const float step = 10.0f / 9.0f;
    const float coeff = -0.5f / (step * step);

    float acc = b1i[tid];
    #pragma unroll
    for (int g = 0; g < GG; g++) {
        float diff = d - (float)g * step;
        float r = expf(coeff * diff * diff);
        acc += r * w1i[g * HH + tid];
    }
    hid[tid] = sspf(acc);
    __syncthreads();

    float acc2 = b2i[tid];
    for (int k = 0; k < HH; k++)
        acc2 = fmaf(hid[k], w2i[k * HH + tid], acc2);

    float C = 0.5f * (cosf(d * 3.14159265358979f / 10.0f) + 1.0f);
    g_table[((size_t)inter * TAB + row) * HH + tid] = acc2 * C;
}

// ---------------------------------------------------------------------------
// Merged weight transpose + fp16 convert: 8 matrices in one launch (grid.y)
// ---------------------------------------------------------------------------
__global__ void transpose_all_kernel(const float* __restrict__ lin1_w,
                                     const float* __restrict__ lin2_w,
                                     const float* __restrict__ lin_w,
                                     const float* __restrict__ out1_w,
                                     const float* __restrict__ out2_w,
                                     __half* __restrict__ wt) {
    int m = blockIdx.y;
    const float* src;
    size_t off;
    int K, N;
    switch (m) {
        case 0: src = lin1_w;          off = WT_LIN1(0); K = 128; N = 128; break;
        case 1: src = lin1_w + 16384;  off = WT_LIN1(1); K = 128; N = 128; break;
        case 2: src = lin2_w;          off = WT_LIN2(0); K = 128; N = 128; break;
        case 3: src = lin2_w + 16384;  off = WT_LIN2(1); K = 128; N = 128; break;
        case 4: src = lin_w;           off = WT_LIN(0);  K = 128; N = 128; break;
        case 5: src = lin_w + 16384;   off = WT_LIN(1);  K = 128; N = 128; break;
        case 6: src = out1_w;          off = WT_OUT1;    K = 128; N = 64;  break;
        default: src = out2_w;         off = WT_OUT2;    K = 64;  N = 128; break;
    }
    int i = blockIdx.x * blockDim.x + threadIdx.x;
    if (i >= K * N) return;
    int k = i / N, n = i % N;
    wt[off + (size_t)n * K + k] = __float2half_rn(src[i]);
}

// ---------------------------------------------------------------------------
// Fused prep: embedding gather (fp32 + fp16 shadow) + zero deg + zero pooled
// ---------------------------------------------------------------------------
__global__ void prep_kernel(const int* __restrict__ z, const float* __restrict__ emb) {
    int idx = blockIdx.x * blockDim.x + threadIdx.x;
    if (idx < NN * (HH / 4)) {
        int n = idx >> 5;
        int c = idx & 31;
        float4 v = ((const float4*)emb)[(size_t)z[n] * (HH / 4) + c];
        ((float4*)g_h)[idx] = v;
        __half2 h0 = __floats2half2_rn(v.x, v.y);
        __half2 h1 = __floats2half2_rn(v.z, v.w);
        __half2 pk[2] = {h0, h1};
        ((uint2*)g_hh)[idx] = *(uint2*)pk;
    }
    if (idx < NN) g_deg[idx] = 0;
    if (idx < BB * HH) g_pooled[idx] = 0.f;
}

// ---------------------------------------------------------------------------
// CSR construction
// ---------------------------------------------------------------------------
__global__ void hist_kernel(const int* __restrict__ ei) {
    int i = blockIdx.x * blockDim.x + threadIdx.x;
    if (i >= EE / 4) return;
    int4 d4 = ((const int4*)(ei + EE))[i];
    atomicAdd(&g_deg[d4.x], 1);
    atomicAdd(&g_deg[d4.y], 1);
    atomicAdd(&g_deg[d4.z], 1);
    atomicAdd(&g_deg[d4.w], 1);
}

__global__ void scan1_kernel() {
    __shared__ int sm[SCAN_B];
    int idx = blockIdx.x * SCAN_B + threadIdx.x;
    int v = (idx < NN) ? g_deg[idx] : 0;
    sm[threadIdx.x] = v;
    __syncthreads();
    for (int off = SCAN_B / 2; off > 0; off >>= 1) {
        if (threadIdx.x < off) sm[threadIdx.x] += sm[threadIdx.x + off];
        __syncthreads();
    }
    if (threadIdx.x == 0) g_bsum[blockIdx.x] = sm[0];
}

__global__ void scan3_kernel() {
    __shared__ int sm[SCAN_B];
    __shared__ int blockoff;
    int idx = blockIdx.x * SCAN_B + threadIdx.x;
    int v = (idx < NN) ? g_deg[idx] : 0;
    sm[threadIdx.x] = v;
    if (threadIdx.x == 0) {
        int run = 0;
        for (int b = 0; b < blockIdx.x; b++) run += g_bsum[b];
        blockoff = run;
    }
    __syncthreads();
    for (int off = 1; off < SCAN_B; off <<= 1) {
        int add = (threadIdx.x >= off) ? sm[threadIdx.x - off] : 0;
        __syncthreads();
        sm[threadIdx.x] += add;
        __syncthreads();
    }
    if (idx < NN) {
        int excl = blockoff + sm[threadIdx.x] - v;
        g_ptr[idx] = excl;
        g_work[idx] = excl;
        if (idx == NN - 1) g_ptr[NN] = blockoff + sm[threadIdx.x];
    }
}

__global__ void fill_kernel(const int* __restrict__ ei, const float* __restrict__ pos) {
    int i = blockIdx.x * blockDim.x + threadIdx.x;
    if (i >= EE / 4) return;
    int4 s4 = ((const int4*)ei)[i];
    int4 d4 = ((const int4*)(ei + EE))[i];
    const float INV_STEP = (float)(TAB - 1) / D_MAX;
    #pragma unroll
    for (int q = 0; q < 4; q++) {
        int s = (&s4.x)[q];
        int d = (&d4.x)[q];
        float dx = pos[s * 3 + 0] - pos[d * 3 + 0];
        float dy = pos[s * 3 + 1] - pos[d * 3 + 1];
        float dz = pos[s * 3 + 2] - pos[d * 3 + 2];
        float dist = sqrtf(dx * dx + dy * dy + dz * dz);
        float t = dist * INV_STEP;
        int i0 = min((int)t, TAB - 2);
        float f = t - (float)i0;
        __half2 f2 = __float2half2_rn(f);
        int slot = atomicAdd(&g_work[d], 1);
        g_csr[slot] = make_int2(s | (i0 << 16), *(int*)&f2);
    }
}

// ---------------------------------------------------------------------------
// CSR edge aggregation: half2 products, pairwise half2 add, fp32 accumulation
// ---------------------------------------------------------------------------
#define EDGE_PROD(J, P0, P1) {                                                      \
    int cx  = __shfl_sync(0xffffffffu, c.x, (J));                                   \
    int cyi = __shfl_sync(0xffffffffu, c.y, (J));                                   \
    int s  = cx & 0xffff;                                                           \
    int i0 = cx >> 16;                                                              \
    __half2 f2 = *reinterpret_cast<__half2*>(&cyi);                                 \
    uint2 xw = *(const uint2*)(g_xjh + (size_t)s * HH + lane * 4);                  \
    __half2 x0 = *reinterpret_cast<__half2*>(&xw.x);                                \
    __half2 x1 = *reinterpret_cast<__half2*>(&xw.y);                                \
    const __half* t0 = tab + i0 * HH + lane * 4;                                    \
    uint2 w0w = *(const uint2*)t0;                                                  \
    uint2 w1w = *(const uint2*)(t0 + HH);                                           \
    __half2 w0a = *reinterpret_cast<__half2*>(&w0w.x);                              \
    __half2 w0b = *reinterpret_cast<__half2*>(&w0w.y);                              \
    __half2 w1a = *reinterpret_cast<__half2*>(&w1w.x);                              \
    __half2 w1b = *reinterpret_cast<__half2*>(&w1w.y);                              \
    P0 = __hmul2(__hfma2(__hsub2(w1a, w0a), f2, w0a), x0);                          \
    P1 = __hmul2(__hfma2(__hsub2(w1b, w0b), f2, w0b), x1);                          \
}

__global__ void __launch_bounds__(1024) edge_conv_csr_kernel(int inter) {
    extern __shared__ __half tab[];
    const float4* src_tab = (const float4*)(g_table + (size_t)inter * TAB * HH);
    for (int i = threadIdx.x; i < TAB * HH / 8; i += 1024) {
        float4 f0 = src_tab[i * 2];
        float4 f1 = src_tab[i * 2 + 1];
        __half2 hh[4];
        hh[0] = __floats2half2_rn(f0.x, f0.y);
        hh[1] = __floats2half2_rn(f0.z, f0.w);
        hh[2] = __floats2half2_rn(f1.x, f1.y);
        hh[3] = __floats2half2_rn(f1.z, f1.w);
        ((uint4*)tab)[i] = *(uint4*)hh;
    }
    __syncthreads();

    int lane = threadIdx.x & 31;
    int gwarp = blockIdx.x * 32 + (threadIdx.x >> 5);
    int nwarp = gridDim.x * 32;

    for (int node = gwarp; node < NN; node += nwarp) {
        int beg = __ldg(&g_ptr[node]);
        int end = __ldg(&g_ptr[node + 1]);

        float4 acc = make_float4(0.f, 0.f, 0.f, 0.f);
        int base = beg;
        for (; base + 32 <= end; base += 32) {
            int2 c = __ldg(&g_csr[base + lane]);
            #pragma unroll 4
            for (int j = 0; j < 32; j += 2) {
                __half2 a0, a1, b0, b1;
                EDGE_PROD(j, a0, a1);
                EDGE_PROD(j + 1, b0, b1);
                __half2 s0 = __hadd2(a0, b0);
                __half2 s1 = __hadd2(a1, b1);
                float2 f0 = __half22float2(s0);
                float2 f1 = __half22float2(s1);
                acc.x += f0.x; acc.y += f0.y; acc.z += f1.x; acc.w += f1.y;
            }
        }
        if (base < end) {
            int k = base + lane;
            int2 c = (k < end) ? __ldg(&g_csr[k]) : make_int2(0, 0);
            int cnt = end - base;
            for (int j = 0; j < cnt; j++) {
                __half2 p0, p1;
                EDGE_PROD(j, p0, p1);
                float2 f0 = __half22float2(p0);
                float2 f1 = __half22float2(p1);
                acc.x += f0.x; acc.y += f0.y; acc.z += f1.x; acc.w += f1.y;
            }
        }
        *(float4*)(g_agg + (size_t)node * HH + lane * 4) = acc;
    }
}

// ---------------------------------------------------------------------------
// Pair epilogue (HHCOPY also mirrors result into g_hh fp16)
// ---------------------------------------------------------------------------
template <int NCOL, bool BIAS, bool ACT, bool RESID, bool POOL, bool OFP16, bool HHCOPY>
__device__ __forceinline__ void epi2(int row, int col, float v0, float v1,
                                     const float* __restrict__ bias, void* outv,
                                     const int* __restrict__ batch) {
    if (row >= NN) return;
    if (BIAS) { v0 += bias[col]; v1 += bias[col + 1]; }
    if (ACT)  { v0 = sspf(v0); v1 = sspf(v1); }
    if (POOL) {
        int b = batch[row];
        float* p = g_pooled + (size_t)b * NCOL + col;
        asm volatile("red.global.add.v2.f32 [%0], {%1,%2};" :: "l"(p), "f"(v0), "f"(v1) : "memory");
    } else if (OFP16) {
        __half2 pk = __floats2half2_rn(v0, v1);
        *(unsigned*)((__half*)outv + (size_t)row * NCOL + col) = *(unsigned*)&pk;
    } else {
        float* o = (float*)outv + (size_t)row * NCOL + col;
        if (RESID) {
            float2 h = *(float2*)o;
            v0 += h.x; v1 += h.y;
        }
        *(float2*)o = make_float2(v0, v1);
        if (HHCOPY) {
            __half2 pk = __floats2half2_rn(v0, v1);
            *(unsigned*)(g_hh + (size_t)row * NCOL + col) = *(unsigned*)&pk;
        }
    }
}

// ---------------------------------------------------------------------------
// fp16 tensor-core GEMM, single-stage K=128 (A already fp16): out = A @ Wt^T
// A and B staged as two 64-K panels of 16KB each (SW128 within panel).
// ---------------------------------------------------------------------------
template <int NCOL, bool OFP16>
__global__ void __launch_bounds__(256, 2)
mma_gemm16_kernel(const __half* __restrict__ A,
                  const __half* __restrict__ Wt,
                  void* outv) {
    constexpr int KDIM = 128;
    constexpr int WN = NCOL / 2;
    constexpr int NT = WN / 8;
    constexpr int PANEL = 16384;

    extern __shared__ char dynsm[];
    char* As = dynsm;                  // 2 panels = 32KB
    char* Bs = dynsm + 2 * PANEL;      // 2 panels = NCOL*128*2*... (for NCOL=128: 32KB)

    int tid = threadIdx.x;
    int warp = tid >> 5, lane = tid & 31;
    int wm = warp & 3, wn = warp >> 2;
    int row0 = blockIdx.x * 128;

    float acc[2][NT][4];
    #pragma unroll
    for (int mt = 0; mt < 2; mt++)
        #pragma unroll
        for (int nt = 0; nt < NT; nt++)
            #pragma unroll
            for (int q = 0; q < 4; q++) acc[mt][nt][q] = 0.f;

    unsigned as_base = smem_u32(As);
    unsigned bs_base = smem_u32(Bs);

    // stage A: 128 rows x 16 chunks (8 halves each)
    #pragma unroll
    for (int i = tid; i < 128 * 16; i += 256) {
        int r = i >> 4, ch = i & 15;
        int grow = row0 + r;
        uint4 v = make_uint4(0, 0, 0, 0);
        if (grow < NN)
            v = *(const uint4*)(A + (size_t)grow * KDIM + ch * 8);
        *(uint4*)(As + (ch >> 3) * PANEL + SWZ(r * 128 + (ch & 7) * 16)) = v;
    }
    // stage B: NCOL rows x 16 chunks
    #pragma unroll
    for (int i = tid; i < NCOL * 16; i += 256) {
        int r = i >> 4, ch = i & 15;
        uint4 v = *(const uint4*)(Wt + (size_t)r * KDIM + ch * 8);
        *(uint4*)(Bs + (ch >> 3) * PANEL + SWZ(r * 128 + (ch & 7) * 16)) = v;
    }
    __syncthreads();

    #pragma unroll
    for (int ks = 0; ks < 8; ks++) {
        int poff = (ks >> 2) * PANEL;
        int koff = (ks & 3) * 32;
        unsigned a[2][4];
        #pragma unroll
        for (int mt = 0; mt < 2; mt++) {
            int r = wm * 32 + mt * 16 + (lane & 15);
            ldsm_x4(a[mt], as_base + poff + SWZ(r * 128 + koff + (lane >> 4) * 16));
        }
        #pragma unroll
        for (int nt = 0; nt < NT; nt++) {
            unsigned b[2];
            int l = lane & 15;
            int r = wn * WN + nt * 8 + (l & 7);
            ldsm_x2(b, bs_base + poff + SWZ(r * 128 + koff + ((l >> 3) & 1) * 16));
            mma_fp16(acc[0][nt], a[0], b);
            mma_fp16(acc[1][nt], a[1], b);
        }
    }

    #pragma unroll
    for (int mt = 0; mt < 2; mt++) {
        #pragma unroll
        for (int nt = 0; nt < NT; nt++) {
            int r = row0 + wm * 32 + mt * 16 + (lane >> 2);
            int c = wn * WN + nt * 8 + (lane & 3) * 2;
            epi2<NCOL, false, false, false, false, OFP16, false>(r, c, acc[mt][nt][0], acc[mt][nt][1], nullptr, outv, nullptr);
            epi2<NCOL, false, false, false, false, OFP16, false>(r + 8, c, acc[mt][nt][2], acc[mt][nt][3], nullptr, outv, nullptr);
        }
    }
}

// ---------------------------------------------------------------------------
// Fused two-GEMM chain: T = ssp(A@W1 + b1); out2 = T@W2 + b2
// AFP16: A is already fp16.  POOL2: pool epilogue; else residual h update (+hh copy)
// ---------------------------------------------------------------------------
template <int K1, int N1, int N2, bool POOL2, bool AFP16>
__global__ void __launch_bounds__(256, 2)
fused2_kernel(const void* __restrict__ Av,
              const __half* __restrict__ W1, const float* __restrict__ b1,
              const __half* __restrict__ W2, const float* __restrict__ b2,
              float* __restrict__ outh, const int* __restrict__ batch) {
    constexpr int WN1 = N1 / 2, NT1 = WN1 / 8;
    constexpr int WN2 = N2 / 2, NT2 = WN2 / 8;
    constexpr int A_B = 128 * 64 * 2;   // 16384
    constexpr int B_B = 16384;
    constexpr int PANEL = 128 * 64 * 2; // 16384

    extern __shared__ char dynsm[];
    char* As = dynsm;
    char* Bs = dynsm + A_B;
    char* Ts = dynsm + A_B + B_B;

    int tid = threadIdx.x;
    int warp = tid >> 5, lane = tid & 31;
    int wm = warp & 3, wn = warp >> 2;
    int row0 = blockIdx.x * 128;

    unsigned as_base = smem_u32(As);
    unsigned bs_base = smem_u32(Bs);
    unsigned ts_base = smem_u32(Ts);

    // ---------------- stage 1: acc1 = A @ W1 ----------------
    float acc1[2][NT1][4];
    #pragma unroll
    for (int mt = 0; mt < 2; mt++)
        #pragma unroll
        for (int nt = 0; nt < NT1; nt++)
            #pragma unroll
            for (int q = 0; q < 4; q++) acc1[mt][nt][q] = 0.f;

    for (int k0 = 0; k0 < K1; k0 += 64) {
        #pragma unroll
        for (int i = tid; i < 128 * 8; i += 256) {
            int r = i >> 3, ch = i & 7;
            int grow = row0 + r;
            if (AFP16) {
                uint4 v = make_uint4(0, 0, 0, 0);
                if (grow < NN)
                    v = *(const uint4*)((const __half*)Av + (size_t)grow * K1 + k0 + ch * 8);
                *(uint4*)(As + SWZ(r * 128 + ch * 16)) = v;
            } else {
                float v[8] = {0.f, 0.f, 0.f, 0.f, 0.f, 0.f, 0.f, 0.f};
                if (grow < NN) {
                    const float* gp = (const float*)Av + (size_t)grow * K1 + k0 + ch * 8;
                    float4 f0 = *(const float4*)gp;
                    float4 f1 = *(const float4*)(gp + 4);
                    v[0] = f0.x; v[1] = f0.y; v[2] = f0.z; v[3] = f0.w;
                    v[4] = f1.x; v[5] = f1.y; v[6] = f1.z; v[7] = f1.w;
                }
                __half2 hh[4];
                #pragma unroll
                for (int q = 0; q < 4; q++) hh[q] = __floats2half2_rn(v[2 * q], v[2 * q + 1]);
                *(uint4*)(As + SWZ(r * 128 + ch * 16)) = *(uint4*)hh;
            }
        }
        #pragma unroll
        for (int i = tid; i < N1 * 8; i += 256) {
            int r = i >> 3, ch = i & 7;
            uint4 w = *(const uint4*)(W1 + (size_t)r * K1 + k0 + ch * 8);
            *(uint4*)(Bs + SWZ(r * 128 + ch * 16)) = w;
        }
        __syncthreads();

        #pragma unroll
        for (int ks = 0; ks < 4; ks++) {
            unsigned a[2][4];
            #pragma unroll
            for (int mt = 0; mt < 2; mt++) {
                int r = wm * 32 + mt * 16 + (lane & 15);
                ldsm_x4(a[mt], as_base + SWZ(r * 128 + ks * 32 + (lane >> 4) * 16));
            }
            #pragma unroll
            for (int nt = 0; nt < NT1; nt++) {
                unsigned b[2];
                int l = lane & 15;
                int r = wn * WN1 + nt * 8 + (l & 7);
                ldsm_x2(b, bs_base + SWZ(r * 128 + ks * 32 + ((l >> 3) & 1) * 16));
                mma_fp16(acc1[0][nt], a[0], b);
                mma_fp16(acc1[1][nt], a[1], b);
            }
        }
        __syncthreads();
    }

    // epilogue 1: T = ssp(acc1 + b1) -> fp16 into Ts panels
    #pragma unroll
    for (int mt = 0; mt < 2; mt++) {
        #pragma unroll
        for (int nt = 0; nt < NT1; nt++) {
            int c = wn * WN1 + nt * 8 + (lane & 3) * 2;
            int panel_off = (c >> 6) * PANEL;
            int kk2 = (c & 63) * 2;
            #pragma unroll
            for (int half = 0; half < 2; half++) {
                int rl = wm * 32 + mt * 16 + (lane >> 2) + half * 8;
                float v0 = sspf(acc1[mt][nt][half * 2 + 0] + b1[c]);
                float v1 = sspf(acc1[mt][nt][half * 2 + 1] + b1[c + 1]);
                __half2 pk = __floats2half2_rn(v0, v1);
                *(unsigned*)(Ts + panel_off + SWZ(rl * 128 + kk2)) = *(unsigned*)&pk;
            }
        }
    }
    __syncthreads();

    // ---------------- stage 2: out = T @ W2 ----------------
    float acc2[2][NT2][4];
    #pragma unroll
    for (int mt = 0; mt < 2; mt++)
        #pragma unroll
        for (int nt = 0; nt < NT2; nt++)
            #pragma unroll
            for (int q = 0; q < 4; q++) acc2[mt][nt][q] = 0.f;

    for (int k0 = 0; k0 < N1; k0 += 64) {
        #pragma unroll
        for (int i = tid; i < N2 * 8; i += 256) {
            int r = i >> 3, ch = i & 7;
            uint4 w = *(const uint4*)(W2 + (size_t)r * N1 + k0 + ch * 8);
            *(uint4*)(Bs + SWZ(r * 128 + ch * 16)) = w;
        }
        __syncthreads();

        int panel_off = (k0 >> 6) * PANEL;
        #pragma unroll
        for (int ks = 0; ks < 4; ks++) {
            unsigned a[2][4];
            #pragma unroll
            for (int mt = 0; mt < 2; mt++) {
                int r = wm * 32 + mt * 16 + (lane & 15);
                ldsm_x4(a[mt], ts_base + panel_off + SWZ(r * 128 + ks * 32 + (lane >> 4) * 16));
            }
            #pragma unroll
            for (int nt = 0; nt < NT2; nt++) {
                unsigned b[2];
                int l = lane & 15;
                int r = wn * WN2 + nt * 8 + (l & 7);
                ldsm_x2(b, bs_base + SWZ(r * 128 + ks * 32 + ((l >> 3) & 1) * 16));
                mma_fp16(acc2[0][nt], a[0], b);
                mma_fp16(acc2[1][nt], a[1], b);
            }
        }
        __syncthreads();
    }

    #pragma unroll
    for (int mt = 0; mt < 2; mt++) {
        #pragma unroll
        for (int nt = 0; nt < NT2; nt++) {
            int r = row0 + wm * 32 + mt * 16 + (lane >> 2);
            int c = wn * WN2 + nt * 8 + (lane & 3) * 2;
            epi2<N2, true, false, !POOL2, POOL2, false, !POOL2>(r, c, acc2[mt][nt][0], acc2[mt][nt][1], b2, outh, batch);
            epi2<N2, true, false, !POOL2, POOL2, false, !POOL2>(r + 8, c, acc2[mt][nt][2], acc2[mt][nt][3], b2, outh, batch);
        }
    }
}

// ---------------------------------------------------------------------------
// Final tiny GEMM
// ---------------------------------------------------------------------------
__global__ void final_kernel(const float* __restrict__ pw, const float* __restrict__ pb,
                             float* __restrict__ out) {
    int tid = threadIdx.x;
    int b = tid >> 2;
    int t = tid & 3;
    float acc = pb[t];
    for (int k = 0; k < HH; k++)
        acc = fmaf(g_pooled[b * HH + k], pw[k * TT + t], acc);
    out[b * TT + t] = acc;
}

// ---------------------------------------------------------------------------
extern "C" void kernel_launch(void* const* d_in, const int* in_sizes, int n_in,
                              void* d_out, int out_size) {
    const int*   z       = (const int*)d_in[0];
    const float* pos     = (const float*)d_in[1];
    const int*   batch   = (const int*)d_in[2];
    const int*   ei      = (const int*)d_in[3];
    const float* emb     = (const float*)d_in[4];
    const float* mlp_w1  = (const float*)d_in[5];
    const float* mlp_b1  = (const float*)d_in[6];
    const float* mlp_w2  = (const float*)d_in[7];
    const float* mlp_b2  = (const float*)d_in[8];
    const float* lin1_w  = (const float*)d_in[9];
    const float* lin2_w  = (const float*)d_in[10];
    const float* lin2_b  = (const float*)d_in[11];
    const float* lin_w   = (const float*)d_in[12];
    const float* lin_b   = (const float*)d_in[13];
    const float* out1_w  = (const float*)d_in[14];
    const float* out1_b  = (const float*)d_in[15];
    const float* out2_w  = (const float*)d_in[16];
    const float* out2_b  = (const float*)d_in[17];
    const float* pred_w  = (const float*)d_in[18];
    const float* pred_b  = (const float*)d_in[19];
    float* out = (float*)d_out;

    float *p_h, *p_agg;
    void *p_xjh, *p_hh;
    __half* p_wt;
    cudaGetSymbolAddress((void**)&p_h, g_h);
    cudaGetSymbolAddress(&p_hh, g_hh);
    cudaGetSymbolAddress(&p_xjh, g_xjh);
    cudaGetSymbolAddress((void**)&p_agg, g_agg);
    cudaGetSymbolAddress((void**)&p_wt, g_wt);

    int dev = 0, smCount = 148;
    cudaGetDevice(&dev);
    cudaDeviceGetAttribute(&smCount, cudaDevAttrMultiProcessorCount, dev);

    const int TAB_SMEM = TAB * HH * (int)sizeof(__half);   // 98304
    cudaFuncSetAttribute(edge_conv_csr_kernel, cudaFuncAttributeMaxDynamicSharedMemorySize, TAB_SMEM);

    const int SM_G16 = 65536;                       // A 32KB + B 32KB
    const int SM_FA  = 16384 + 16384 + 32768;       // 65536 (N1=128)
    const int SM_FB  = 16384 + 16384 + 16384;       // 49152 (N1=64)
    cudaFuncSetAttribute(mma_gemm16_kernel<128, true>,
                         cudaFuncAttributeMaxDynamicSharedMemorySize, SM_G16);
    cudaFuncSetAttribute(fused2_kernel<128, 128, 128, false, false>,
                         cudaFuncAttributeMaxDynamicSharedMemorySize, SM_FA);
    cudaFuncSetAttribute(fused2_kernel<128, 64, 128, true, true>,
                         cudaFuncAttributeMaxDynamicSharedMemorySize, SM_FB);

    int gblocks = (NN + 127) / 128;

    // prep
    dim3 tg(64, 8);
    transpose_all_kernel<<<tg, 256>>>(lin1_w, lin2_w, lin_w, out1_w, out2_w, p_wt);
    prep_kernel<<<(NN * 32 + 255) / 256, 256>>>(z, emb);
    dim3 tb(TAB, 2);
    build_table_kernel<<<tb, HH>>>(mlp_w1, mlp_b1, mlp_w2, mlp_b2);
    mma_gemm16_kernel<128, true><<<gblocks, 256, SM_G16>>>(
        (const __half*)p_hh, p_wt + WT_LIN1(0), p_xjh);
    hist_kernel<<<(EE / 4 + 255) / 256, 256>>>(ei);
    scan1_kernel<<<NBLK, SCAN_B>>>();
    scan3_kernel<<<NBLK, SCAN_B>>>();
    fill_kernel<<<(EE / 4 + 255) / 256, 256>>>(ei, pos);

    for (int i = 0; i < 2; i++) {
        if (i > 0) {
            mma_gemm16_kernel<128, true><<<gblocks, 256, SM_G16>>>(
                (const __half*)p_hh, p_wt + WT_LIN1(i), p_xjh);
        }
        edge_conv_csr_kernel<<<smCount, 1024, TAB_SMEM>>>(i);
        fused2_kernel<128, 128, 128, false, false><<<gblocks, 256, SM_FA>>>(
            p_agg,
            p_wt + WT_LIN2(i), lin2_b + (size_t)i * HH,
            p_wt + WT_LIN(i),  lin_b + (size_t)i * HH,
            p_h, nullptr);
    }

    fused2_kernel<128, 64, 128, true, true><<<gblocks, 256, SM_FB>>>(
        p_hh,
        p_wt + WT_OUT1, out1_b,
        p_wt + WT_OUT2, out2_b,
        nullptr, batch);
    final_kernel<<<1, 256>>>(pred_w, pred_b, out);
}

// round 12
// speedup vs baseline: 1.0569x; 1.0569x over previous
#include <cuda_runtime.h>
#include <cuda_bf16.h>
#include <cuda_fp16.h>
#include <stdint.h>
#include <math.h>

#define NN 50000
#define EE 1600000
#define HH 128
#define BB 64
#define TT 4
#define GG 10
#define TAB 192
#define D_MAX 8.6603f
#define SCAN_B 1024
#define NBLK ((NN + SCAN_B - 1) / SCAN_B)

// scratch (static device globals — no runtime allocation)
static __device__ float g_table[TAB * HH * 2];   // fp32 master table (2 interactions)
static __device__ float g_h[NN * HH];
static __device__ __half g_hh[NN * HH];          // fp16 shadow of h (GEMM A operand)
static __device__ __half g_xjh[NN * HH];
static __device__ __half g_aggh[NN * HH];        // fp16 agg (GEMM A operand)
static __device__ float g_pooled[BB * HH];
static __device__ __half g_wt[7 * 16384];        // transposed fp16 weights
// CSR (dst-major)
static __device__ int  g_deg[NN];
static __device__ int  g_ptr[NN + 1];
static __device__ int  g_work[NN];
static __device__ int  g_bsum[NBLK];
static __device__ int2 g_csr[EE];                // {src | i0<<16, half2(f,f) bits}

#define WT_LIN1(i)  ((size_t)(i) * 16384)
#define WT_LIN2(i)  ((size_t)(32768) + (size_t)(i) * 16384)
#define WT_LIN(i)   ((size_t)(65536) + (size_t)(i) * 16384)
#define WT_OUT1     ((size_t)98304)
#define WT_OUT2     ((size_t)106496)

__device__ __forceinline__ float sspf(float x) {
    float ax = fabsf(x);
    return fmaxf(x, 0.0f) + log1pf(__expf(-ax)) - 0.6931471805599453f;
}

#define SWZ(off) ((off) ^ (((off) >> 3) & 0x70))

__device__ __forceinline__ unsigned smem_u32(const void* p) {
    return (unsigned)__cvta_generic_to_shared(p);
}
__device__ __forceinline__ void ldsm_x4(unsigned* r, unsigned addr) {
    asm volatile("ldmatrix.sync.aligned.m8n8.x4.shared.b16 {%0,%1,%2,%3}, [%4];"
                 : "=r"(r[0]), "=r"(r[1]), "=r"(r[2]), "=r"(r[3]) : "r"(addr));
}
__device__ __forceinline__ void ldsm_x2(unsigned* r, unsigned addr) {
    asm volatile("ldmatrix.sync.aligned.m8n8.x2.shared.b16 {%0,%1}, [%2];"
                 : "=r"(r[0]), "=r"(r[1]) : "r"(addr));
}
__device__ __forceinline__ void mma_fp16(float* d, const unsigned* a, const unsigned* b) {
    asm volatile("mma.sync.aligned.m16n8k16.row.col.f32.f16.f16.f32 "
                 "{%0,%1,%2,%3}, {%4,%5,%6,%7}, {%8,%9}, {%0,%1,%2,%3};"
                 : "+f"(d[0]), "+f"(d[1]), "+f"(d[2]), "+f"(d[3])
                 : "r"(a[0]), "r"(a[1]), "r"(a[2]), "r"(a[3]), "r"(b[0]), "r"(b[1]));
}

// ---------------------------------------------------------------------------
// Build filter table (fp32 master, TAB=192 knots)
// ---------------------------------------------------------------------------
__global__ void build_table_kernel(const float* __restrict__ w1, const float* __restrict__ b1,
                                   const float* __restrict__ w2, const float* __restrict__ b2) {
    int row = blockIdx.x;
    int inter = blockIdx.y;
    int tid = threadIdx.x;
    float d = row * (D_MAX / (float)(TAB - 1));

    __shared__ float hid[HH];
    const float* w1i = w1 + (size_t)inter * GG * HH;
    const float* b1i = b1 + (size_t)inter * HH;
    const float* w2i = w2 + (size_t)inter * HH * HH;
    const float* b2i = b2 + (size_t)inter * HH;

    const float step = 10.0f / 9.0f;
    const float coeff = -0.5f / (step * step);

    float acc = b1i[tid];
    #pragma unroll
    for (int g = 0; g < GG; g++) {
        float diff = d - (float)g * step;
        float r = expf(coeff * diff * diff);
        acc += r * w1i[g * HH + tid];
    }
    hid[tid] = sspf(acc);
    __syncthreads();

    float acc2 = b2i[tid];
    for (int k = 0; k < HH; k++)
        acc2 = fmaf(hid[k], w2i[k * HH + tid], acc2);

    float C = 0.5f * (cosf(d * 3.14159265358979f / 10.0f) + 1.0f);
    g_table[((size_t)inter * TAB + row) * HH + tid] = acc2 * C;
}

// ---------------------------------------------------------------------------
// Merged weight transpose + fp16 convert
// ---------------------------------------------------------------------------
__global__ void transpose_all_kernel(const float* __restrict__ lin1_w,
                                     const float* __restrict__ lin2_w,
                                     const float* __restrict__ lin_w,
                                     const float* __restrict__ out1_w,
                                     const float* __restrict__ out2_w,
                                     __half* __restrict__ wt) {
    int m = blockIdx.y;
    const float* src;
    size_t off;
    int K, N;
    switch (m) {
        case 0: src = lin1_w;          off = WT_LIN1(0); K = 128; N = 128; break;
        case 1: src = lin1_w + 16384;  off = WT_LIN1(1); K = 128; N = 128; break;
        case 2: src = lin2_w;          off = WT_LIN2(0); K = 128; N = 128; break;
        case 3: src = lin2_w + 16384;  off = WT_LIN2(1); K = 128; N = 128; break;
        case 4: src = lin_w;           off = WT_LIN(0);  K = 128; N = 128; break;
        case 5: src = lin_w + 16384;   off = WT_LIN(1);  K = 128; N = 128; break;
        case 6: src = out1_w;          off = WT_OUT1;    K = 128; N = 64;  break;
        default: src = out2_w;         off = WT_OUT2;    K = 64;  N = 128; break;
    }
    int i = blockIdx.x * blockDim.x + threadIdx.x;
    if (i >= K * N) return;
    int k = i / N, n = i % N;
    wt[off + (size_t)n * K + k] = __float2half_rn(src[i]);
}

// ---------------------------------------------------------------------------
// Fused prep: embedding gather (fp32 + fp16 shadow) + zero deg + zero pooled
// ---------------------------------------------------------------------------
__global__ void prep_kernel(const int* __restrict__ z, const float* __restrict__ emb) {
    int idx = blockIdx.x * blockDim.x + threadIdx.x;
    if (idx < NN * (HH / 4)) {
        int n = idx >> 5;
        int c = idx & 31;
        float4 v = ((const float4*)emb)[(size_t)z[n] * (HH / 4) + c];
        ((float4*)g_h)[idx] = v;
        __half2 pk[2] = {__floats2half2_rn(v.x, v.y), __floats2half2_rn(v.z, v.w)};
        ((uint2*)g_hh)[idx] = *(uint2*)pk;
    }
    if (idx < NN) g_deg[idx] = 0;
    if (idx < BB * HH) g_pooled[idx] = 0.f;
}

// ---------------------------------------------------------------------------
// CSR construction
// ---------------------------------------------------------------------------
__global__ void hist_kernel(const int* __restrict__ ei) {
    int i = blockIdx.x * blockDim.x + threadIdx.x;
    if (i >= EE / 4) return;
    int4 d4 = ((const int4*)(ei + EE))[i];
    atomicAdd(&g_deg[d4.x], 1);
    atomicAdd(&g_deg[d4.y], 1);
    atomicAdd(&g_deg[d4.z], 1);
    atomicAdd(&g_deg[d4.w], 1);
}

__global__ void scan1_kernel() {
    __shared__ int sm[SCAN_B];
    int idx = blockIdx.x * SCAN_B + threadIdx.x;
    int v = (idx < NN) ? g_deg[idx] : 0;
    sm[threadIdx.x] = v;
    __syncthreads();
    for (int off = SCAN_B / 2; off > 0; off >>= 1) {
        if (threadIdx.x < off) sm[threadIdx.x] += sm[threadIdx.x + off];
        __syncthreads();
    }
    if (threadIdx.x == 0) g_bsum[blockIdx.x] = sm[0];
}

__global__ void scan3_kernel() {
    __shared__ int sm[SCAN_B];
    __shared__ int blockoff;
    int idx = blockIdx.x * SCAN_B + threadIdx.x;
    int v = (idx < NN) ? g_deg[idx] : 0;
    sm[threadIdx.x] = v;
    if (threadIdx.x == 0) {
        int run = 0;
        for (int b = 0; b < blockIdx.x; b++) run += g_bsum[b];
        blockoff = run;
    }
    __syncthreads();
    for (int off = 1; off < SCAN_B; off <<= 1) {
        int add = (threadIdx.x >= off) ? sm[threadIdx.x - off] : 0;
        __syncthreads();
        sm[threadIdx.x] += add;
        __syncthreads();
    }
    if (idx < NN) {
        int excl = blockoff + sm[threadIdx.x] - v;
        g_ptr[idx] = excl;
        g_work[idx] = excl;
        if (idx == NN - 1) g_ptr[NN] = blockoff + sm[threadIdx.x];
    }
}

__global__ void fill_kernel(const int* __restrict__ ei, const float* __restrict__ pos) {
    int i = blockIdx.x * blockDim.x + threadIdx.x;
    if (i >= EE / 4) return;
    int4 s4 = ((const int4*)ei)[i];
    int4 d4 = ((const int4*)(ei + EE))[i];
    const float INV_STEP = (float)(TAB - 1) / D_MAX;
    #pragma unroll
    for (int q = 0; q < 4; q++) {
        int s = (&s4.x)[q];
        int d = (&d4.x)[q];
        float dx = pos[s * 3 + 0] - pos[d * 3 + 0];
        float dy = pos[s * 3 + 1] - pos[d * 3 + 1];
        float dz = pos[s * 3 + 2] - pos[d * 3 + 2];
        float dist = sqrtf(dx * dx + dy * dy + dz * dz);
        float t = dist * INV_STEP;
        int i0 = min((int)t, TAB - 2);
        float f = t - (float)i0;
        __half2 f2 = __float2half2_rn(f);
        int slot = atomicAdd(&g_work[d], 1);
        g_csr[slot] = make_int2(s | (i0 << 16), *(int*)&f2);
    }
}

// ---------------------------------------------------------------------------
// CSR edge aggregation: pair-interleaved fp16 table (one LDS.128 per edge),
// half2 math, fp32 accumulation, fp16 agg output.
// Smem entry i (512B): 32 chunks of 16B = {w_i[4 cols] , w_{i+1}[4 cols]}
// ---------------------------------------------------------------------------
#define EDGE_PROD(J, P0, P1) {                                                      \
    int cx  = __shfl_sync(0xffffffffu, c.x, (J));                                   \
    int cyi = __shfl_sync(0xffffffffu, c.y, (J));                                   \
    int s  = cx & 0xffff;                                                           \
    int i0 = cx >> 16;                                                              \
    __half2 f2 = *reinterpret_cast<__half2*>(&cyi);                                 \
    uint2 xw = *(const uint2*)(g_xjh + (size_t)s * HH + lane * 4);                  \
    __half2 x0 = *reinterpret_cast<__half2*>(&xw.x);                                \
    __half2 x1 = *reinterpret_cast<__half2*>(&xw.y);                                \
    uint4 wv = *(const uint4*)(tab + i0 * 256 + lane * 8);                          \
    __half2 w0a = *reinterpret_cast<__half2*>(&wv.x);                               \
    __half2 w0b = *reinterpret_cast<__half2*>(&wv.y);                               \
    __half2 w1a = *reinterpret_cast<__half2*>(&wv.z);                               \
    __half2 w1b = *reinterpret_cast<__half2*>(&wv.w);                               \
    P0 = __hmul2(__hfma2(__hsub2(w1a, w0a), f2, w0a), x0);                          \
    P1 = __hmul2(__hfma2(__hsub2(w1b, w0b), f2, w0b), x1);                          \
}

__global__ void __launch_bounds__(1024) edge_conv_csr_kernel(int inter) {
    extern __shared__ __half tab[];
    // build interleaved table: chunk c -> entry i = c>>5, colgroup g = c&31
    const float4* tsrc = (const float4*)(g_table + (size_t)inter * TAB * HH);
    for (int cch = threadIdx.x; cch < TAB * 32; cch += 1024) {
        int i = cch >> 5, g = cch & 31;
        int i1 = min(i + 1, TAB - 1);
        float4 r0 = tsrc[i * 32 + g];
        float4 r1 = tsrc[i1 * 32 + g];
        __half2 hh[4];
        hh[0] = __floats2half2_rn(r0.x, r0.y);
        hh[1] = __floats2half2_rn(r0.z, r0.w);
        hh[2] = __floats2half2_rn(r1.x, r1.y);
        hh[3] = __floats2half2_rn(r1.z, r1.w);
        ((uint4*)tab)[cch] = *(uint4*)hh;
    }
    __syncthreads();

    int lane = threadIdx.x & 31;
    int gwarp = blockIdx.x * 32 + (threadIdx.x >> 5);
    int nwarp = gridDim.x * 32;

    for (int node = gwarp; node < NN; node += nwarp) {
        int beg = __ldg(&g_ptr[node]);
        int end = __ldg(&g_ptr[node + 1]);

        float4 acc = make_float4(0.f, 0.f, 0.f, 0.f);
        int base = beg;
        for (; base + 32 <= end; base += 32) {
            int2 c = __ldg(&g_csr[base + lane]);
            #pragma unroll 4
            for (int j = 0; j < 32; j += 2) {
                __half2 a0, a1, b0, b1;
                EDGE_PROD(j, a0, a1);
                EDGE_PROD(j + 1, b0, b1);
                __half2 s0 = __hadd2(a0, b0);
                __half2 s1 = __hadd2(a1, b1);
                float2 f0 = __half22float2(s0);
                float2 f1 = __half22float2(s1);
                acc.x += f0.x; acc.y += f0.y; acc.z += f1.x; acc.w += f1.y;
            }
        }
        if (base < end) {
            int k = base + lane;
            int2 c = (k < end) ? __ldg(&g_csr[k]) : make_int2(0, 0);
            int cnt = end - base;
            for (int j = 0; j < cnt; j++) {
                __half2 p0, p1;
                EDGE_PROD(j, p0, p1);
                float2 f0 = __half22float2(p0);
                float2 f1 = __half22float2(p1);
                acc.x += f0.x; acc.y += f0.y; acc.z += f1.x; acc.w += f1.y;
            }
        }
        __half2 o0 = __floats2half2_rn(acc.x, acc.y);
        __half2 o1 = __floats2half2_rn(acc.z, acc.w);
        __half2 op[2] = {o0, o1};
        *(uint2*)(g_aggh + (size_t)node * HH + lane * 4) = *(uint2*)op;
    }
}

// ---------------------------------------------------------------------------
// Pair epilogue (HHCOPY also mirrors result into g_hh fp16)
// ---------------------------------------------------------------------------
template <int NCOL, bool BIAS, bool ACT, bool RESID, bool POOL, bool OFP16, bool HHCOPY>
__device__ __forceinline__ void epi2(int row, int col, float v0, float v1,
                                     const float* __restrict__ bias, void* outv,
                                     const int* __restrict__ batch) {
    if (row >= NN) return;
    if (BIAS) { v0 += bias[col]; v1 += bias[col + 1]; }
    if (ACT)  { v0 = sspf(v0); v1 = sspf(v1); }
    if (POOL) {
        int b = batch[row];
        float* p = g_pooled + (size_t)b * NCOL + col;
        asm volatile("red.global.add.v2.f32 [%0], {%1,%2};" :: "l"(p), "f"(v0), "f"(v1) : "memory");
    } else if (OFP16) {
        __half2 pk = __floats2half2_rn(v0, v1);
        *(unsigned*)((__half*)outv + (size_t)row * NCOL + col) = *(unsigned*)&pk;
    } else {
        float* o = (float*)outv + (size_t)row * NCOL + col;
        if (RESID) {
            float2 h = *(float2*)o;
            v0 += h.x; v1 += h.y;
        }
        *(float2*)o = make_float2(v0, v1);
        if (HHCOPY) {
            __half2 pk = __floats2half2_rn(v0, v1);
            *(unsigned*)(g_hh + (size_t)row * NCOL + col) = *(unsigned*)&pk;
        }
    }
}

// ---------------------------------------------------------------------------
// fp16 tensor-core GEMM, single-stage K=128 (A already fp16): out = A @ Wt^T
// ---------------------------------------------------------------------------
template <int NCOL, bool OFP16>
__global__ void __launch_bounds__(256, 2)
mma_gemm16_kernel(const __half* __restrict__ A,
                  const __half* __restrict__ Wt,
                  void* outv) {
    constexpr int KDIM = 128;
    constexpr int WN = NCOL / 2;
    constexpr int NT = WN / 8;
    constexpr int PANEL = 16384;

    extern __shared__ char dynsm[];
    char* As = dynsm;
    char* Bs = dynsm + 2 * PANEL;

    int tid = threadIdx.x;
    int warp = tid >> 5, lane = tid & 31;
    int wm = warp & 3, wn = warp >> 2;
    int row0 = blockIdx.x * 128;

    float acc[2][NT][4];
    #pragma unroll
    for (int mt = 0; mt < 2; mt++)
        #pragma unroll
        for (int nt = 0; nt < NT; nt++)
            #pragma unroll
            for (int q = 0; q < 4; q++) acc[mt][nt][q] = 0.f;

    unsigned as_base = smem_u32(As);
    unsigned bs_base = smem_u32(Bs);

    #pragma unroll
    for (int i = tid; i < 128 * 16; i += 256) {
        int r = i >> 4, ch = i & 15;
        int grow = row0 + r;
        uint4 v = make_uint4(0, 0, 0, 0);
        if (grow < NN)
            v = *(const uint4*)(A + (size_t)grow * KDIM + ch * 8);
        *(uint4*)(As + (ch >> 3) * PANEL + SWZ(r * 128 + (ch & 7) * 16)) = v;
    }
    #pragma unroll
    for (int i = tid; i < NCOL * 16; i += 256) {
        int r = i >> 4, ch = i & 15;
        uint4 v = *(const uint4*)(Wt + (size_t)r * KDIM + ch * 8);
        *(uint4*)(Bs + (ch >> 3) * PANEL + SWZ(r * 128 + (ch & 7) * 16)) = v;
    }
    __syncthreads();

    #pragma unroll
    for (int ks = 0; ks < 8; ks++) {
        int poff = (ks >> 2) * PANEL;
        int koff = (ks & 3) * 32;
        unsigned a[2][4];
        #pragma unroll
        for (int mt = 0; mt < 2; mt++) {
            int r = wm * 32 + mt * 16 + (lane & 15);
            ldsm_x4(a[mt], as_base + poff + SWZ(r * 128 + koff + (lane >> 4) * 16));
        }
        #pragma unroll
        for (int nt = 0; nt < NT; nt++) {
            unsigned b[2];
            int l = lane & 15;
            int r = wn * WN + nt * 8 + (l & 7);
            ldsm_x2(b, bs_base + poff + SWZ(r * 128 + koff + ((l >> 3) & 1) * 16));
            mma_fp16(acc[0][nt], a[0], b);
            mma_fp16(acc[1][nt], a[1], b);
        }
    }

    #pragma unroll
    for (int mt = 0; mt < 2; mt++) {
        #pragma unroll
        for (int nt = 0; nt < NT; nt++) {
            int r = row0 + wm * 32 + mt * 16 + (lane >> 2);
            int c = wn * WN + nt * 8 + (lane & 3) * 2;
            epi2<NCOL, false, false, false, false, OFP16, false>(r, c, acc[mt][nt][0], acc[mt][nt][1], nullptr, outv, nullptr);
            epi2<NCOL, false, false, false, false, OFP16, false>(r + 8, c, acc[mt][nt][2], acc[mt][nt][3], nullptr, outv, nullptr);
        }
    }
}

// ---------------------------------------------------------------------------
// Fused two-GEMM chain: T = ssp(A@W1 + b1); out2 = T@W2 + b2
// AFP16: A already fp16.  POOL2: pool epilogue; else residual h update (+hh copy)
// ---------------------------------------------------------------------------
template <int K1, int N1, int N2, bool POOL2, bool AFP16>
__global__ void __launch_bounds__(256, 2)
fused2_kernel(const void* __restrict__ Av,
              const __half* __restrict__ W1, const float* __restrict__ b1,
              const __half* __restrict__ W2, const float* __restrict__ b2,
              float* __restrict__ outh, const int* __restrict__ batch) {
    constexpr int WN1 = N1 / 2, NT1 = WN1 / 8;
    constexpr int WN2 = N2 / 2, NT2 = WN2 / 8;
    constexpr int A_B = 128 * 64 * 2;
    constexpr int B_B = 16384;
    constexpr int PANEL = 128 * 64 * 2;

    extern __shared__ char dynsm[];
    char* As = dynsm;
    char* Bs = dynsm + A_B;
    char* Ts = dynsm + A_B + B_B;

    int tid = threadIdx.x;
    int warp = tid >> 5, lane = tid & 31;
    int wm = warp & 3, wn = warp >> 2;
    int row0 = blockIdx.x * 128;

    unsigned as_base = smem_u32(As);
    unsigned bs_base = smem_u32(Bs);
    unsigned ts_base = smem_u32(Ts);

    float acc1[2][NT1][4];
    #pragma unroll
    for (int mt = 0; mt < 2; mt++)
        #pragma unroll
        for (int nt = 0; nt < NT1; nt++)
            #pragma unroll
            for (int q = 0; q < 4; q++) acc1[mt][nt][q] = 0.f;

    for (int k0 = 0; k0 < K1; k0 += 64) {
        #pragma unroll
        for (int i = tid; i < 128 * 8; i += 256) {
            int r = i >> 3, ch = i & 7;
            int grow = row0 + r;
            if (AFP16) {
                uint4 v = make_uint4(0, 0, 0, 0);
                if (grow < NN)
                    v = *(const uint4*)((const __half*)Av + (size_t)grow * K1 + k0 + ch * 8);
                *(uint4*)(As + SWZ(r * 128 + ch * 16)) = v;
            } else {
                float v[8] = {0.f, 0.f, 0.f, 0.f, 0.f, 0.f, 0.f, 0.f};
                if (grow < NN) {
                    const float* gp = (const float*)Av + (size_t)grow * K1 + k0 + ch * 8;
                    float4 f0 = *(const float4*)gp;
                    float4 f1 = *(const float4*)(gp + 4);
                    v[0] = f0.x; v[1] = f0.y; v[2] = f0.z; v[3] = f0.w;
                    v[4] = f1.x; v[5] = f1.y; v[6] = f1.z; v[7] = f1.w;
                }
                __half2 hh[4];
                #pragma unroll
                for (int q = 0; q < 4; q++) hh[q] = __floats2half2_rn(v[2 * q], v[2 * q + 1]);
                *(uint4*)(As + SWZ(r * 128 + ch * 16)) = *(uint4*)hh;
            }
        }
        #pragma unroll
        for (int i = tid; i < N1 * 8; i += 256) {
            int r = i >> 3, ch = i & 7;
            uint4 w = *(const uint4*)(W1 + (size_t)r * K1 + k0 + ch * 8);
            *(uint4*)(Bs + SWZ(r * 128 + ch * 16)) = w;
        }
        __syncthreads();

        #pragma unroll
        for (int ks = 0; ks < 4; ks++) {
            unsigned a[2][4];
            #pragma unroll
            for (int mt = 0; mt < 2; mt++) {
                int r = wm * 32 + mt * 16 + (lane & 15);
                ldsm_x4(a[mt], as_base + SWZ(r * 128 + ks * 32 + (lane >> 4) * 16));
            }
            #pragma unroll
            for (int nt = 0; nt < NT1; nt++) {
                unsigned b[2];
                int l = lane & 15;
                int r = wn * WN1 + nt * 8 + (l & 7);
                ldsm_x2(b, bs_base + SWZ(r * 128 + ks * 32 + ((l >> 3) & 1) * 16));
                mma_fp16(acc1[0][nt], a[0], b);
                mma_fp16(acc1[1][nt], a[1], b);
            }
        }
        __syncthreads();
    }

    #pragma unroll
    for (int mt = 0; mt < 2; mt++) {
        #pragma unroll
        for (int nt = 0; nt < NT1; nt++) {
            int c = wn * WN1 + nt * 8 + (lane & 3) * 2;
            int panel_off = (c >> 6) * PANEL;
            int kk2 = (c & 63) * 2;
            #pragma unroll
            for (int half = 0; half < 2; half++) {
                int rl = wm * 32 + mt * 16 + (lane >> 2) + half * 8;
                float v0 = sspf(acc1[mt][nt][half * 2 + 0] + b1[c]);
                float v1 = sspf(acc1[mt][nt][half * 2 + 1] + b1[c + 1]);
                __half2 pk = __floats2half2_rn(v0, v1);
                *(unsigned*)(Ts + panel_off + SWZ(rl * 128 + kk2)) = *(unsigned*)&pk;
            }
        }
    }
    __syncthreads();

    float acc2[2][NT2][4];
    #pragma unroll
    for (int mt = 0; mt < 2; mt++)
        #pragma unroll
        for (int nt = 0; nt < NT2; nt++)
            #pragma unroll
            for (int q = 0; q < 4; q++) acc2[mt][nt][q] = 0.f;

    for (int k0 = 0; k0 < N1; k0 += 64) {
        #pragma unroll
        for (int i = tid; i < N2 * 8; i += 256) {
            int r = i >> 3, ch = i & 7;
            uint4 w = *(const uint4*)(W2 + (size_t)r * N1 + k0 + ch * 8);
            *(uint4*)(Bs + SWZ(r * 128 + ch * 16)) = w;
        }
        __syncthreads();

        int panel_off = (k0 >> 6) * PANEL;
        #pragma unroll
        for (int ks = 0; ks < 4; ks++) {
            unsigned a[2][4];
            #pragma unroll
            for (int mt = 0; mt < 2; mt++) {
                int r = wm * 32 + mt * 16 + (lane & 15);
                ldsm_x4(a[mt], ts_base + panel_off + SWZ(r * 128 + ks * 32 + (lane >> 4) * 16));
            }
            #pragma unroll
            for (int nt = 0; nt < NT2; nt++) {
                unsigned b[2];
                int l = lane & 15;
                int r = wn * WN2 + nt * 8 + (l & 7);
                ldsm_x2(b, bs_base + SWZ(r * 128 + ks * 32 + ((l >> 3) & 1) * 16));
                mma_fp16(acc2[0][nt], a[0], b);
                mma_fp16(acc2[1][nt], a[1], b);
            }
        }
        __syncthreads();
    }

    #pragma unroll
    for (int mt = 0; mt < 2; mt++) {
        #pragma unroll
        for (int nt = 0; nt < NT2; nt++) {
            int r = row0 + wm * 32 + mt * 16 + (lane >> 2);
            int c = wn * WN2 + nt * 8 + (lane & 3) * 2;
            epi2<N2, true, false, !POOL2, POOL2, false, !POOL2>(r, c, acc2[mt][nt][0], acc2[mt][nt][1], b2, outh, batch);
            epi2<N2, true, false, !POOL2, POOL2, false, !POOL2>(r + 8, c, acc2[mt][nt][2], acc2[mt][nt][3], b2, outh, batch);
        }
    }
}

// ---------------------------------------------------------------------------
// Final tiny GEMM
// ---------------------------------------------------------------------------
__global__ void final_kernel(const float* __restrict__ pw, const float* __restrict__ pb,
                             float* __restrict__ out) {
    int tid = threadIdx.x;
    int b = tid >> 2;
    int t = tid & 3;
    float acc = pb[t];
    for (int k = 0; k < HH; k++)
        acc = fmaf(g_pooled[b * HH + k], pw[k * TT + t], acc);
    out[b * TT + t] = acc;
}

// ---------------------------------------------------------------------------
extern "C" void kernel_launch(void* const* d_in, const int* in_sizes, int n_in,
                              void* d_out, int out_size) {
    const int*   z       = (const int*)d_in[0];
    const float* pos     = (const float*)d_in[1];
    const int*   batch   = (const int*)d_in[2];
    const int*   ei      = (const int*)d_in[3];
    const float* emb     = (const float*)d_in[4];
    const float* mlp_w1  = (const float*)d_in[5];
    const float* mlp_b1  = (const float*)d_in[6];
    const float* mlp_w2  = (const float*)d_in[7];
    const float* mlp_b2  = (const float*)d_in[8];
    const float* lin1_w  = (const float*)d_in[9];
    const float* lin2_w  = (const float*)d_in[10];
    const float* lin2_b  = (const float*)d_in[11];
    const float* lin_w   = (const float*)d_in[12];
    const float* lin_b   = (const float*)d_in[13];
    const float* out1_w  = (const float*)d_in[14];
    const float* out1_b  = (const float*)d_in[15];
    const float* out2_w  = (const float*)d_in[16];
    const float* out2_b  = (const float*)d_in[17];
    const float* pred_w  = (const float*)d_in[18];
    const float* pred_b  = (const float*)d_in[19];
    float* out = (float*)d_out;

    float* p_h;
    void *p_xjh, *p_hh, *p_aggh;
    __half* p_wt;
    cudaGetSymbolAddress((void**)&p_h, g_h);
    cudaGetSymbolAddress(&p_hh, g_hh);
    cudaGetSymbolAddress(&p_xjh, g_xjh);
    cudaGetSymbolAddress(&p_aggh, g_aggh);
    cudaGetSymbolAddress((void**)&p_wt, g_wt);

    int dev = 0, smCount = 148;
    cudaGetDevice(&dev);
    cudaDeviceGetAttribute(&smCount, cudaDevAttrMultiProcessorCount, dev);

    const int TAB_SMEM = TAB * 512;                 // 98304 (interleaved pairs)
    cudaFuncSetAttribute(edge_conv_csr_kernel, cudaFuncAttributeMaxDynamicSharedMemorySize, TAB_SMEM);

    const int SM_G16 = 65536;
    const int SM_FA  = 16384 + 16384 + 32768;       // 65536 (N1=128)
    const int SM_FB  = 16384 + 16384 + 16384;       // 49152 (N1=64)
    cudaFuncSetAttribute(mma_gemm16_kernel<128, true>,
                         cudaFuncAttributeMaxDynamicSharedMemorySize, SM_G16);
    cudaFuncSetAttribute(fused2_kernel<128, 128, 128, false, true>,
                         cudaFuncAttributeMaxDynamicSharedMemorySize, SM_FA);
    cudaFuncSetAttribute(fused2_kernel<128, 64, 128, true, true>,
                         cudaFuncAttributeMaxDynamicSharedMemorySize, SM_FB);

    int gblocks = (NN + 127) / 128;

    // prep
    dim3 tg(64, 8);
    transpose_all_kernel<<<tg, 256>>>(lin1_w, lin2_w, lin_w, out1_w, out2_w, p_wt);
    prep_kernel<<<(NN * 32 + 255) / 256, 256>>>(z, emb);
    dim3 tb(TAB, 2);
    build_table_kernel<<<tb, HH>>>(mlp_w1, mlp_b1, mlp_w2, mlp_b2);
    mma_gemm16_kernel<128, true><<<gblocks, 256, SM_G16>>>(
        (const __half*)p_hh, p_wt + WT_LIN1(0), p_xjh);
    hist_kernel<<<(EE / 4 + 255) / 256, 256>>>(ei);
    scan1_kernel<<<NBLK, SCAN_B>>>();
    scan3_kernel<<<NBLK, SCAN_B>>>();
    fill_kernel<<<(EE / 4 + 255) / 256, 256>>>(ei, pos);

    for (int i = 0; i < 2; i++) {
        if (i > 0) {
            mma_gemm16_kernel<128, true><<<gblocks, 256, SM_G16>>>(
                (const __half*)p_hh, p_wt + WT_LIN1(i), p_xjh);
        }
        edge_conv_csr_kernel<<<smCount, 1024, TAB_SMEM>>>(i);
        fused2_kernel<128, 128, 128, false, true><<<gblocks, 256, SM_FA>>>(
            p_aggh,
            p_wt + WT_LIN2(i), lin2_b + (size_t)i * HH,
            p_wt + WT_LIN(i),  lin_b + (size_t)i * HH,
            p_h, nullptr);
    }

    fused2_kernel<128, 64, 128, true, true><<<gblocks, 256, SM_FB>>>(
        p_hh,
        p_wt + WT_OUT1, out1_b,
        p_wt + WT_OUT2, out2_b,
        nullptr, batch);
    final_kernel<<<1, 256>>>(pred_w, pred_b, out);
}

// round 13
// speedup vs baseline: 1.1214x; 1.0610x over previous
#include <cuda_runtime.h>
#include <cuda_bf16.h>
#include <cuda_fp16.h>
#include <stdint.h>
#include <math.h>

#define NN 50000
#define EE 1600000
#define HH 128
#define BB 64
#define TT 4
#define GG 10
#define TAB 96
#define D_MAX 8.6603f
#define SCAN_B 1024
#define NBLK ((NN + SCAN_B - 1) / SCAN_B)

// scratch (static device globals — no runtime allocation)
static __device__ float g_table[TAB * HH * 2];   // fp32 master table (2 interactions)
static __device__ float g_h[NN * HH];
static __device__ __half g_hh[NN * HH];          // fp16 shadow of h (GEMM A operand)
static __device__ __half g_xjh[NN * HH];
static __device__ __half g_aggh[NN * HH];        // fp16 agg (GEMM A operand)
static __device__ float g_pooled[BB * HH];
static __device__ __half g_wt[7 * 16384];        // transposed fp16 weights
// CSR (dst-major)
static __device__ int  g_deg[NN];
static __device__ int  g_ptr[NN + 1];
static __device__ int  g_work[NN];
static __device__ int  g_bsum[NBLK];
static __device__ int2 g_csr[EE];                // {src | i0<<16, half2(f,f) bits}

#define WT_LIN1(i)  ((size_t)(i) * 16384)
#define WT_LIN2(i)  ((size_t)(32768) + (size_t)(i) * 16384)
#define WT_LIN(i)   ((size_t)(65536) + (size_t)(i) * 16384)
#define WT_OUT1     ((size_t)98304)
#define WT_OUT2     ((size_t)106496)

__device__ __forceinline__ float sspf(float x) {
    float ax = fabsf(x);
    return fmaxf(x, 0.0f) + log1pf(__expf(-ax)) - 0.6931471805599453f;
}

#define SWZ(off) ((off) ^ (((off) >> 3) & 0x70))

__device__ __forceinline__ unsigned smem_u32(const void* p) {
    return (unsigned)__cvta_generic_to_shared(p);
}
__device__ __forceinline__ void ldsm_x4(unsigned* r, unsigned addr) {
    asm volatile("ldmatrix.sync.aligned.m8n8.x4.shared.b16 {%0,%1,%2,%3}, [%4];"
                 : "=r"(r[0]), "=r"(r[1]), "=r"(r[2]), "=r"(r[3]) : "r"(addr));
}
__device__ __forceinline__ void ldsm_x2(unsigned* r, unsigned addr) {
    asm volatile("ldmatrix.sync.aligned.m8n8.x2.shared.b16 {%0,%1}, [%2];"
                 : "=r"(r[0]), "=r"(r[1]) : "r"(addr));
}
__device__ __forceinline__ void mma_fp16(float* d, const unsigned* a, const unsigned* b) {
    asm volatile("mma.sync.aligned.m16n8k16.row.col.f32.f16.f16.f32 "
                 "{%0,%1,%2,%3}, {%4,%5,%6,%7}, {%8,%9}, {%0,%1,%2,%3};"
                 : "+f"(d[0]), "+f"(d[1]), "+f"(d[2]), "+f"(d[3])
                 : "r"(a[0]), "r"(a[1]), "r"(a[2]), "r"(a[3]), "r"(b[0]), "r"(b[1]));
}

// ---------------------------------------------------------------------------
// Build filter table (fp32 master, TAB knots)
// ---------------------------------------------------------------------------
__global__ void build_table_kernel(const float* __restrict__ w1, const float* __restrict__ b1,
                                   const float* __restrict__ w2, const float* __restrict__ b2) {
    int row = blockIdx.x;
    int inter = blockIdx.y;
    int tid = threadIdx.x;
    float d = row * (D_MAX / (float)(TAB - 1));

    __shared__ float hid[HH];
    const float* w1i = w1 + (size_t)inter * GG * HH;
    const float* b1i = b1 + (size_t)inter * HH;
    const float* w2i = w2 + (size_t)inter * HH * HH;
    const float* b2i = b2 + (size_t)inter * HH;

    const float step = 10.0f / 9.0f;
    const float coeff = -0.5f / (step * step);

    float acc = b1i[tid];
    #pragma unroll
    for (int g = 0; g < GG; g++) {
        float diff = d - (float)g * step;
        float r = expf(coeff * diff * diff);
        acc += r * w1i[g * HH + tid];
    }
    hid[tid] = sspf(acc);
    __syncthreads();

    float acc2 = b2i[tid];
    for (int k = 0; k < HH; k++)
        acc2 = fmaf(hid[k], w2i[k * HH + tid], acc2);

    float C = 0.5f * (cosf(d * 3.14159265358979f / 10.0f) + 1.0f);
    g_table[((size_t)inter * TAB + row) * HH + tid] = acc2 * C;
}

// ---------------------------------------------------------------------------
// Merged weight transpose + fp16 convert
// ---------------------------------------------------------------------------
__global__ void transpose_all_kernel(const float* __restrict__ lin1_w,
                                     const float* __restrict__ lin2_w,
                                     const float* __restrict__ lin_w,
                                     const float* __restrict__ out1_w,
                                     const float* __restrict__ out2_w,
                                     __half* __restrict__ wt) {
    int m = blockIdx.y;
    const float* src;
    size_t off;
    int K, N;
    switch (m) {
        case 0: src = lin1_w;          off = WT_LIN1(0); K = 128; N = 128; break;
        case 1: src = lin1_w + 16384;  off = WT_LIN1(1); K = 128; N = 128; break;
        case 2: src = lin2_w;          off = WT_LIN2(0); K = 128; N = 128; break;
        case 3: src = lin2_w + 16384;  off = WT_LIN2(1); K = 128; N = 128; break;
        case 4: src = lin_w;           off = WT_LIN(0);  K = 128; N = 128; break;
        case 5: src = lin_w + 16384;   off = WT_LIN(1);  K = 128; N = 128; break;
        case 6: src = out1_w;          off = WT_OUT1;    K = 128; N = 64;  break;
        default: src = out2_w;         off = WT_OUT2;    K = 64;  N = 128; break;
    }
    int i = blockIdx.x * blockDim.x + threadIdx.x;
    if (i >= K * N) return;
    int k = i / N, n = i % N;
    wt[off + (size_t)n * K + k] = __float2half_rn(src[i]);
}

// ---------------------------------------------------------------------------
// Fused prep: embedding gather (fp32 + fp16 shadow) + zero deg + zero pooled
// ---------------------------------------------------------------------------
__global__ void prep_kernel(const int* __restrict__ z, const float* __restrict__ emb) {
    int idx = blockIdx.x * blockDim.x + threadIdx.x;
    if (idx < NN * (HH / 4)) {
        int n = idx >> 5;
        int c = idx & 31;
        float4 v = ((const float4*)emb)[(size_t)z[n] * (HH / 4) + c];
        ((float4*)g_h)[idx] = v;
        __half2 pk[2] = {__floats2half2_rn(v.x, v.y), __floats2half2_rn(v.z, v.w)};
        ((uint2*)g_hh)[idx] = *(uint2*)pk;
    }
    if (idx < NN) g_deg[idx] = 0;
    if (idx < BB * HH) g_pooled[idx] = 0.f;
}

// ---------------------------------------------------------------------------
// CSR construction
// ---------------------------------------------------------------------------
__global__ void hist_kernel(const int* __restrict__ ei) {
    int i = blockIdx.x * blockDim.x + threadIdx.x;
    if (i >= EE / 4) return;
    int4 d4 = ((const int4*)(ei + EE))[i];
    atomicAdd(&g_deg[d4.x], 1);
    atomicAdd(&g_deg[d4.y], 1);
    atomicAdd(&g_deg[d4.z], 1);
    atomicAdd(&g_deg[d4.w], 1);
}

__global__ void scan1_kernel() {
    __shared__ int sm[SCAN_B];
    int idx = blockIdx.x * SCAN_B + threadIdx.x;
    int v = (idx < NN) ? g_deg[idx] : 0;
    sm[threadIdx.x] = v;
    __syncthreads();
    for (int off = SCAN_B / 2; off > 0; off >>= 1) {
        if (threadIdx.x < off) sm[threadIdx.x] += sm[threadIdx.x + off];
        __syncthreads();
    }
    if (threadIdx.x == 0) g_bsum[blockIdx.x] = sm[0];
}

__global__ void scan3_kernel() {
    __shared__ int sm[SCAN_B];
    __shared__ int blockoff;
    int idx = blockIdx.x * SCAN_B + threadIdx.x;
    int v = (idx < NN) ? g_deg[idx] : 0;
    sm[threadIdx.x] = v;
    if (threadIdx.x == 0) {
        int run = 0;
        for (int b = 0; b < blockIdx.x; b++) run += g_bsum[b];
        blockoff = run;
    }
    __syncthreads();
    for (int off = 1; off < SCAN_B; off <<= 1) {
        int add = (threadIdx.x >= off) ? sm[threadIdx.x - off] : 0;
        __syncthreads();
        sm[threadIdx.x] += add;
        __syncthreads();
    }
    if (idx < NN) {
        int excl = blockoff + sm[threadIdx.x] - v;
        g_ptr[idx] = excl;
        g_work[idx] = excl;
        if (idx == NN - 1) g_ptr[NN] = blockoff + sm[threadIdx.x];
    }
}

__global__ void fill_kernel(const int* __restrict__ ei, const float* __restrict__ pos) {
    int i = blockIdx.x * blockDim.x + threadIdx.x;
    if (i >= EE / 4) return;
    int4 s4 = ((const int4*)ei)[i];
    int4 d4 = ((const int4*)(ei + EE))[i];
    const float INV_STEP = (float)(TAB - 1) / D_MAX;
    #pragma unroll
    for (int q = 0; q < 4; q++) {
        int s = (&s4.x)[q];
        int d = (&d4.x)[q];
        float dx = pos[s * 3 + 0] - pos[d * 3 + 0];
        float dy = pos[s * 3 + 1] - pos[d * 3 + 1];
        float dz = pos[s * 3 + 2] - pos[d * 3 + 2];
        float dist = sqrtf(dx * dx + dy * dy + dz * dz);
        float t = dist * INV_STEP;
        int i0 = min((int)t, TAB - 2);
        float f = t - (float)i0;
        __half2 f2 = __float2half2_rn(f);
        int slot = atomicAdd(&g_work[d], 1);
        g_csr[slot] = make_int2(s | (i0 << 16), *(int*)&f2);
    }
}

// ---------------------------------------------------------------------------
// CSR edge aggregation: pair-interleaved fp16 table (one LDS.128 per edge),
// half2 math, fp32 accumulation, fp16 agg output.
// TAB=96 -> 48KB table -> 2 blocks/SM (64 warps/SM).
// ---------------------------------------------------------------------------
#define EDGE_PROD(J, P0, P1) {                                                      \
    int cx  = __shfl_sync(0xffffffffu, c.x, (J));                                   \
    int cyi = __shfl_sync(0xffffffffu, c.y, (J));                                   \
    int s  = cx & 0xffff;                                                           \
    int i0 = cx >> 16;                                                              \
    __half2 f2 = *reinterpret_cast<__half2*>(&cyi);                                 \
    uint2 xw = *(const uint2*)(g_xjh + (size_t)s * HH + lane * 4);                  \
    __half2 x0 = *reinterpret_cast<__half2*>(&xw.x);                                \
    __half2 x1 = *reinterpret_cast<__half2*>(&xw.y);                                \
    uint4 wv = *(const uint4*)(tab + i0 * 256 + lane * 8);                          \
    __half2 w0a = *reinterpret_cast<__half2*>(&wv.x);                               \
    __half2 w0b = *reinterpret_cast<__half2*>(&wv.y);                               \
    __half2 w1a = *reinterpret_cast<__half2*>(&wv.z);                               \
    __half2 w1b = *reinterpret_cast<__half2*>(&wv.w);                               \
    P0 = __hmul2(__hfma2(__hsub2(w1a, w0a), f2, w0a), x0);                          \
    P1 = __hmul2(__hfma2(__hsub2(w1b, w0b), f2, w0b), x1);                          \
}

__global__ void __launch_bounds__(1024, 2) edge_conv_csr_kernel(int inter) {
    extern __shared__ __half tab[];
    // build interleaved table: chunk c -> entry i = c>>5, colgroup g = c&31
    const float4* tsrc = (const float4*)(g_table + (size_t)inter * TAB * HH);
    for (int cch = threadIdx.x; cch < TAB * 32; cch += 1024) {
        int i = cch >> 5, g = cch & 31;
        int i1 = min(i + 1, TAB - 1);
        float4 r0 = tsrc[i * 32 + g];
        float4 r1 = tsrc[i1 * 32 + g];
        __half2 hh[4];
        hh[0] = __floats2half2_rn(r0.x, r0.y);
        hh[1] = __floats2half2_rn(r0.z, r0.w);
        hh[2] = __floats2half2_rn(r1.x, r1.y);
        hh[3] = __floats2half2_rn(r1.z, r1.w);
        ((uint4*)tab)[cch] = *(uint4*)hh;
    }
    __syncthreads();

    int lane = threadIdx.x & 31;
    int gwarp = blockIdx.x * 32 + (threadIdx.x >> 5);
    int nwarp = gridDim.x * 32;

    for (int node = gwarp; node < NN; node += nwarp) {
        int beg = __ldg(&g_ptr[node]);
        int end = __ldg(&g_ptr[node + 1]);

        float4 acc = make_float4(0.f, 0.f, 0.f, 0.f);
        int base = beg;
        for (; base + 32 <= end; base += 32) {
            int2 c = __ldg(&g_csr[base + lane]);
            #pragma unroll 8
            for (int j = 0; j < 32; j += 2) {
                __half2 a0, a1, b0, b1;
                EDGE_PROD(j, a0, a1);
                EDGE_PROD(j + 1, b0, b1);
                __half2 s0 = __hadd2(a0, b0);
                __half2 s1 = __hadd2(a1, b1);
                float2 f0 = __half22float2(s0);
                float2 f1 = __half22float2(s1);
                acc.x += f0.x; acc.y += f0.y; acc.z += f1.x; acc.w += f1.y;
            }
        }
        if (base < end) {
            int k = base + lane;
            int2 c = (k < end) ? __ldg(&g_csr[k]) : make_int2(0, 0);
            int cnt = end - base;
            for (int j = 0; j < cnt; j++) {
                __half2 p0, p1;
                EDGE_PROD(j, p0, p1);
                float2 f0 = __half22float2(p0);
                float2 f1 = __half22float2(p1);
                acc.x += f0.x; acc.y += f0.y; acc.z += f1.x; acc.w += f1.y;
            }
        }
        __half2 o0 = __floats2half2_rn(acc.x, acc.y);
        __half2 o1 = __floats2half2_rn(acc.z, acc.w);
        __half2 op[2] = {o0, o1};
        *(uint2*)(g_aggh + (size_t)node * HH + lane * 4) = *(uint2*)op;
    }
}

// ---------------------------------------------------------------------------
// Pair epilogue (HHCOPY also mirrors result into g_hh fp16)
// ---------------------------------------------------------------------------
template <int NCOL, bool BIAS, bool ACT, bool RESID, bool POOL, bool OFP16, bool HHCOPY>
__device__ __forceinline__ void epi2(int row, int col, float v0, float v1,
                                     const float* __restrict__ bias, void* outv,
                                     const int* __restrict__ batch) {
    if (row >= NN) return;
    if (BIAS) { v0 += bias[col]; v1 += bias[col + 1]; }
    if (ACT)  { v0 = sspf(v0); v1 = sspf(v1); }
    if (POOL) {
        int b = batch[row];
        float* p = g_pooled + (size_t)b * NCOL + col;
        asm volatile("red.global.add.v2.f32 [%0], {%1,%2};" :: "l"(p), "f"(v0), "f"(v1) : "memory");
    } else if (OFP16) {
        __half2 pk = __floats2half2_rn(v0, v1);
        *(unsigned*)((__half*)outv + (size_t)row * NCOL + col) = *(unsigned*)&pk;
    } else {
        float* o = (float*)outv + (size_t)row * NCOL + col;
        if (RESID) {
            float2 h = *(float2*)o;
            v0 += h.x; v1 += h.y;
        }
        *(float2*)o = make_float2(v0, v1);
        if (HHCOPY) {
            __half2 pk = __floats2half2_rn(v0, v1);
            *(unsigned*)(g_hh + (size_t)row * NCOL + col) = *(unsigned*)&pk;
        }
    }
}

// ---------------------------------------------------------------------------
// fp16 tensor-core GEMM, single-stage K=128 (A already fp16): out = A @ Wt^T
// ---------------------------------------------------------------------------
template <int NCOL, bool OFP16>
__global__ void __launch_bounds__(256, 2)
mma_gemm16_kernel(const __half* __restrict__ A,
                  const __half* __restrict__ Wt,
                  void* outv) {
    constexpr int KDIM = 128;
    constexpr int WN = NCOL / 2;
    constexpr int NT = WN / 8;
    constexpr int PANEL = 16384;

    extern __shared__ char dynsm[];
    char* As = dynsm;
    char* Bs = dynsm + 2 * PANEL;

    int tid = threadIdx.x;
    int warp = tid >> 5, lane = tid & 31;
    int wm = warp & 3, wn = warp >> 2;
    int row0 = blockIdx.x * 128;

    float acc[2][NT][4];
    #pragma unroll
    for (int mt = 0; mt < 2; mt++)
        #pragma unroll
        for (int nt = 0; nt < NT; nt++)
            #pragma unroll
            for (int q = 0; q < 4; q++) acc[mt][nt][q] = 0.f;

    unsigned as_base = smem_u32(As);
    unsigned bs_base = smem_u32(Bs);

    #pragma unroll
    for (int i = tid; i < 128 * 16; i += 256) {
        int r = i >> 4, ch = i & 15;
        int grow = row0 + r;
        uint4 v = make_uint4(0, 0, 0, 0);
        if (grow < NN)
            v = *(const uint4*)(A + (size_t)grow * KDIM + ch * 8);
        *(uint4*)(As + (ch >> 3) * PANEL + SWZ(r * 128 + (ch & 7) * 16)) = v;
    }
    #pragma unroll
    for (int i = tid; i < NCOL * 16; i += 256) {
        int r = i >> 4, ch = i & 15;
        uint4 v = *(const uint4*)(Wt + (size_t)r * KDIM + ch * 8);
        *(uint4*)(Bs + (ch >> 3) * PANEL + SWZ(r * 128 + (ch & 7) * 16)) = v;
    }
    __syncthreads();

    #pragma unroll
    for (int ks = 0; ks < 8; ks++) {
        int poff = (ks >> 2) * PANEL;
        int koff = (ks & 3) * 32;
        unsigned a[2][4];
        #pragma unroll
        for (int mt = 0; mt < 2; mt++) {
            int r = wm * 32 + mt * 16 + (lane & 15);
            ldsm_x4(a[mt], as_base + poff + SWZ(r * 128 + koff + (lane >> 4) * 16));
        }
        #pragma unroll
        for (int nt = 0; nt < NT; nt++) {
            unsigned b[2];
            int l = lane & 15;
            int r = wn * WN + nt * 8 + (l & 7);
            ldsm_x2(b, bs_base + poff + SWZ(r * 128 + koff + ((l >> 3) & 1) * 16));
            mma_fp16(acc[0][nt], a[0], b);
            mma_fp16(acc[1][nt], a[1], b);
        }
    }

    #pragma unroll
    for (int mt = 0; mt < 2; mt++) {
        #pragma unroll
        for (int nt = 0; nt < NT; nt++) {
            int r = row0 + wm * 32 + mt * 16 + (lane >> 2);
            int c = wn * WN + nt * 8 + (lane & 3) * 2;
            epi2<NCOL, false, false, false, false, OFP16, false>(r, c, acc[mt][nt][0], acc[mt][nt][1], nullptr, outv, nullptr);
            epi2<NCOL, false, false, false, false, OFP16, false>(r + 8, c, acc[mt][nt][2], acc[mt][nt][3], nullptr, outv, nullptr);
        }
    }
}

// ---------------------------------------------------------------------------
// Fused two-GEMM chain: T = ssp(A@W1 + b1); out2 = T@W2 + b2
// AFP16: A already fp16.  POOL2: pool epilogue; else residual h update (+hh copy)
// ---------------------------------------------------------------------------
template <int K1, int N1, int N2, bool POOL2, bool AFP16>
__global__ void __launch_bounds__(256, 2)
fused2_kernel(const void* __restrict__ Av,
              const __half* __restrict__ W1, const float* __restrict__ b1,
              const __half* __restrict__ W2, const float* __restrict__ b2,
              float* __restrict__ outh, const int* __restrict__ batch) {
    constexpr int WN1 = N1 / 2, NT1 = WN1 / 8;
    constexpr int WN2 = N2 / 2, NT2 = WN2 / 8;
    constexpr int A_B = 128 * 64 * 2;
    constexpr int B_B = 16384;
    constexpr int PANEL = 128 * 64 * 2;

    extern __shared__ char dynsm[];
    char* As = dynsm;
    char* Bs = dynsm + A_B;
    char* Ts = dynsm + A_B + B_B;

    int tid = threadIdx.x;
    int warp = tid >> 5, lane = tid & 31;
    int wm = warp & 3, wn = warp >> 2;
    int row0 = blockIdx.x * 128;

    unsigned as_base = smem_u32(As);
    unsigned bs_base = smem_u32(Bs);
    unsigned ts_base = smem_u32(Ts);

    float acc1[2][NT1][4];
    #pragma unroll
    for (int mt = 0; mt < 2; mt++)
        #pragma unroll
        for (int nt = 0; nt < NT1; nt++)
            #pragma unroll
            for (int q = 0; q < 4; q++) acc1[mt][nt][q] = 0.f;

    for (int k0 = 0; k0 < K1; k0 += 64) {
        #pragma unroll
        for (int i = tid; i < 128 * 8; i += 256) {
            int r = i >> 3, ch = i & 7;
            int grow = row0 + r;
            if (AFP16) {
                uint4 v = make_uint4(0, 0, 0, 0);
                if (grow < NN)
                    v = *(const uint4*)((const __half*)Av + (size_t)grow * K1 + k0 + ch * 8);
                *(uint4*)(As + SWZ(r * 128 + ch * 16)) = v;
            } else {
                float v[8] = {0.f, 0.f, 0.f, 0.f, 0.f, 0.f, 0.f, 0.f};
                if (grow < NN) {
                    const float* gp = (const float*)Av + (size_t)grow * K1 + k0 + ch * 8;
                    float4 f0 = *(const float4*)gp;
                    float4 f1 = *(const float4*)(gp + 4);
                    v[0] = f0.x; v[1] = f0.y; v[2] = f0.z; v[3] = f0.w;
                    v[4] = f1.x; v[5] = f1.y; v[6] = f1.z; v[7] = f1.w;
                }
                __half2 hh[4];
                #pragma unroll
                for (int q = 0; q < 4; q++) hh[q] = __floats2half2_rn(v[2 * q], v[2 * q + 1]);
                *(uint4*)(As + SWZ(r * 128 + ch * 16)) = *(uint4*)hh;
            }
        }
        #pragma unroll
        for (int i = tid; i < N1 * 8; i += 256) {
            int r = i >> 3, ch = i & 7;
            uint4 w = *(const uint4*)(W1 + (size_t)r * K1 + k0 + ch * 8);
            *(uint4*)(Bs + SWZ(r * 128 + ch * 16)) = w;
        }
        __syncthreads();

        #pragma unroll
        for (int ks = 0; ks < 4; ks++) {
            unsigned a[2][4];
            #pragma unroll
            for (int mt = 0; mt < 2; mt++) {
                int r = wm * 32 + mt * 16 + (lane & 15);
                ldsm_x4(a[mt], as_base + SWZ(r * 128 + ks * 32 + (lane >> 4) * 16));
            }
            #pragma unroll
            for (int nt = 0; nt < NT1; nt++) {
                unsigned b[2];
                int l = lane & 15;
                int r = wn * WN1 + nt * 8 + (l & 7);
                ldsm_x2(b, bs_base + SWZ(r * 128 + ks * 32 + ((l >> 3) & 1) * 16));
                mma_fp16(acc1[0][nt], a[0], b);
                mma_fp16(acc1[1][nt], a[1], b);
            }
        }
        __syncthreads();
    }

    #pragma unroll
    for (int mt = 0; mt < 2; mt++) {
        #pragma unroll
        for (int nt = 0; nt < NT1; nt++) {
            int c = wn * WN1 + nt * 8 + (lane & 3) * 2;
            int panel_off = (c >> 6) * PANEL;
            int kk2 = (c & 63) * 2;
            #pragma unroll
            for (int half = 0; half < 2; half++) {
                int rl = wm * 32 + mt * 16 + (lane >> 2) + half * 8;
                float v0 = sspf(acc1[mt][nt][half * 2 + 0] + b1[c]);
                float v1 = sspf(acc1[mt][nt][half * 2 + 1] + b1[c + 1]);
                __half2 pk = __floats2half2_rn(v0, v1);
                *(unsigned*)(Ts + panel_off + SWZ(rl * 128 + kk2)) = *(unsigned*)&pk;
            }
        }
    }
    __syncthreads();

    float acc2[2][NT2][4];
    #pragma unroll
    for (int mt = 0; mt < 2; mt++)
        #pragma unroll
        for (int nt = 0; nt < NT2; nt++)
            #pragma unroll
            for (int q = 0; q < 4; q++) acc2[mt][nt][q] = 0.f;

    for (int k0 = 0; k0 < N1; k0 += 64) {
        #pragma unroll
        for (int i = tid; i < N2 * 8; i += 256) {
            int r = i >> 3, ch = i & 7;
            uint4 w = *(const uint4*)(W2 + (size_t)r * N1 + k0 + ch * 8);
            *(uint4*)(Bs + SWZ(r * 128 + ch * 16)) = w;
        }
        __syncthreads();

        int panel_off = (k0 >> 6) * PANEL;
        #pragma unroll
        for (int ks = 0; ks < 4; ks++) {
            unsigned a[2][4];
            #pragma unroll
            for (int mt = 0; mt < 2; mt++) {
                int r = wm * 32 + mt * 16 + (lane & 15);
                ldsm_x4(a[mt], ts_base + panel_off + SWZ(r * 128 + ks * 32 + (lane >> 4) * 16));
            }
            #pragma unroll
            for (int nt = 0; nt < NT2; nt++) {
                unsigned b[2];
                int l = lane & 15;
                int r = wn * WN2 + nt * 8 + (l & 7);
                ldsm_x2(b, bs_base + SWZ(r * 128 + ks * 32 + ((l >> 3) & 1) * 16));
                mma_fp16(acc2[0][nt], a[0], b);
                mma_fp16(acc2[1][nt], a[1], b);
            }
        }
        __syncthreads();
    }

    #pragma unroll
    for (int mt = 0; mt < 2; mt++) {
        #pragma unroll
        for (int nt = 0; nt < NT2; nt++) {
            int r = row0 + wm * 32 + mt * 16 + (lane >> 2);
            int c = wn * WN2 + nt * 8 + (lane & 3) * 2;
            epi2<N2, true, false, !POOL2, POOL2, false, !POOL2>(r, c, acc2[mt][nt][0], acc2[mt][nt][1], b2, outh, batch);
            epi2<N2, true, false, !POOL2, POOL2, false, !POOL2>(r + 8, c, acc2[mt][nt][2], acc2[mt][nt][3], b2, outh, batch);
        }
    }
}

// ---------------------------------------------------------------------------
// Final tiny GEMM
// ---------------------------------------------------------------------------
__global__ void final_kernel(const float* __restrict__ pw, const float* __restrict__ pb,
                             float* __restrict__ out) {
    int tid = threadIdx.x;
    int b = tid >> 2;
    int t = tid & 3;
    float acc = pb[t];
    for (int k = 0; k < HH; k++)
        acc = fmaf(g_pooled[b * HH + k], pw[k * TT + t], acc);
    out[b * TT + t] = acc;
}

// ---------------------------------------------------------------------------
extern "C" void kernel_launch(void* const* d_in, const int* in_sizes, int n_in,
                              void* d_out, int out_size) {
    const int*   z       = (const int*)d_in[0];
    const float* pos     = (const float*)d_in[1];
    const int*   batch   = (const int*)d_in[2];
    const int*   ei      = (const int*)d_in[3];
    const float* emb     = (const float*)d_in[4];
    const float* mlp_w1  = (const float*)d_in[5];
    const float* mlp_b1  = (const float*)d_in[6];
    const float* mlp_w2  = (const float*)d_in[7];
    const float* mlp_b2  = (const float*)d_in[8];
    const float* lin1_w  = (const float*)d_in[9];
    const float* lin2_w  = (const float*)d_in[10];
    const float* lin2_b  = (const float*)d_in[11];
    const float* lin_w   = (const float*)d_in[12];
    const float* lin_b   = (const float*)d_in[13];
    const float* out1_w  = (const float*)d_in[14];
    const float* out1_b  = (const float*)d_in[15];
    const float* out2_w  = (const float*)d_in[16];
    const float* out2_b  = (const float*)d_in[17];
    const float* pred_w  = (const float*)d_in[18];
    const float* pred_b  = (const float*)d_in[19];
    float* out = (float*)d_out;

    float* p_h;
    void *p_xjh, *p_hh, *p_aggh;
    __half* p_wt;
    cudaGetSymbolAddress((void**)&p_h, g_h);
    cudaGetSymbolAddress(&p_hh, g_hh);
    cudaGetSymbolAddress(&p_xjh, g_xjh);
    cudaGetSymbolAddress(&p_aggh, g_aggh);
    cudaGetSymbolAddress((void**)&p_wt, g_wt);

    int dev = 0, smCount = 148;
    cudaGetDevice(&dev);
    cudaDeviceGetAttribute(&smCount, cudaDevAttrMultiProcessorCount, dev);

    const int TAB_SMEM = TAB * 512;                 // 49152 (interleaved pairs)
    cudaFuncSetAttribute(edge_conv_csr_kernel, cudaFuncAttributeMaxDynamicSharedMemorySize, TAB_SMEM);

    const int SM_G16 = 65536;
    const int SM_FA  = 16384 + 16384 + 32768;       // 65536 (N1=128)
    const int SM_FB  = 16384 + 16384 + 16384;       // 49152 (N1=64)
    cudaFuncSetAttribute(mma_gemm16_kernel<128, true>,
                         cudaFuncAttributeMaxDynamicSharedMemorySize, SM_G16);
    cudaFuncSetAttribute(fused2_kernel<128, 128, 128, false, true>,
                         cudaFuncAttributeMaxDynamicSharedMemorySize, SM_FA);
    cudaFuncSetAttribute(fused2_kernel<128, 64, 128, true, true>,
                         cudaFuncAttributeMaxDynamicSharedMemorySize, SM_FB);

    int gblocks = (NN + 127) / 128;

    // prep
    dim3 tg(64, 8);
    transpose_all_kernel<<<tg, 256>>>(lin1_w, lin2_w, lin_w, out1_w, out2_w, p_wt);
    prep_kernel<<<(NN * 32 + 255) / 256, 256>>>(z, emb);
    dim3 tb(TAB, 2);
    build_table_kernel<<<tb, HH>>>(mlp_w1, mlp_b1, mlp_w2, mlp_b2);
    mma_gemm16_kernel<128, true><<<gblocks, 256, SM_G16>>>(
        (const __half*)p_hh, p_wt + WT_LIN1(0), p_xjh);
    hist_kernel<<<(EE / 4 + 255) / 256, 256>>>(ei);
    scan1_kernel<<<NBLK, SCAN_B>>>();
    scan3_kernel<<<NBLK, SCAN_B>>>();
    fill_kernel<<<(EE / 4 + 255) / 256, 256>>>(ei, pos);

    for (int i = 0; i < 2; i++) {
        if (i > 0) {
            mma_gemm16_kernel<128, true><<<gblocks, 256, SM_G16>>>(
                (const __half*)p_hh, p_wt + WT_LIN1(i), p_xjh);
        }
        edge_conv_csr_kernel<<<2 * smCount, 1024, TAB_SMEM>>>(i);
        fused2_kernel<128, 128, 128, false, true><<<gblocks, 256, SM_FA>>>(
            p_aggh,
            p_wt + WT_LIN2(i), lin2_b + (size_t)i * HH,
            p_wt + WT_LIN(i),  lin_b + (size_t)i * HH,
            p_h, nullptr);
    }

    fused2_kernel<128, 64, 128, true, true><<<gblocks, 256, SM_FB>>>(
        p_hh,
        p_wt + WT_OUT1, out1_b,
        p_wt + WT_OUT2, out2_b,
        nullptr, batch);
    final_kernel<<<1, 256>>>(pred_w, pred_b, out);
}

// round 14
// speedup vs baseline: 1.1572x; 1.0319x over previous
#include <cuda_runtime.h>
#include <cuda_bf16.h>
#include <cuda_fp16.h>
#include <stdint.h>
#include <math.h>

#define NN 50000
#define EE 1600000
#define HH 128
#define BB 64
#define TT 4
#define GG 10
#define TAB 96
#define D_MAX 8.6603f
#define SCAN_B 1024
#define NBLK ((NN + SCAN_B - 1) / SCAN_B)

// scratch (static device globals — no runtime allocation)
static __device__ float g_table[TAB * HH * 2];   // fp32 master table (2 interactions)
static __device__ float g_h[NN * HH];
static __device__ __half g_hh[NN * HH];          // fp16 shadow of h (GEMM A operand)
static __device__ __half g_xjh[NN * HH];
static __device__ __half g_aggh[NN * HH];        // fp16 agg (GEMM A operand)
static __device__ float g_pooled[BB * HH];
static __device__ __half g_wt[7 * 16384];        // transposed fp16 weights
// CSR (dst-major)
static __device__ int  g_deg[NN];
static __device__ int  g_ptr[NN + 1];
static __device__ int  g_work[NN];
static __device__ int  g_bsum[NBLK];
static __device__ int2 g_csr[EE];                // {src | i0<<16, half2(f,f) bits}

#define WT_LIN1(i)  ((size_t)(i) * 16384)
#define WT_LIN2(i)  ((size_t)(32768) + (size_t)(i) * 16384)
#define WT_LIN(i)   ((size_t)(65536) + (size_t)(i) * 16384)
#define WT_OUT1     ((size_t)98304)
#define WT_OUT2     ((size_t)106496)

__device__ __forceinline__ float sspf(float x) {
    float ax = fabsf(x);
    return fmaxf(x, 0.0f) + log1pf(__expf(-ax)) - 0.6931471805599453f;
}

#define SWZ(off) ((off) ^ (((off) >> 3) & 0x70))

__device__ __forceinline__ unsigned smem_u32(const void* p) {
    return (unsigned)__cvta_generic_to_shared(p);
}
__device__ __forceinline__ void ldsm_x4(unsigned* r, unsigned addr) {
    asm volatile("ldmatrix.sync.aligned.m8n8.x4.shared.b16 {%0,%1,%2,%3}, [%4];"
                 : "=r"(r[0]), "=r"(r[1]), "=r"(r[2]), "=r"(r[3]) : "r"(addr));
}
__device__ __forceinline__ void ldsm_x2(unsigned* r, unsigned addr) {
    asm volatile("ldmatrix.sync.aligned.m8n8.x2.shared.b16 {%0,%1}, [%2];"
                 : "=r"(r[0]), "=r"(r[1]) : "r"(addr));
}
__device__ __forceinline__ void mma_fp16(float* d, const unsigned* a, const unsigned* b) {
    asm volatile("mma.sync.aligned.m16n8k16.row.col.f32.f16.f16.f32 "
                 "{%0,%1,%2,%3}, {%4,%5,%6,%7}, {%8,%9}, {%0,%1,%2,%3};"
                 : "+f"(d[0]), "+f"(d[1]), "+f"(d[2]), "+f"(d[3])
                 : "r"(a[0]), "r"(a[1]), "r"(a[2]), "r"(a[3]), "r"(b[0]), "r"(b[1]));
}

// ---------------------------------------------------------------------------
// Build filter table (fp32 master, TAB knots)
// ---------------------------------------------------------------------------
__global__ void build_table_kernel(const float* __restrict__ w1, const float* __restrict__ b1,
                                   const float* __restrict__ w2, const float* __restrict__ b2) {
    int row = blockIdx.x;
    int inter = blockIdx.y;
    int tid = threadIdx.x;
    float d = row * (D_MAX / (float)(TAB - 1));

    __shared__ float hid[HH];
    const float* w1i = w1 + (size_t)inter * GG * HH;
    const float* b1i = b1 + (size_t)inter * HH;
    const float* w2i = w2 + (size_t)inter * HH * HH;
    const float* b2i = b2 + (size_t)inter * HH;

    const float step = 10.0f / 9.0f;
    const float coeff = -0.5f / (step * step);

    float acc = b1i[tid];
    #pragma unroll
    for (int g = 0; g < GG; g++) {
        float diff = d - (float)g * step;
        float r = expf(coeff * diff * diff);
        acc += r * w1i[g * HH + tid];
    }
    hid[tid] = sspf(acc);
    __syncthreads();

    float acc2 = b2i[tid];
    for (int k = 0; k < HH; k++)
        acc2 = fmaf(hid[k], w2i[k * HH + tid], acc2);

    float C = 0.5f * (cosf(d * 3.14159265358979f / 10.0f) + 1.0f);
    g_table[((size_t)inter * TAB + row) * HH + tid] = acc2 * C;
}

// ---------------------------------------------------------------------------
// Merged weight transpose + fp16 convert
// ---------------------------------------------------------------------------
__global__ void transpose_all_kernel(const float* __restrict__ lin1_w,
                                     const float* __restrict__ lin2_w,
                                     const float* __restrict__ lin_w,
                                     const float* __restrict__ out1_w,
                                     const float* __restrict__ out2_w,
                                     __half* __restrict__ wt) {
    int m = blockIdx.y;
    const float* src;
    size_t off;
    int K, N;
    switch (m) {
        case 0: src = lin1_w;          off = WT_LIN1(0); K = 128; N = 128; break;
        case 1: src = lin1_w + 16384;  off = WT_LIN1(1); K = 128; N = 128; break;
        case 2: src = lin2_w;          off = WT_LIN2(0); K = 128; N = 128; break;
        case 3: src = lin2_w + 16384;  off = WT_LIN2(1); K = 128; N = 128; break;
        case 4: src = lin_w;           off = WT_LIN(0);  K = 128; N = 128; break;
        case 5: src = lin_w + 16384;   off = WT_LIN(1);  K = 128; N = 128; break;
        case 6: src = out1_w;          off = WT_OUT1;    K = 128; N = 64;  break;
        default: src = out2_w;         off = WT_OUT2;    K = 64;  N = 128; break;
    }
    int i = blockIdx.x * blockDim.x + threadIdx.x;
    if (i >= K * N) return;
    int k = i / N, n = i % N;
    wt[off + (size_t)n * K + k] = __float2half_rn(src[i]);
}

// ---------------------------------------------------------------------------
// Fused prep: embedding gather (fp32 + fp16 shadow) + zero pooled
// ---------------------------------------------------------------------------
__global__ void prep_kernel(const int* __restrict__ z, const float* __restrict__ emb) {
    int idx = blockIdx.x * blockDim.x + threadIdx.x;
    if (idx < NN * (HH / 4)) {
        int n = idx >> 5;
        int c = idx & 31;
        float4 v = ((const float4*)emb)[(size_t)z[n] * (HH / 4) + c];
        ((float4*)g_h)[idx] = v;
        __half2 pk[2] = {__floats2half2_rn(v.x, v.y), __floats2half2_rn(v.z, v.w)};
        ((uint2*)g_hh)[idx] = *(uint2*)pk;
    }
    if (idx < BB * HH) g_pooled[idx] = 0.f;
}

// ---------------------------------------------------------------------------
// CSR construction (aux stream)
// ---------------------------------------------------------------------------
__global__ void zero_deg_kernel() {
    int i = blockIdx.x * blockDim.x + threadIdx.x;
    if (i < NN) g_deg[i] = 0;
}

__global__ void hist_kernel(const int* __restrict__ ei) {
    int i = blockIdx.x * blockDim.x + threadIdx.x;
    if (i >= EE / 4) return;
    int4 d4 = ((const int4*)(ei + EE))[i];
    atomicAdd(&g_deg[d4.x], 1);
    atomicAdd(&g_deg[d4.y], 1);
    atomicAdd(&g_deg[d4.z], 1);
    atomicAdd(&g_deg[d4.w], 1);
}

__global__ void scan1_kernel() {
    __shared__ int sm[SCAN_B];
    int idx = blockIdx.x * SCAN_B + threadIdx.x;
    int v = (idx < NN) ? g_deg[idx] : 0;
    sm[threadIdx.x] = v;
    __syncthreads();
    for (int off = SCAN_B / 2; off > 0; off >>= 1) {
        if (threadIdx.x < off) sm[threadIdx.x] += sm[threadIdx.x + off];
        __syncthreads();
    }
    if (threadIdx.x == 0) g_bsum[blockIdx.x] = sm[0];
}

__global__ void scan3_kernel() {
    __shared__ int sm[SCAN_B];
    __shared__ int blockoff;
    int idx = blockIdx.x * SCAN_B + threadIdx.x;
    int v = (idx < NN) ? g_deg[idx] : 0;
    sm[threadIdx.x] = v;
    if (threadIdx.x == 0) {
        int run = 0;
        for (int b = 0; b < blockIdx.x; b++) run += g_bsum[b];
        blockoff = run;
    }
    __syncthreads();
    for (int off = 1; off < SCAN_B; off <<= 1) {
        int add = (threadIdx.x >= off) ? sm[threadIdx.x - off] : 0;
        __syncthreads();
        sm[threadIdx.x] += add;
        __syncthreads();
    }
    if (idx < NN) {
        int excl = blockoff + sm[threadIdx.x] - v;
        g_ptr[idx] = excl;
        g_work[idx] = excl;
        if (idx == NN - 1) g_ptr[NN] = blockoff + sm[threadIdx.x];
    }
}

__global__ void fill_kernel(const int* __restrict__ ei, const float* __restrict__ pos) {
    int i = blockIdx.x * blockDim.x + threadIdx.x;
    if (i >= EE / 4) return;
    int4 s4 = ((const int4*)ei)[i];
    int4 d4 = ((const int4*)(ei + EE))[i];
    const float INV_STEP = (float)(TAB - 1) / D_MAX;
    #pragma unroll
    for (int q = 0; q < 4; q++) {
        int s = (&s4.x)[q];
        int d = (&d4.x)[q];
        float dx = pos[s * 3 + 0] - pos[d * 3 + 0];
        float dy = pos[s * 3 + 1] - pos[d * 3 + 1];
        float dz = pos[s * 3 + 2] - pos[d * 3 + 2];
        float dist = sqrtf(dx * dx + dy * dy + dz * dz);
        float t = dist * INV_STEP;
        int i0 = min((int)t, TAB - 2);
        float f = t - (float)i0;
        __half2 f2 = __float2half2_rn(f);
        int slot = atomicAdd(&g_work[d], 1);
        g_csr[slot] = make_int2(s | (i0 << 16), *(int*)&f2);
    }
}

// ---------------------------------------------------------------------------
// CSR edge aggregation: pair-interleaved fp16 table (one LDS.128 per edge),
// half2 math, fp32 accumulation, fp16 agg output. TAB=96 -> 48KB -> 2 blk/SM.
// ---------------------------------------------------------------------------
#define EDGE_PROD(J, P0, P1) {                                                      \
    int cx  = __shfl_sync(0xffffffffu, c.x, (J));                                   \
    int cyi = __shfl_sync(0xffffffffu, c.y, (J));                                   \
    int s  = cx & 0xffff;                                                           \
    int i0 = cx >> 16;                                                              \
    __half2 f2 = *reinterpret_cast<__half2*>(&cyi);                                 \
    uint2 xw = *(const uint2*)(g_xjh + (size_t)s * HH + lane * 4);                  \
    __half2 x0 = *reinterpret_cast<__half2*>(&xw.x);                                \
    __half2 x1 = *reinterpret_cast<__half2*>(&xw.y);                                \
    uint4 wv = *(const uint4*)(tab + i0 * 256 + lane * 8);                          \
    __half2 w0a = *reinterpret_cast<__half2*>(&wv.x);                               \
    __half2 w0b = *reinterpret_cast<__half2*>(&wv.y);                               \
    __half2 w1a = *reinterpret_cast<__half2*>(&wv.z);                               \
    __half2 w1b = *reinterpret_cast<__half2*>(&wv.w);                               \
    P0 = __hmul2(__hfma2(__hsub2(w1a, w0a), f2, w0a), x0);                          \
    P1 = __hmul2(__hfma2(__hsub2(w1b, w0b), f2, w0b), x1);                          \
}

__global__ void __launch_bounds__(1024, 2) edge_conv_csr_kernel(int inter) {
    extern __shared__ __half tab[];
    const float4* tsrc = (const float4*)(g_table + (size_t)inter * TAB * HH);
    for (int cch = threadIdx.x; cch < TAB * 32; cch += 1024) {
        int i = cch >> 5, g = cch & 31;
        int i1 = min(i + 1, TAB - 1);
        float4 r0 = tsrc[i * 32 + g];
        float4 r1 = tsrc[i1 * 32 + g];
        __half2 hh[4];
        hh[0] = __floats2half2_rn(r0.x, r0.y);
        hh[1] = __floats2half2_rn(r0.z, r0.w);
        hh[2] = __floats2half2_rn(r1.x, r1.y);
        hh[3] = __floats2half2_rn(r1.z, r1.w);
        ((uint4*)tab)[cch] = *(uint4*)hh;
    }
    __syncthreads();

    int lane = threadIdx.x & 31;
    int gwarp = blockIdx.x * 32 + (threadIdx.x >> 5);
    int nwarp = gridDim.x * 32;

    for (int node = gwarp; node < NN; node += nwarp) {
        int beg = __ldg(&g_ptr[node]);
        int end = __ldg(&g_ptr[node + 1]);

        float4 acc = make_float4(0.f, 0.f, 0.f, 0.f);
        int base = beg;
        for (; base + 32 <= end; base += 32) {
            int2 c = __ldg(&g_csr[base + lane]);
            #pragma unroll 8
            for (int j = 0; j < 32; j += 2) {
                __half2 a0, a1, b0, b1;
                EDGE_PROD(j, a0, a1);
                EDGE_PROD(j + 1, b0, b1);
                __half2 s0 = __hadd2(a0, b0);
                __half2 s1 = __hadd2(a1, b1);
                float2 f0 = __half22float2(s0);
                float2 f1 = __half22float2(s1);
                acc.x += f0.x; acc.y += f0.y; acc.z += f1.x; acc.w += f1.y;
            }
        }
        if (base < end) {
            int k = base + lane;
            int2 c = (k < end) ? __ldg(&g_csr[k]) : make_int2(0, 0);
            int cnt = end - base;
            for (int j = 0; j < cnt; j++) {
                __half2 p0, p1;
                EDGE_PROD(j, p0, p1);
                float2 f0 = __half22float2(p0);
                float2 f1 = __half22float2(p1);
                acc.x += f0.x; acc.y += f0.y; acc.z += f1.x; acc.w += f1.y;
            }
        }
        __half2 o0 = __floats2half2_rn(acc.x, acc.y);
        __half2 o1 = __floats2half2_rn(acc.z, acc.w);
        __half2 op[2] = {o0, o1};
        *(uint2*)(g_aggh + (size_t)node * HH + lane * 4) = *(uint2*)op;
    }
}

// ---------------------------------------------------------------------------
// Pair epilogue (HHCOPY also mirrors result into g_hh fp16)
// ---------------------------------------------------------------------------
template <int NCOL, bool BIAS, bool ACT, bool RESID, bool POOL, bool OFP16, bool HHCOPY>
__device__ __forceinline__ void epi2(int row, int col, float v0, float v1,
                                     const float* __restrict__ bias, void* outv,
                                     const int* __restrict__ batch) {
    if (row >= NN) return;
    if (BIAS) { v0 += bias[col]; v1 += bias[col + 1]; }
    if (ACT)  { v0 = sspf(v0); v1 = sspf(v1); }
    if (POOL) {
        int b = batch[row];
        float* p = g_pooled + (size_t)b * NCOL + col;
        asm volatile("red.global.add.v2.f32 [%0], {%1,%2};" :: "l"(p), "f"(v0), "f"(v1) : "memory");
    } else if (OFP16) {
        __half2 pk = __floats2half2_rn(v0, v1);
        *(unsigned*)((__half*)outv + (size_t)row * NCOL + col) = *(unsigned*)&pk;
    } else {
        float* o = (float*)outv + (size_t)row * NCOL + col;
        if (RESID) {
            float2 h = *(float2*)o;
            v0 += h.x; v1 += h.y;
        }
        *(float2*)o = make_float2(v0, v1);
        if (HHCOPY) {
            __half2 pk = __floats2half2_rn(v0, v1);
            *(unsigned*)(g_hh + (size_t)row * NCOL + col) = *(unsigned*)&pk;
        }
    }
}

// ---------------------------------------------------------------------------
// fp16 tensor-core GEMM, single-stage K=128 (A already fp16): out = A @ Wt^T
// ---------------------------------------------------------------------------
template <int NCOL, bool OFP16>
__global__ void __launch_bounds__(256, 2)
mma_gemm16_kernel(const __half* __restrict__ A,
                  const __half* __restrict__ Wt,
                  void* outv) {
    constexpr int KDIM = 128;
    constexpr int WN = NCOL / 2;
    constexpr int NT = WN / 8;
    constexpr int PANEL = 16384;

    extern __shared__ char dynsm[];
    char* As = dynsm;
    char* Bs = dynsm + 2 * PANEL;

    int tid = threadIdx.x;
    int warp = tid >> 5, lane = tid & 31;
    int wm = warp & 3, wn = warp >> 2;
    int row0 = blockIdx.x * 128;

    float acc[2][NT][4];
    #pragma unroll
    for (int mt = 0; mt < 2; mt++)
        #pragma unroll
        for (int nt = 0; nt < NT; nt++)
            #pragma unroll
            for (int q = 0; q < 4; q++) acc[mt][nt][q] = 0.f;

    unsigned as_base = smem_u32(As);
    unsigned bs_base = smem_u32(Bs);

    #pragma unroll
    for (int i = tid; i < 128 * 16; i += 256) {
        int r = i >> 4, ch = i & 15;
        int grow = row0 + r;
        uint4 v = make_uint4(0, 0, 0, 0);
        if (grow < NN)
            v = *(const uint4*)(A + (size_t)grow * KDIM + ch * 8);
        *(uint4*)(As + (ch >> 3) * PANEL + SWZ(r * 128 + (ch & 7) * 16)) = v;
    }
    #pragma unroll
    for (int i = tid; i < NCOL * 16; i += 256) {
        int r = i >> 4, ch = i & 15;
        uint4 v = *(const uint4*)(Wt + (size_t)r * KDIM + ch * 8);
        *(uint4*)(Bs + (ch >> 3) * PANEL + SWZ(r * 128 + (ch & 7) * 16)) = v;
    }
    __syncthreads();

    #pragma unroll
    for (int ks = 0; ks < 8; ks++) {
        int poff = (ks >> 2) * PANEL;
        int koff = (ks & 3) * 32;
        unsigned a[2][4];
        #pragma unroll
        for (int mt = 0; mt < 2; mt++) {
            int r = wm * 32 + mt * 16 + (lane & 15);
            ldsm_x4(a[mt], as_base + poff + SWZ(r * 128 + koff + (lane >> 4) * 16));
        }
        #pragma unroll
        for (int nt = 0; nt < NT; nt++) {
            unsigned b[2];
            int l = lane & 15;
            int r = wn * WN + nt * 8 + (l & 7);
            ldsm_x2(b, bs_base + poff + SWZ(r * 128 + koff + ((l >> 3) & 1) * 16));
            mma_fp16(acc[0][nt], a[0], b);
            mma_fp16(acc[1][nt], a[1], b);
        }
    }

    #pragma unroll
    for (int mt = 0; mt < 2; mt++) {
        #pragma unroll
        for (int nt = 0; nt < NT; nt++) {
            int r = row0 + wm * 32 + mt * 16 + (lane >> 2);
            int c = wn * WN + nt * 8 + (lane & 3) * 2;
            epi2<NCOL, false, false, false, false, OFP16, false>(r, c, acc[mt][nt][0], acc[mt][nt][1], nullptr, outv, nullptr);
            epi2<NCOL, false, false, false, false, OFP16, false>(r + 8, c, acc[mt][nt][2], acc[mt][nt][3], nullptr, outv, nullptr);
        }
    }
}

// ---------------------------------------------------------------------------
// Fused two-GEMM chain: T = ssp(A@W1 + b1); out2 = T@W2 + b2
// AFP16: A already fp16.  POOL2: pool epilogue; else residual h update (+hh copy)
// ---------------------------------------------------------------------------
template <int K1, int N1, int N2, bool POOL2, bool AFP16>
__global__ void __launch_bounds__(256, 2)
fused2_kernel(const void* __restrict__ Av,
              const __half* __restrict__ W1, const float* __restrict__ b1,
              const __half* __restrict__ W2, const float* __restrict__ b2,
              float* __restrict__ outh, const int* __restrict__ batch) {
    constexpr int WN1 = N1 / 2, NT1 = WN1 / 8;
    constexpr int WN2 = N2 / 2, NT2 = WN2 / 8;
    constexpr int A_B = 128 * 64 * 2;
    constexpr int B_B = 16384;
    constexpr int PANEL = 128 * 64 * 2;

    extern __shared__ char dynsm[];
    char* As = dynsm;
    char* Bs = dynsm + A_B;
    char* Ts = dynsm + A_B + B_B;

    int tid = threadIdx.x;
    int warp = tid >> 5, lane = tid & 31;
    int wm = warp & 3, wn = warp >> 2;
    int row0 = blockIdx.x * 128;

    unsigned as_base = smem_u32(As);
    unsigned bs_base = smem_u32(Bs);
    unsigned ts_base = smem_u32(Ts);

    float acc1[2][NT1][4];
    #pragma unroll
    for (int mt = 0; mt < 2; mt++)
        #pragma unroll
        for (int nt = 0; nt < NT1; nt++)
            #pragma unroll
            for (int q = 0; q < 4; q++) acc1[mt][nt][q] = 0.f;

    for (int k0 = 0; k0 < K1; k0 += 64) {
        #pragma unroll
        for (int i = tid; i < 128 * 8; i += 256) {
            int r = i >> 3, ch = i & 7;
            int grow = row0 + r;
            if (AFP16) {
                uint4 v = make_uint4(0, 0, 0, 0);
                if (grow < NN)
                    v = *(const uint4*)((const __half*)Av + (size_t)grow * K1 + k0 + ch * 8);
                *(uint4*)(As + SWZ(r * 128 + ch * 16)) = v;
            } else {
                float v[8] = {0.f, 0.f, 0.f, 0.f, 0.f, 0.f, 0.f, 0.f};
                if (grow < NN) {
                    const float* gp = (const float*)Av + (size_t)grow * K1 + k0 + ch * 8;
                    float4 f0 = *(const float4*)gp;
                    float4 f1 = *(const float4*)(gp + 4);
                    v[0] = f0.x; v[1] = f0.y; v[2] = f0.z; v[3] = f0.w;
                    v[4] = f1.x; v[5] = f1.y; v[6] = f1.z; v[7] = f1.w;
                }
                __half2 hh[4];
                #pragma unroll
                for (int q = 0; q < 4; q++) hh[q] = __floats2half2_rn(v[2 * q], v[2 * q + 1]);
                *(uint4*)(As + SWZ(r * 128 + ch * 16)) = *(uint4*)hh;
            }
        }
        #pragma unroll
        for (int i = tid; i < N1 * 8; i += 256) {
            int r = i >> 3, ch = i & 7;
            uint4 w = *(const uint4*)(W1 + (size_t)r * K1 + k0 + ch * 8);
            *(uint4*)(Bs + SWZ(r * 128 + ch * 16)) = w;
        }
        __syncthreads();

        #pragma unroll
        for (int ks = 0; ks < 4; ks++) {
            unsigned a[2][4];
            #pragma unroll
            for (int mt = 0; mt < 2; mt++) {
                int r = wm * 32 + mt * 16 + (lane & 15);
                ldsm_x4(a[mt], as_base + SWZ(r * 128 + ks * 32 + (lane >> 4) * 16));
            }
            #pragma unroll
            for (int nt = 0; nt < NT1; nt++) {
                unsigned b[2];
                int l = lane & 15;
                int r = wn * WN1 + nt * 8 + (l & 7);
                ldsm_x2(b, bs_base + SWZ(r * 128 + ks * 32 + ((l >> 3) & 1) * 16));
                mma_fp16(acc1[0][nt], a[0], b);
                mma_fp16(acc1[1][nt], a[1], b);
            }
        }
        __syncthreads();
    }

    #pragma unroll
    for (int mt = 0; mt < 2; mt++) {
        #pragma unroll
        for (int nt = 0; nt < NT1; nt++) {
            int c = wn * WN1 + nt * 8 + (lane & 3) * 2;
            int panel_off = (c >> 6) * PANEL;
            int kk2 = (c & 63) * 2;
            #pragma unroll
            for (int half = 0; half < 2; half++) {
                int rl = wm * 32 + mt * 16 + (lane >> 2) + half * 8;
                float v0 = sspf(acc1[mt][nt][half * 2 + 0] + b1[c]);
                float v1 = sspf(acc1[mt][nt][half * 2 + 1] + b1[c + 1]);
                __half2 pk = __floats2half2_rn(v0, v1);
                *(unsigned*)(Ts + panel_off + SWZ(rl * 128 + kk2)) = *(unsigned*)&pk;
            }
        }
    }
    __syncthreads();

    float acc2[2][NT2][4];
    #pragma unroll
    for (int mt = 0; mt < 2; mt++)
        #pragma unroll
        for (int nt = 0; nt < NT2; nt++)
            #pragma unroll
            for (int q = 0; q < 4; q++) acc2[mt][nt][q] = 0.f;

    for (int k0 = 0; k0 < N1; k0 += 64) {
        #pragma unroll
        for (int i = tid; i < N2 * 8; i += 256) {
            int r = i >> 3, ch = i & 7;
            uint4 w = *(const uint4*)(W2 + (size_t)r * N1 + k0 + ch * 8);
            *(uint4*)(Bs + SWZ(r * 128 + ch * 16)) = w;
        }
        __syncthreads();

        int panel_off = (k0 >> 6) * PANEL;
        #pragma unroll
        for (int ks = 0; ks < 4; ks++) {
            unsigned a[2][4];
            #pragma unroll
            for (int mt = 0; mt < 2; mt++) {
                int r = wm * 32 + mt * 16 + (lane & 15);
                ldsm_x4(a[mt], ts_base + panel_off + SWZ(r * 128 + ks * 32 + (lane >> 4) * 16));
            }
            #pragma unroll
            for (int nt = 0; nt < NT2; nt++) {
                unsigned b[2];
                int l = lane & 15;
                int r = wn * WN2 + nt * 8 + (l & 7);
                ldsm_x2(b, bs_base + SWZ(r * 128 + ks * 32 + ((l >> 3) & 1) * 16));
                mma_fp16(acc2[0][nt], a[0], b);
                mma_fp16(acc2[1][nt], a[1], b);
            }
        }
        __syncthreads();
    }

    #pragma unroll
    for (int mt = 0; mt < 2; mt++) {
        #pragma unroll
        for (int nt = 0; nt < NT2; nt++) {
            int r = row0 + wm * 32 + mt * 16 + (lane >> 2);
            int c = wn * WN2 + nt * 8 + (lane & 3) * 2;
            epi2<N2, true, false, !POOL2, POOL2, false, !POOL2>(r, c, acc2[mt][nt][0], acc2[mt][nt][1], b2, outh, batch);
            epi2<N2, true, false, !POOL2, POOL2, false, !POOL2>(r + 8, c, acc2[mt][nt][2], acc2[mt][nt][3], b2, outh, batch);
        }
    }
}

// ---------------------------------------------------------------------------
// Final tiny GEMM
// ---------------------------------------------------------------------------
__global__ void final_kernel(const float* __restrict__ pw, const float* __restrict__ pb,
                             float* __restrict__ out) {
    int tid = threadIdx.x;
    int b = tid >> 2;
    int t = tid & 3;
    float acc = pb[t];
    for (int k = 0; k < HH; k++)
        acc = fmaf(g_pooled[b * HH + k], pw[k * TT + t], acc);
    out[b * TT + t] = acc;
}

// ---------------------------------------------------------------------------
extern "C" void kernel_launch(void* const* d_in, const int* in_sizes, int n_in,
                              void* d_out, int out_size) {
    const int*   z       = (const int*)d_in[0];
    const float* pos     = (const float*)d_in[1];
    const int*   batch   = (const int*)d_in[2];
    const int*   ei      = (const int*)d_in[3];
    const float* emb     = (const float*)d_in[4];
    const float* mlp_w1  = (const float*)d_in[5];
    const float* mlp_b1  = (const float*)d_in[6];
    const float* mlp_w2  = (const float*)d_in[7];
    const float* mlp_b2  = (const float*)d_in[8];
    const float* lin1_w  = (const float*)d_in[9];
    const float* lin2_w  = (const float*)d_in[10];
    const float* lin2_b  = (const float*)d_in[11];
    const float* lin_w   = (const float*)d_in[12];
    const float* lin_b   = (const float*)d_in[13];
    const float* out1_w  = (const float*)d_in[14];
    const float* out1_b  = (const float*)d_in[15];
    const float* out2_w  = (const float*)d_in[16];
    const float* out2_b  = (const float*)d_in[17];
    const float* pred_w  = (const float*)d_in[18];
    const float* pred_b  = (const float*)d_in[19];
    float* out = (float*)d_out;

    float* p_h;
    void *p_xjh, *p_hh, *p_aggh;
    __half* p_wt;
    cudaGetSymbolAddress((void**)&p_h, g_h);
    cudaGetSymbolAddress(&p_hh, g_hh);
    cudaGetSymbolAddress(&p_xjh, g_xjh);
    cudaGetSymbolAddress(&p_aggh, g_aggh);
    cudaGetSymbolAddress((void**)&p_wt, g_wt);

    int dev = 0, smCount = 148;
    cudaGetDevice(&dev);
    cudaDeviceGetAttribute(&smCount, cudaDevAttrMultiProcessorCount, dev);

    // one-time host-side stream/event objects (no device memory)
    static cudaStream_t s_aux = nullptr;
    static cudaEvent_t ev_fork = nullptr, ev_join = nullptr;
    if (!s_aux) {
        cudaStreamCreateWithFlags(&s_aux, cudaStreamNonBlocking);
        cudaEventCreateWithFlags(&ev_fork, cudaEventDisableTiming);
        cudaEventCreateWithFlags(&ev_join, cudaEventDisableTiming);
    }

    const int TAB_SMEM = TAB * 512;                 // 49152 (interleaved pairs)
    cudaFuncSetAttribute(edge_conv_csr_kernel, cudaFuncAttributeMaxDynamicSharedMemorySize, TAB_SMEM);

    const int SM_G16 = 65536;
    const int SM_FA  = 16384 + 16384 + 32768;       // 65536 (N1=128)
    const int SM_FB  = 16384 + 16384 + 16384;       // 49152 (N1=64)
    cudaFuncSetAttribute(mma_gemm16_kernel<128, true>,
                         cudaFuncAttributeMaxDynamicSharedMemorySize, SM_G16);
    cudaFuncSetAttribute(fused2_kernel<128, 128, 128, false, true>,
                         cudaFuncAttributeMaxDynamicSharedMemorySize, SM_FA);
    cudaFuncSetAttribute(fused2_kernel<128, 64, 128, true, true>,
                         cudaFuncAttributeMaxDynamicSharedMemorySize, SM_FB);

    int gblocks = (NN + 127) / 128;

    // ---- fork: CSR build on aux stream, concurrent with weight/table/lin1 prep
    cudaEventRecord(ev_fork, 0);
    cudaStreamWaitEvent(s_aux, ev_fork, 0);
    zero_deg_kernel<<<(NN + 255) / 256, 256, 0, s_aux>>>();
    hist_kernel<<<(EE / 4 + 255) / 256, 256, 0, s_aux>>>(ei);
    scan1_kernel<<<NBLK, SCAN_B, 0, s_aux>>>();
    scan3_kernel<<<NBLK, SCAN_B, 0, s_aux>>>();
    fill_kernel<<<(EE / 4 + 255) / 256, 256, 0, s_aux>>>(ei, pos);
    cudaEventRecord(ev_join, s_aux);

    // ---- main stream: prep chain
    dim3 tg(64, 8);
    transpose_all_kernel<<<tg, 256>>>(lin1_w, lin2_w, lin_w, out1_w, out2_w, p_wt);
    prep_kernel<<<(NN * 32 + 255) / 256, 256>>>(z, emb);
    dim3 tb(TAB, 2);
    build_table_kernel<<<tb, HH>>>(mlp_w1, mlp_b1, mlp_w2, mlp_b2);
    mma_gemm16_kernel<128, true><<<gblocks, 256, SM_G16>>>(
        (const __half*)p_hh, p_wt + WT_LIN1(0), p_xjh);

    // ---- join before first edge conv
    cudaStreamWaitEvent(0, ev_join, 0);

    for (int i = 0; i < 2; i++) {
        if (i > 0) {
            mma_gemm16_kernel<128, true><<<gblocks, 256, SM_G16>>>(
                (const __half*)p_hh, p_wt + WT_LIN1(i), p_xjh);
        }
        edge_conv_csr_kernel<<<2 * smCount, 1024, TAB_SMEM>>>(i);
        fused2_kernel<128, 128, 128, false, true><<<gblocks, 256, SM_FA>>>(
            p_aggh,
            p_wt + WT_LIN2(i), lin2_b + (size_t)i * HH,
            p_wt + WT_LIN(i),  lin_b + (size_t)i * HH,
            p_h, nullptr);
    }

    fused2_kernel<128, 64, 128, true, true><<<gblocks, 256, SM_FB>>>(
        p_hh,
        p_wt + WT_OUT1, out1_b,
        p_wt + WT_OUT2, out2_b,
        nullptr, batch);
    final_kernel<<<1, 256>>>(pred_w, pred_b, out);
}

// round 15
// speedup vs baseline: 1.1932x; 1.0311x over previous
#include <cuda_runtime.h>
#include <cuda_bf16.h>
#include <cuda_fp16.h>
#include <stdint.h>
#include <math.h>

#define NN 50000
#define EE 1600000
#define HH 128
#define BB 64
#define TT 4
#define GG 10
#define TAB 96
#define D_MAX 8.6603f
#define SCAN_B 1024
#define NBLK ((NN + SCAN_B - 1) / SCAN_B)

// scratch (static device globals — no runtime allocation)
static __device__ float g_table[TAB * HH * 2];
static __device__ float g_h[NN * HH];
static __device__ __half g_hh[NN * HH];
static __device__ __half g_xjh[NN * HH];
static __device__ __half g_aggh[NN * HH];
static __device__ float g_pooled[BB * HH];
static __device__ __half g_wt[7 * 16384];
// CSR (dst-major)
static __device__ int  g_deg[NN];
static __device__ int  g_ptr[NN + 1];
static __device__ int  g_work[NN];
static __device__ int  g_bsum[NBLK];
static __device__ int2 g_csr[EE];

#define WT_LIN1(i)  ((size_t)(i) * 16384)
#define WT_LIN2(i)  ((size_t)(32768) + (size_t)(i) * 16384)
#define WT_LIN(i)   ((size_t)(65536) + (size_t)(i) * 16384)
#define WT_OUT1     ((size_t)98304)
#define WT_OUT2     ((size_t)106496)

__device__ __forceinline__ float sspf(float x) {
    float ax = fabsf(x);
    return fmaxf(x, 0.0f) + log1pf(__expf(-ax)) - 0.6931471805599453f;
}

#define SWZ(off) ((off) ^ (((off) >> 3) & 0x70))

__device__ __forceinline__ unsigned smem_u32(const void* p) {
    return (unsigned)__cvta_generic_to_shared(p);
}
__device__ __forceinline__ void ldsm_x4(unsigned* r, unsigned addr) {
    asm volatile("ldmatrix.sync.aligned.m8n8.x4.shared.b16 {%0,%1,%2,%3}, [%4];"
                 : "=r"(r[0]), "=r"(r[1]), "=r"(r[2]), "=r"(r[3]) : "r"(addr));
}
__device__ __forceinline__ void ldsm_x2(unsigned* r, unsigned addr) {
    asm volatile("ldmatrix.sync.aligned.m8n8.x2.shared.b16 {%0,%1}, [%2];"
                 : "=r"(r[0]), "=r"(r[1]) : "r"(addr));
}
__device__ __forceinline__ void mma_fp16(float* d, const unsigned* a, const unsigned* b) {
    asm volatile("mma.sync.aligned.m16n8k16.row.col.f32.f16.f16.f32 "
                 "{%0,%1,%2,%3}, {%4,%5,%6,%7}, {%8,%9}, {%0,%1,%2,%3};"
                 : "+f"(d[0]), "+f"(d[1]), "+f"(d[2]), "+f"(d[3])
                 : "r"(a[0]), "r"(a[1]), "r"(a[2]), "r"(a[3]), "r"(b[0]), "r"(b[1]));
}

// ---------------------------------------------------------------------------
// Build filter table
// ---------------------------------------------------------------------------
__global__ void build_table_kernel(const float* __restrict__ w1, const float* __restrict__ b1,
                                   const float* __restrict__ w2, const float* __restrict__ b2) {
    int row = blockIdx.x;
    int inter = blockIdx.y;
    int tid = threadIdx.x;
    float d = row * (D_MAX / (float)(TAB - 1));

    __shared__ float hid[HH];
    const float* w1i = w1 + (size_t)inter * GG * HH;
    const float* b1i = b1 + (size_t)inter * HH;
    const float* w2i = w2 + (size_t)inter * HH * HH;
    const float* b2i = b2 + (size_t)inter * HH;

    const float step = 10.0f / 9.0f;
    const float coeff = -0.5f / (step * step);

    float acc = b1i[tid];
    #pragma unroll
    for (int g = 0; g < GG; g++) {
        float diff = d - (float)g * step;
        float r = expf(coeff * diff * diff);
        acc += r * w1i[g * HH + tid];
    }
    hid[tid] = sspf(acc);
    __syncthreads();

    float acc2 = b2i[tid];
    for (int k = 0; k < HH; k++)
        acc2 = fmaf(hid[k], w2i[k * HH + tid], acc2);

    float C = 0.5f * (cosf(d * 3.14159265358979f / 10.0f) + 1.0f);
    g_table[((size_t)inter * TAB + row) * HH + tid] = acc2 * C;
}

// ---------------------------------------------------------------------------
// Merged weight transpose + fp16 convert
// ---------------------------------------------------------------------------
__global__ void transpose_all_kernel(const float* __restrict__ lin1_w,
                                     const float* __restrict__ lin2_w,
                                     const float* __restrict__ lin_w,
                                     const float* __restrict__ out1_w,
                                     const float* __restrict__ out2_w,
                                     __half* __restrict__ wt) {
    int m = blockIdx.y;
    const float* src;
    size_t off;
    int K, N;
    switch (m) {
        case 0: src = lin1_w;          off = WT_LIN1(0); K = 128; N = 128; break;
        case 1: src = lin1_w + 16384;  off = WT_LIN1(1); K = 128; N = 128; break;
        case 2: src = lin2_w;          off = WT_LIN2(0); K = 128; N = 128; break;
        case 3: src = lin2_w + 16384;  off = WT_LIN2(1); K = 128; N = 128; break;
        case 4: src = lin_w;           off = WT_LIN(0);  K = 128; N = 128; break;
        case 5: src = lin_w + 16384;   off = WT_LIN(1);  K = 128; N = 128; break;
        case 6: src = out1_w;          off = WT_OUT1;    K = 128; N = 64;  break;
        default: src = out2_w;         off = WT_OUT2;    K = 64;  N = 128; break;
    }
    int i = blockIdx.x * blockDim.x + threadIdx.x;
    if (i >= K * N) return;
    int k = i / N, n = i % N;
    wt[off + (size_t)n * K + k] = __float2half_rn(src[i]);
}

// ---------------------------------------------------------------------------
// Fused prep: embedding gather (fp32 + fp16 shadow) + zero pooled
// ---------------------------------------------------------------------------
__global__ void prep_kernel(const int* __restrict__ z, const float* __restrict__ emb) {
    int idx = blockIdx.x * blockDim.x + threadIdx.x;
    if (idx < NN * (HH / 4)) {
        int n = idx >> 5;
        int c = idx & 31;
        float4 v = ((const float4*)emb)[(size_t)z[n] * (HH / 4) + c];
        ((float4*)g_h)[idx] = v;
        __half2 pk[2] = {__floats2half2_rn(v.x, v.y), __floats2half2_rn(v.z, v.w)};
        ((uint2*)g_hh)[idx] = *(uint2*)pk;
    }
    if (idx < BB * HH) g_pooled[idx] = 0.f;
}

// ---------------------------------------------------------------------------
// CSR construction (aux stream)
// ---------------------------------------------------------------------------
__global__ void zero_deg_kernel() {
    int i = blockIdx.x * blockDim.x + threadIdx.x;
    if (i < NN) g_deg[i] = 0;
}

__global__ void hist_kernel(const int* __restrict__ ei) {
    int i = blockIdx.x * blockDim.x + threadIdx.x;
    if (i >= EE / 4) return;
    int4 d4 = ((const int4*)(ei + EE))[i];
    atomicAdd(&g_deg[d4.x], 1);
    atomicAdd(&g_deg[d4.y], 1);
    atomicAdd(&g_deg[d4.z], 1);
    atomicAdd(&g_deg[d4.w], 1);
}

__global__ void scan1_kernel() {
    __shared__ int sm[SCAN_B];
    int idx = blockIdx.x * SCAN_B + threadIdx.x;
    int v = (idx < NN) ? g_deg[idx] : 0;
    sm[threadIdx.x] = v;
    __syncthreads();
    for (int off = SCAN_B / 2; off > 0; off >>= 1) {
        if (threadIdx.x < off) sm[threadIdx.x] += sm[threadIdx.x + off];
        __syncthreads();
    }
    if (threadIdx.x == 0) g_bsum[blockIdx.x] = sm[0];
}

__global__ void scan3_kernel() {
    __shared__ int sm[SCAN_B];
    __shared__ int soff[2];
    int idx = blockIdx.x * SCAN_B + threadIdx.x;
    int v = (idx < NN) ? g_deg[idx] : 0;
    sm[threadIdx.x] = v;
    // parallel cross-block offset (lanes load g_bsum concurrently)
    if (threadIdx.x < 64) {
        int t = threadIdx.x;
        int b = (t < NBLK && t < blockIdx.x) ? g_bsum[t] : 0;
        #pragma unroll
        for (int o = 16; o; o >>= 1) b += __shfl_down_sync(0xffffffffu, b, o);
        if ((t & 31) == 0) soff[t >> 5] = b;
    }
    __syncthreads();
    int blockoff = soff[0] + soff[1];
    for (int off = 1; off < SCAN_B; off <<= 1) {
        int add = (threadIdx.x >= off) ? sm[threadIdx.x - off] : 0;
        __syncthreads();
        sm[threadIdx.x] += add;
        __syncthreads();
    }
    if (idx < NN) {
        int excl = blockoff + sm[threadIdx.x] - v;
        g_ptr[idx] = excl;
        g_work[idx] = excl;
        if (idx == NN - 1) g_ptr[NN] = blockoff + sm[threadIdx.x];
    }
}

__global__ void fill_kernel(const int* __restrict__ ei, const float* __restrict__ pos) {
    int i = blockIdx.x * blockDim.x + threadIdx.x;
    if (i >= EE / 4) return;
    int4 s4 = ((const int4*)ei)[i];
    int4 d4 = ((const int4*)(ei + EE))[i];
    const float INV_STEP = (float)(TAB - 1) / D_MAX;
    #pragma unroll
    for (int q = 0; q < 4; q++) {
        int s = (&s4.x)[q];
        int d = (&d4.x)[q];
        float dx = pos[s * 3 + 0] - pos[d * 3 + 0];
        float dy = pos[s * 3 + 1] - pos[d * 3 + 1];
        float dz = pos[s * 3 + 2] - pos[d * 3 + 2];
        float dist = sqrtf(dx * dx + dy * dy + dz * dz);
        float t = dist * INV_STEP;
        int i0 = min((int)t, TAB - 2);
        float f = t - (float)i0;
        __half2 f2 = __float2half2_rn(f);
        int slot = atomicAdd(&g_work[d], 1);
        g_csr[slot] = make_int2(s | (i0 << 16), *(int*)&f2);
    }
}

// ---------------------------------------------------------------------------
// CSR edge aggregation: pair-interleaved fp16 table, half2 math, fp32 accum
// ---------------------------------------------------------------------------
#define EDGE_PROD(J, P0, P1) {                                                      \
    int cx  = __shfl_sync(0xffffffffu, c.x, (J));                                   \
    int cyi = __shfl_sync(0xffffffffu, c.y, (J));                                   \
    int s  = cx & 0xffff;                                                           \
    int i0 = cx >> 16;                                                              \
    __half2 f2 = *reinterpret_cast<__half2*>(&cyi);                                 \
    uint2 xw = *(const uint2*)(g_xjh + (size_t)s * HH + lane * 4);                  \
    __half2 x0 = *reinterpret_cast<__half2*>(&xw.x);                                \
    __half2 x1 = *reinterpret_cast<__half2*>(&xw.y);                                \
    uint4 wv = *(const uint4*)(tab + i0 * 256 + lane * 8);                          \
    __half2 w0a = *reinterpret_cast<__half2*>(&wv.x);                               \
    __half2 w0b = *reinterpret_cast<__half2*>(&wv.y);                               \
    __half2 w1a = *reinterpret_cast<__half2*>(&wv.z);                               \
    __half2 w1b = *reinterpret_cast<__half2*>(&wv.w);                               \
    P0 = __hmul2(__hfma2(__hsub2(w1a, w0a), f2, w0a), x0);                          \
    P1 = __hmul2(__hfma2(__hsub2(w1b, w0b), f2, w0b), x1);                          \
}

__global__ void __launch_bounds__(1024, 2) edge_conv_csr_kernel(int inter) {
    extern __shared__ __half tab[];
    const float4* tsrc = (const float4*)(g_table + (size_t)inter * TAB * HH);
    for (int cch = threadIdx.x; cch < TAB * 32; cch += 1024) {
        int i = cch >> 5, g = cch & 31;
        int i1 = min(i + 1, TAB - 1);
        float4 r0 = tsrc[i * 32 + g];
        float4 r1 = tsrc[i1 * 32 + g];
        __half2 hh[4];
        hh[0] = __floats2half2_rn(r0.x, r0.y);
        hh[1] = __floats2half2_rn(r0.z, r0.w);
        hh[2] = __floats2half2_rn(r1.x, r1.y);
        hh[3] = __floats2half2_rn(r1.z, r1.w);
        ((uint4*)tab)[cch] = *(uint4*)hh;
    }
    __syncthreads();

    int lane = threadIdx.x & 31;
    int gwarp = blockIdx.x * 32 + (threadIdx.x >> 5);
    int nwarp = gridDim.x * 32;

    for (int node = gwarp; node < NN; node += nwarp) {
        int beg = __ldg(&g_ptr[node]);
        int end = __ldg(&g_ptr[node + 1]);

        float4 acc = make_float4(0.f, 0.f, 0.f, 0.f);
        int base = beg;
        for (; base + 32 <= end; base += 32) {
            int2 c = __ldg(&g_csr[base + lane]);
            #pragma unroll 8
            for (int j = 0; j < 32; j += 2) {
                __half2 a0, a1, b0, b1;
                EDGE_PROD(j, a0, a1);
                EDGE_PROD(j + 1, b0, b1);
                __half2 s0 = __hadd2(a0, b0);
                __half2 s1 = __hadd2(a1, b1);
                float2 f0 = __half22float2(s0);
                float2 f1 = __half22float2(s1);
                acc.x += f0.x; acc.y += f0.y; acc.z += f1.x; acc.w += f1.y;
            }
        }
        if (base < end) {
            int k = base + lane;
            int2 c = (k < end) ? __ldg(&g_csr[k]) : make_int2(0, 0);
            int cnt = end - base;
            for (int j = 0; j < cnt; j++) {
                __half2 p0, p1;
                EDGE_PROD(j, p0, p1);
                float2 f0 = __half22float2(p0);
                float2 f1 = __half22float2(p1);
                acc.x += f0.x; acc.y += f0.y; acc.z += f1.x; acc.w += f1.y;
            }
        }
        __half2 o0 = __floats2half2_rn(acc.x, acc.y);
        __half2 o1 = __floats2half2_rn(acc.z, acc.w);
        __half2 op[2] = {o0, o1};
        *(uint2*)(g_aggh + (size_t)node * HH + lane * 4) = *(uint2*)op;
    }
}

// ---------------------------------------------------------------------------
// Pair epilogue
// ---------------------------------------------------------------------------
template <int NCOL, bool BIAS, bool ACT, bool RESID, bool POOL, bool OFP16, bool HHCOPY>
__device__ __forceinline__ void epi2(int row, int col, float v0, float v1,
                                     const float* __restrict__ bias, void* outv,
                                     const int* __restrict__ batch) {
    if (row >= NN) return;
    if (BIAS) { v0 += bias[col]; v1 += bias[col + 1]; }
    if (ACT)  { v0 = sspf(v0); v1 = sspf(v1); }
    if (POOL) {
        int b = batch[row];
        float* p = g_pooled + (size_t)b * NCOL + col;
        asm volatile("red.global.add.v2.f32 [%0], {%1,%2};" :: "l"(p), "f"(v0), "f"(v1) : "memory");
    } else if (OFP16) {
        __half2 pk = __floats2half2_rn(v0, v1);
        *(unsigned*)((__half*)outv + (size_t)row * NCOL + col) = *(unsigned*)&pk;
    } else {
        float* o = (float*)outv + (size_t)row * NCOL + col;
        if (RESID) {
            float2 h = *(float2*)o;
            v0 += h.x; v1 += h.y;
        }
        *(float2*)o = make_float2(v0, v1);
        if (HHCOPY) {
            __half2 pk = __floats2half2_rn(v0, v1);
            *(unsigned*)(g_hh + (size_t)row * NCOL + col) = *(unsigned*)&pk;
        }
    }
}

// ---------------------------------------------------------------------------
// fp16 tensor-core GEMM, single-stage K=128 (A already fp16): out = A @ Wt^T
// ---------------------------------------------------------------------------
template <int NCOL, bool OFP16>
__global__ void __launch_bounds__(256, 2)
mma_gemm16_kernel(const __half* __restrict__ A,
                  const __half* __restrict__ Wt,
                  void* outv) {
    constexpr int KDIM = 128;
    constexpr int WN = NCOL / 2;
    constexpr int NT = WN / 8;
    constexpr int PANEL = 16384;

    extern __shared__ char dynsm[];
    char* As = dynsm;
    char* Bs = dynsm + 2 * PANEL;

    int tid = threadIdx.x;
    int warp = tid >> 5, lane = tid & 31;
    int wm = warp & 3, wn = warp >> 2;
    int row0 = blockIdx.x * 128;

    float acc[2][NT][4];
    #pragma unroll
    for (int mt = 0; mt < 2; mt++)
        #pragma unroll
        for (int nt = 0; nt < NT; nt++)
            #pragma unroll
            for (int q = 0; q < 4; q++) acc[mt][nt][q] = 0.f;

    unsigned as_base = smem_u32(As);
    unsigned bs_base = smem_u32(Bs);

    #pragma unroll
    for (int i = tid; i < 128 * 16; i += 256) {
        int r = i >> 4, ch = i & 15;
        int grow = row0 + r;
        uint4 v = make_uint4(0, 0, 0, 0);
        if (grow < NN)
            v = *(const uint4*)(A + (size_t)grow * KDIM + ch * 8);
        *(uint4*)(As + (ch >> 3) * PANEL + SWZ(r * 128 + (ch & 7) * 16)) = v;
    }
    #pragma unroll
    for (int i = tid; i < NCOL * 16; i += 256) {
        int r = i >> 4, ch = i & 15;
        uint4 v = *(const uint4*)(Wt + (size_t)r * KDIM + ch * 8);
        *(uint4*)(Bs + (ch >> 3) * PANEL + SWZ(r * 128 + (ch & 7) * 16)) = v;
    }
    __syncthreads();

    #pragma unroll
    for (int ks = 0; ks < 8; ks++) {
        int poff = (ks >> 2) * PANEL;
        int koff = (ks & 3) * 32;
        unsigned a[2][4];
        #pragma unroll
        for (int mt = 0; mt < 2; mt++) {
            int r = wm * 32 + mt * 16 + (lane & 15);
            ldsm_x4(a[mt], as_base + poff + SWZ(r * 128 + koff + (lane >> 4) * 16));
        }
        #pragma unroll
        for (int nt = 0; nt < NT; nt++) {
            unsigned b[2];
            int l = lane & 15;
            int r = wn * WN + nt * 8 + (l & 7);
            ldsm_x2(b, bs_base + poff + SWZ(r * 128 + koff + ((l >> 3) & 1) * 16));
            mma_fp16(acc[0][nt], a[0], b);
            mma_fp16(acc[1][nt], a[1], b);
        }
    }

    #pragma unroll
    for (int mt = 0; mt < 2; mt++) {
        #pragma unroll
        for (int nt = 0; nt < NT; nt++) {
            int r = row0 + wm * 32 + mt * 16 + (lane >> 2);
            int c = wn * WN + nt * 8 + (lane & 3) * 2;
            epi2<NCOL, false, false, false, false, OFP16, false>(r, c, acc[mt][nt][0], acc[mt][nt][1], nullptr, outv, nullptr);
            epi2<NCOL, false, false, false, false, OFP16, false>(r + 8, c, acc[mt][nt][2], acc[mt][nt][3], nullptr, outv, nullptr);
        }
    }
}

// ---------------------------------------------------------------------------
// Fused two-GEMM chain: T = ssp(A@W1 + b1); out2 = T@W2 + b2
// ---------------------------------------------------------------------------
template <int K1, int N1, int N2, bool POOL2, bool AFP16>
__global__ void __launch_bounds__(256, 2)
fused2_kernel(const void* __restrict__ Av,
              const __half* __restrict__ W1, const float* __restrict__ b1,
              const __half* __restrict__ W2, const float* __restrict__ b2,
              float* __restrict__ outh, const int* __restrict__ batch) {
    constexpr int WN1 = N1 / 2, NT1 = WN1 / 8;
    constexpr int WN2 = N2 / 2, NT2 = WN2 / 8;
    constexpr int A_B = 128 * 64 * 2;
    constexpr int B_B = 16384;
    constexpr int PANEL = 128 * 64 * 2;

    extern __shared__ char dynsm[];
    char* As = dynsm;
    char* Bs = dynsm + A_B;
    char* Ts = dynsm + A_B + B_B;

    int tid = threadIdx.x;
    int warp = tid >> 5, lane = tid & 31;
    int wm = warp & 3, wn = warp >> 2;
    int row0 = blockIdx.x * 128;

    unsigned as_base = smem_u32(As);
    unsigned bs_base = smem_u32(Bs);
    unsigned ts_base = smem_u32(Ts);

    float acc1[2][NT1][4];
    #pragma unroll
    for (int mt = 0; mt < 2; mt++)
        #pragma unroll
        for (int nt = 0; nt < NT1; nt++)
            #pragma unroll
            for (int q = 0; q < 4; q++) acc1[mt][nt][q] = 0.f;

    for (int k0 = 0; k0 < K1; k0 += 64) {
        #pragma unroll
        for (int i = tid; i < 128 * 8; i += 256) {
            int r = i >> 3, ch = i & 7;
            int grow = row0 + r;
            if (AFP16) {
                uint4 v = make_uint4(0, 0, 0, 0);
                if (grow < NN)
                    v = *(const uint4*)((const __half*)Av + (size_t)grow * K1 + k0 + ch * 8);
                *(uint4*)(As + SWZ(r * 128 + ch * 16)) = v;
            } else {
                float v[8] = {0.f, 0.f, 0.f, 0.f, 0.f, 0.f, 0.f, 0.f};
                if (grow < NN) {
                    const float* gp = (const float*)Av + (size_t)grow * K1 + k0 + ch * 8;
                    float4 f0 = *(const float4*)gp;
                    float4 f1 = *(const float4*)(gp + 4);
                    v[0] = f0.x; v[1] = f0.y; v[2] = f0.z; v[3] = f0.w;
                    v[4] = f1.x; v[5] = f1.y; v[6] = f1.z; v[7] = f1.w;
                }
                __half2 hh[4];
                #pragma unroll
                for (int q = 0; q < 4; q++) hh[q] = __floats2half2_rn(v[2 * q], v[2 * q + 1]);
                *(uint4*)(As + SWZ(r * 128 + ch * 16)) = *(uint4*)hh;
            }
        }
        #pragma unroll
        for (int i = tid; i < N1 * 8; i += 256) {
            int r = i >> 3, ch = i & 7;
            uint4 w = *(const uint4*)(W1 + (size_t)r * K1 + k0 + ch * 8);
            *(uint4*)(Bs + SWZ(r * 128 + ch * 16)) = w;
        }
        __syncthreads();

        #pragma unroll
        for (int ks = 0; ks < 4; ks++) {
            unsigned a[2][4];
            #pragma unroll
            for (int mt = 0; mt < 2; mt++) {
                int r = wm * 32 + mt * 16 + (lane & 15);
                ldsm_x4(a[mt], as_base + SWZ(r * 128 + ks * 32 + (lane >> 4) * 16));
            }
            #pragma unroll
            for (int nt = 0; nt < NT1; nt++) {
                unsigned b[2];
                int l = lane & 15;
                int r = wn * WN1 + nt * 8 + (l & 7);
                ldsm_x2(b, bs_base + SWZ(r * 128 + ks * 32 + ((l >> 3) & 1) * 16));
                mma_fp16(acc1[0][nt], a[0], b);
                mma_fp16(acc1[1][nt], a[1], b);
            }
        }
        __syncthreads();
    }

    #pragma unroll
    for (int mt = 0; mt < 2; mt++) {
        #pragma unroll
        for (int nt = 0; nt < NT1; nt++) {
            int c = wn * WN1 + nt * 8 + (lane & 3) * 2;
            int panel_off = (c >> 6) * PANEL;
            int kk2 = (c & 63) * 2;
            #pragma unroll
            for (int half = 0; half < 2; half++) {
                int rl = wm * 32 + mt * 16 + (lane >> 2) + half * 8;
                float v0 = sspf(acc1[mt][nt][half * 2 + 0] + b1[c]);
                float v1 = sspf(acc1[mt][nt][half * 2 + 1] + b1[c + 1]);
                __half2 pk = __floats2half2_rn(v0, v1);
                *(unsigned*)(Ts + panel_off + SWZ(rl * 128 + kk2)) = *(unsigned*)&pk;
            }
        }
    }
    __syncthreads();

    float acc2[2][NT2][4];
    #pragma unroll
    for (int mt = 0; mt < 2; mt++)
        #pragma unroll
        for (int nt = 0; nt < NT2; nt++)
            #pragma unroll
            for (int q = 0; q < 4; q++) acc2[mt][nt][q] = 0.f;

    for (int k0 = 0; k0 < N1; k0 += 64) {
        #pragma unroll
        for (int i = tid; i < N2 * 8; i += 256) {
            int r = i >> 3, ch = i & 7;
            uint4 w = *(const uint4*)(W2 + (size_t)r * N1 + k0 + ch * 8);
            *(uint4*)(Bs + SWZ(r * 128 + ch * 16)) = w;
        }
        __syncthreads();

        int panel_off = (k0 >> 6) * PANEL;
        #pragma unroll
        for (int ks = 0; ks < 4; ks++) {
            unsigned a[2][4];
            #pragma unroll
            for (int mt = 0; mt < 2; mt++) {
                int r = wm * 32 + mt * 16 + (lane & 15);
                ldsm_x4(a[mt], ts_base + panel_off + SWZ(r * 128 + ks * 32 + (lane >> 4) * 16));
            }
            #pragma unroll
            for (int nt = 0; nt < NT2; nt++) {
                unsigned b[2];
                int l = lane & 15;
                int r = wn * WN2 + nt * 8 + (l & 7);
                ldsm_x2(b, bs_base + SWZ(r * 128 + ks * 32 + ((l >> 3) & 1) * 16));
                mma_fp16(acc2[0][nt], a[0], b);
                mma_fp16(acc2[1][nt], a[1], b);
            }
        }
        __syncthreads();
    }

    #pragma unroll
    for (int mt = 0; mt < 2; mt++) {
        #pragma unroll
        for (int nt = 0; nt < NT2; nt++) {
            int r = row0 + wm * 32 + mt * 16 + (lane >> 2);
            int c = wn * WN2 + nt * 8 + (lane & 3) * 2;
            epi2<N2, true, false, !POOL2, POOL2, false, !POOL2>(r, c, acc2[mt][nt][0], acc2[mt][nt][1], b2, outh, batch);
            epi2<N2, true, false, !POOL2, POOL2, false, !POOL2>(r + 8, c, acc2[mt][nt][2], acc2[mt][nt][3], b2, outh, batch);
        }
    }
}

// ---------------------------------------------------------------------------
// Fused THREE-GEMM chain (interaction i=0 path):
//   T  = ssp(aggh @ W1 + b1)        (lin2)
//   hn = h + (T @ W2 + b2)          (lin; write h fp32, stash hn fp16 in Ts)
//   xjh = hn @ W3                   (lin1 of NEXT interaction)
// ---------------------------------------------------------------------------
__global__ void __launch_bounds__(256, 2)
fused3_kernel(const __half* __restrict__ Av,
              const __half* __restrict__ W1, const float* __restrict__ b1,
              const __half* __restrict__ W2, const float* __restrict__ b2,
              const __half* __restrict__ W3,
              float* __restrict__ outh, __half* __restrict__ xjo) {
    constexpr int NT1 = 8, NT2 = 8, NT3 = 8;   // N=128 everywhere, 2 N-warps
    constexpr int A_B = 16384, B_B = 16384, PANEL = 16384;

    extern __shared__ char dynsm[];
    char* As = dynsm;
    char* Bs = dynsm + A_B;
    char* Ts = dynsm + A_B + B_B;

    int tid = threadIdx.x;
    int warp = tid >> 5, lane = tid & 31;
    int wm = warp & 3, wn = warp >> 2;
    int row0 = blockIdx.x * 128;

    unsigned as_base = smem_u32(As);
    unsigned bs_base = smem_u32(Bs);
    unsigned ts_base = smem_u32(Ts);

    // ---- stage 1: acc1 = aggh @ W1
    float acc1[2][NT1][4];
    #pragma unroll
    for (int mt = 0; mt < 2; mt++)
        #pragma unroll
        for (int nt = 0; nt < NT1; nt++)
            #pragma unroll
            for (int q = 0; q < 4; q++) acc1[mt][nt][q] = 0.f;

    for (int k0 = 0; k0 < 128; k0 += 64) {
        #pragma unroll
        for (int i = tid; i < 128 * 8; i += 256) {
            int r = i >> 3, ch = i & 7;
            int grow = row0 + r;
            uint4 v = make_uint4(0, 0, 0, 0);
            if (grow < NN)
                v = *(const uint4*)(Av + (size_t)grow * 128 + k0 + ch * 8);
            *(uint4*)(As + SWZ(r * 128 + ch * 16)) = v;
        }
        #pragma unroll
        for (int i = tid; i < 128 * 8; i += 256) {
            int r = i >> 3, ch = i & 7;
            uint4 w = *(const uint4*)(W1 + (size_t)r * 128 + k0 + ch * 8);
            *(uint4*)(Bs + SWZ(r * 128 + ch * 16)) = w;
        }
        __syncthreads();
        #pragma unroll
        for (int ks = 0; ks < 4; ks++) {
            unsigned a[2][4];
            #pragma unroll
            for (int mt = 0; mt < 2; mt++) {
                int r = wm * 32 + mt * 16 + (lane & 15);
                ldsm_x4(a[mt], as_base + SWZ(r * 128 + ks * 32 + (lane >> 4) * 16));
            }
            #pragma unroll
            for (int nt = 0; nt < NT1; nt++) {
                unsigned b[2];
                int l = lane & 15;
                int r = wn * 64 + nt * 8 + (l & 7);
                ldsm_x2(b, bs_base + SWZ(r * 128 + ks * 32 + ((l >> 3) & 1) * 16));
                mma_fp16(acc1[0][nt], a[0], b);
                mma_fp16(acc1[1][nt], a[1], b);
            }
        }
        __syncthreads();
    }

    // epi 1: T = ssp(acc1 + b1) -> Ts
    #pragma unroll
    for (int mt = 0; mt < 2; mt++) {
        #pragma unroll
        for (int nt = 0; nt < NT1; nt++) {
            int c = wn * 64 + nt * 8 + (lane & 3) * 2;
            int panel_off = (c >> 6) * PANEL;
            int kk2 = (c & 63) * 2;
            #pragma unroll
            for (int half = 0; half < 2; half++) {
                int rl = wm * 32 + mt * 16 + (lane >> 2) + half * 8;
                float v0 = sspf(acc1[mt][nt][half * 2 + 0] + b1[c]);
                float v1 = sspf(acc1[mt][nt][half * 2 + 1] + b1[c + 1]);
                __half2 pk = __floats2half2_rn(v0, v1);
                *(unsigned*)(Ts + panel_off + SWZ(rl * 128 + kk2)) = *(unsigned*)&pk;
            }
        }
    }
    __syncthreads();

    // ---- stage 2: acc2 = T @ W2
    float acc2[2][NT2][4];
    #pragma unroll
    for (int mt = 0; mt < 2; mt++)
        #pragma unroll
        for (int nt = 0; nt < NT2; nt++)
            #pragma unroll
            for (int q = 0; q < 4; q++) acc2[mt][nt][q] = 0.f;

    for (int k0 = 0; k0 < 128; k0 += 64) {
        #pragma unroll
        for (int i = tid; i < 128 * 8; i += 256) {
            int r = i >> 3, ch = i & 7;
            uint4 w = *(const uint4*)(W2 + (size_t)r * 128 + k0 + ch * 8);
            *(uint4*)(Bs + SWZ(r * 128 + ch * 16)) = w;
        }
        __syncthreads();
        int panel_off = (k0 >> 6) * PANEL;
        #pragma unroll
        for (int ks = 0; ks < 4; ks++) {
            unsigned a[2][4];
            #pragma unroll
            for (int mt = 0; mt < 2; mt++) {
                int r = wm * 32 + mt * 16 + (lane & 15);
                ldsm_x4(a[mt], ts_base + panel_off + SWZ(r * 128 + ks * 32 + (lane >> 4) * 16));
            }
            #pragma unroll
            for (int nt = 0; nt < NT2; nt++) {
                unsigned b[2];
                int l = lane & 15;
                int r = wn * 64 + nt * 8 + (l & 7);
                ldsm_x2(b, bs_base + SWZ(r * 128 + ks * 32 + ((l >> 3) & 1) * 16));
                mma_fp16(acc2[0][nt], a[0], b);
                mma_fp16(acc2[1][nt], a[1], b);
            }
        }
        __syncthreads();
    }

    // epi 2: hn = h + acc2 + b2  -> write h fp32, stash hn fp16 in Ts
    #pragma unroll
    for (int mt = 0; mt < 2; mt++) {
        #pragma unroll
        for (int nt = 0; nt < NT2; nt++) {
            int c = wn * 64 + nt * 8 + (lane & 3) * 2;
            int panel_off = (c >> 6) * PANEL;
            int kk2 = (c & 63) * 2;
            #pragma unroll
            for (int half = 0; half < 2; half++) {
                int rl = wm * 32 + mt * 16 + (lane >> 2) + half * 8;
                int row = row0 + rl;
                float v0 = acc2[mt][nt][half * 2 + 0] + b2[c];
                float v1 = acc2[mt][nt][half * 2 + 1] + b2[c + 1];
                if (row < NN) {
                    float* o = outh + (size_t)row * 128 + c;
                    float2 hprev = *(float2*)o;
                    v0 += hprev.x; v1 += hprev.y;
                    *(float2*)o = make_float2(v0, v1);
                }
                __half2 pk = __floats2half2_rn(v0, v1);
                *(unsigned*)(Ts + panel_off + SWZ(rl * 128 + kk2)) = *(unsigned*)&pk;
            }
        }
    }
    __syncthreads();

    // ---- stage 3: xjh = hn @ W3
    float acc3[2][NT3][4];
    #pragma unroll
    for (int mt = 0; mt < 2; mt++)
        #pragma unroll
        for (int nt = 0; nt < NT3; nt++)
            #pragma unroll
            for (int q = 0; q < 4; q++) acc3[mt][nt][q] = 0.f;

    for (int k0 = 0; k0 < 128; k0 += 64) {
        #pragma unroll
        for (int i = tid; i < 128 * 8; i += 256) {
            int r = i >> 3, ch = i & 7;
            uint4 w = *(const uint4*)(W3 + (size_t)r * 128 + k0 + ch * 8);
            *(uint4*)(Bs + SWZ(r * 128 + ch * 16)) = w;
        }
        __syncthreads();
        int panel_off = (k0 >> 6) * PANEL;
        #pragma unroll
        for (int ks = 0; ks < 4; ks++) {
            unsigned a[2][4];
            #pragma unroll
            for (int mt = 0; mt < 2; mt++) {
                int r = wm * 32 + mt * 16 + (lane & 15);
                ldsm_x4(a[mt], ts_base + panel_off + SWZ(r * 128 + ks * 32 + (lane >> 4) * 16));
            }
            #pragma unroll
            for (int nt = 0; nt < NT3; nt++) {
                unsigned b[2];
                int l = lane & 15;
                int r = wn * 64 + nt * 8 + (l & 7);
                ldsm_x2(b, bs_base + SWZ(r * 128 + ks * 32 + ((l >> 3) & 1) * 16));
                mma_fp16(acc3[0][nt], a[0], b);
                mma_fp16(acc3[1][nt], a[1], b);
            }
        }
        __syncthreads();
    }

    #pragma unroll
    for (int mt = 0; mt < 2; mt++) {
        #pragma unroll
        for (int nt = 0; nt < NT3; nt++) {
            int r = row0 + wm * 32 + mt * 16 + (lane >> 2);
            int c = wn * 64 + nt * 8 + (lane & 3) * 2;
            #pragma unroll
            for (int half = 0; half < 2; half++) {
                int row = r + half * 8;
                if (row < NN) {
                    __half2 pk = __floats2half2_rn(acc3[mt][nt][half * 2], acc3[mt][nt][half * 2 + 1]);
                    *(unsigned*)(xjo + (size_t)row * 128 + c) = *(unsigned*)&pk;
                }
            }
        }
    }
}

// ---------------------------------------------------------------------------
// Final tiny GEMM
// ---------------------------------------------------------------------------
__global__ void final_kernel(const float* __restrict__ pw, const float* __restrict__ pb,
                             float* __restrict__ out) {
    int tid = threadIdx.x;
    int b = tid >> 2;
    int t = tid & 3;
    float acc = pb[t];
    for (int k = 0; k < HH; k++)
        acc = fmaf(g_pooled[b * HH + k], pw[k * TT + t], acc);
    out[b * TT + t] = acc;
}

// ---------------------------------------------------------------------------
extern "C" void kernel_launch(void* const* d_in, const int* in_sizes, int n_in,
                              void* d_out, int out_size) {
    const int*   z       = (const int*)d_in[0];
    const float* pos     = (const float*)d_in[1];
    const int*   batch   = (const int*)d_in[2];
    const int*   ei      = (const int*)d_in[3];
    const float* emb     = (const float*)d_in[4];
    const float* mlp_w1  = (const float*)d_in[5];
    const float* mlp_b1  = (const float*)d_in[6];
    const float* mlp_w2  = (const float*)d_in[7];
    const float* mlp_b2  = (const float*)d_in[8];
    const float* lin1_w  = (const float*)d_in[9];
    const float* lin2_w  = (const float*)d_in[10];
    const float* lin2_b  = (const float*)d_in[11];
    const float* lin_w   = (const float*)d_in[12];
    const float* lin_b   = (const float*)d_in[13];
    const float* out1_w  = (const float*)d_in[14];
    const float* out1_b  = (const float*)d_in[15];
    const float* out2_w  = (const float*)d_in[16];
    const float* out2_b  = (const float*)d_in[17];
    const float* pred_w  = (const float*)d_in[18];
    const float* pred_b  = (const float*)d_in[19];
    float* out = (float*)d_out;

    float* p_h;
    void *p_xjh, *p_hh, *p_aggh;
    __half* p_wt;
    cudaGetSymbolAddress((void**)&p_h, g_h);
    cudaGetSymbolAddress(&p_hh, g_hh);
    cudaGetSymbolAddress(&p_xjh, g_xjh);
    cudaGetSymbolAddress(&p_aggh, g_aggh);
    cudaGetSymbolAddress((void**)&p_wt, g_wt);

    int dev = 0, smCount = 148;
    cudaGetDevice(&dev);
    cudaDeviceGetAttribute(&smCount, cudaDevAttrMultiProcessorCount, dev);

    static cudaStream_t s_aux = nullptr;
    static cudaEvent_t ev_fork = nullptr, ev_join = nullptr;
    if (!s_aux) {
        cudaStreamCreateWithFlags(&s_aux, cudaStreamNonBlocking);
        cudaEventCreateWithFlags(&ev_fork, cudaEventDisableTiming);
        cudaEventCreateWithFlags(&ev_join, cudaEventDisableTiming);
    }

    const int TAB_SMEM = TAB * 512;                 // 49152
    cudaFuncSetAttribute(edge_conv_csr_kernel, cudaFuncAttributeMaxDynamicSharedMemorySize, TAB_SMEM);

    const int SM_G16 = 65536;
    const int SM_FA  = 16384 + 16384 + 32768;       // 65536
    const int SM_FB  = 16384 + 16384 + 16384;       // 49152
    cudaFuncSetAttribute(mma_gemm16_kernel<128, true>,
                         cudaFuncAttributeMaxDynamicSharedMemorySize, SM_G16);
    cudaFuncSetAttribute(fused3_kernel,
                         cudaFuncAttributeMaxDynamicSharedMemorySize, SM_FA);
    cudaFuncSetAttribute(fused2_kernel<128, 128, 128, false, true>,
                         cudaFuncAttributeMaxDynamicSharedMemorySize, SM_FA);
    cudaFuncSetAttribute(fused2_kernel<128, 64, 128, true, true>,
                         cudaFuncAttributeMaxDynamicSharedMemorySize, SM_FB);

    int gblocks = (NN + 127) / 128;

    // ---- fork: CSR build on aux stream
    cudaEventRecord(ev_fork, 0);
    cudaStreamWaitEvent(s_aux, ev_fork, 0);
    zero_deg_kernel<<<(NN + 255) / 256, 256, 0, s_aux>>>();
    hist_kernel<<<(EE / 4 + 255) / 256, 256, 0, s_aux>>>(ei);
    scan1_kernel<<<NBLK, SCAN_B, 0, s_aux>>>();
    scan3_kernel<<<NBLK, SCAN_B, 0, s_aux>>>();
    fill_kernel<<<(EE / 4 + 255) / 256, 256, 0, s_aux>>>(ei, pos);
    cudaEventRecord(ev_join, s_aux);

    // ---- main stream: prep chain
    dim3 tg(64, 8);
    transpose_all_kernel<<<tg, 256>>>(lin1_w, lin2_w, lin_w, out1_w, out2_w, p_wt);
    prep_kernel<<<(NN * 32 + 255) / 256, 256>>>(z, emb);
    dim3 tb(TAB, 2);
    build_table_kernel<<<tb, HH>>>(mlp_w1, mlp_b1, mlp_w2, mlp_b2);
    mma_gemm16_kernel<128, true><<<gblocks, 256, SM_G16>>>(
        (const __half*)p_hh, p_wt + WT_LIN1(0), p_xjh);

    // ---- join
    cudaStreamWaitEvent(0, ev_join, 0);

    // interaction 0: edge conv + 3-GEMM chain (includes lin1 for interaction 1)
    edge_conv_csr_kernel<<<2 * smCount, 1024, TAB_SMEM>>>(0);
    fused3_kernel<<<gblocks, 256, SM_FA>>>(
        (const __half*)p_aggh,
        p_wt + WT_LIN2(0), lin2_b,
        p_wt + WT_LIN(0),  lin_b,
        p_wt + WT_LIN1(1),
        p_h, (__half*)p_xjh);

    // interaction 1: edge conv + 2-GEMM chain (h update + hh mirror)
    edge_conv_csr_kernel<<<2 * smCount, 1024, TAB_SMEM>>>(1);
    fused2_kernel<128, 128, 128, false, true><<<gblocks, 256, SM_FA>>>(
        p_aggh,
        p_wt + WT_LIN2(1), lin2_b + HH,
        p_wt + WT_LIN(1),  lin_b + HH,
        p_h, nullptr);

    // readout
    fused2_kernel<128, 64, 128, true, true><<<gblocks, 256, SM_FB>>>(
        p_hh,
        p_wt + WT_OUT1, out1_b,
        p_wt + WT_OUT2, out2_b,
        nullptr, batch);
    final_kernel<<<1, 256>>>(pred_w, pred_b, out);
}

// round 16
// speedup vs baseline: 1.1999x; 1.0056x over previous
#include <cuda_runtime.h>
#include <cuda_bf16.h>
#include <cuda_fp16.h>
#include <stdint.h>
#include <math.h>

#define NN 50000
#define EE 1600000
#define HH 128
#define BB 64
#define TT 4
#define GG 10
#define TAB 96
#define D_MAX 8.6603f
#define SCAN_B 1024
#define NBLK ((NN + SCAN_B - 1) / SCAN_B)

// scratch (static device globals — no runtime allocation)
static __device__ __half g_tabh[2 * TAB * 256];  // pair-interleaved fp16 filter table
static __device__ float g_h[NN * HH];
static __device__ __half g_hh[NN * HH];
static __device__ __half g_xjh[NN * HH];
static __device__ __half g_aggh[NN * HH];
static __device__ float g_pooled[BB * HH];
static __device__ __half g_wt[7 * 16384];
// CSR (dst-major)
static __device__ int  g_deg[NN];
static __device__ int  g_ptr[NN + 1];
static __device__ int  g_work[NN];
static __device__ int  g_bsum[NBLK];
static __device__ int2 g_csr[EE];

#define WT_LIN1(i)  ((size_t)(i) * 16384)
#define WT_LIN2(i)  ((size_t)(32768) + (size_t)(i) * 16384)
#define WT_LIN(i)   ((size_t)(65536) + (size_t)(i) * 16384)
#define WT_OUT1     ((size_t)98304)
#define WT_OUT2     ((size_t)106496)

__device__ __forceinline__ float sspf(float x) {
    float ax = fabsf(x);
    return fmaxf(x, 0.0f) + log1pf(__expf(-ax)) - 0.6931471805599453f;
}

#define SWZ(off) ((off) ^ (((off) >> 3) & 0x70))

__device__ __forceinline__ unsigned smem_u32(const void* p) {
    return (unsigned)__cvta_generic_to_shared(p);
}
__device__ __forceinline__ void ldsm_x4(unsigned* r, unsigned addr) {
    asm volatile("ldmatrix.sync.aligned.m8n8.x4.shared.b16 {%0,%1,%2,%3}, [%4];"
                 : "=r"(r[0]), "=r"(r[1]), "=r"(r[2]), "=r"(r[3]) : "r"(addr));
}
__device__ __forceinline__ void ldsm_x2(unsigned* r, unsigned addr) {
    asm volatile("ldmatrix.sync.aligned.m8n8.x2.shared.b16 {%0,%1}, [%2];"
                 : "=r"(r[0]), "=r"(r[1]) : "r"(addr));
}
__device__ __forceinline__ void mma_fp16(float* d, const unsigned* a, const unsigned* b) {
    asm volatile("mma.sync.aligned.m16n8k16.row.col.f32.f16.f16.f32 "
                 "{%0,%1,%2,%3}, {%4,%5,%6,%7}, {%8,%9}, {%0,%1,%2,%3};"
                 : "+f"(d[0]), "+f"(d[1]), "+f"(d[2]), "+f"(d[3])
                 : "r"(a[0]), "r"(a[1]), "r"(a[2]), "r"(a[3]), "r"(b[0]), "r"(b[1]));
}

// ---------------------------------------------------------------------------
// Build filter table directly in pair-interleaved fp16 layout:
//   entry i, chunk g (16B): {row_i cols 4g..4g+3 , row_{i+1} cols 4g..4g+3}
// Row r writes first half of entry r and second half of entry r-1
// (row TAB-1 also writes second half of entry TAB-1 = clamp).
// ---------------------------------------------------------------------------
__global__ void build_table_kernel(const float* __restrict__ w1, const float* __restrict__ b1,
                                   const float* __restrict__ w2, const float* __restrict__ b2) {
    int row = blockIdx.x;
    int inter = blockIdx.y;
    int tid = threadIdx.x;
    float d = row * (D_MAX / (float)(TAB - 1));

    __shared__ float hid[HH];
    const float* w1i = w1 + (size_t)inter * GG * HH;
    const float* b1i = b1 + (size_t)inter * HH;
    const float* w2i = w2 + (size_t)inter * HH * HH;
    const float* b2i = b2 + (size_t)inter * HH;

    const float step = 10.0f / 9.0f;
    const float coeff = -0.5f / (step * step);

    float acc = b1i[tid];
    #pragma unroll
    for (int g = 0; g < GG; g++) {
        float diff = d - (float)g * step;
        float r = expf(coeff * diff * diff);
        acc += r * w1i[g * HH + tid];
    }
    hid[tid] = sspf(acc);
    __syncthreads();

    float acc2 = b2i[tid];
    for (int k = 0; k < HH; k++)
        acc2 = fmaf(hid[k], w2i[k * HH + tid], acc2);

    float C = 0.5f * (cosf(d * 3.14159265358979f / 10.0f) + 1.0f);
    __half v = __float2half_rn(acc2 * C);

    // interleaved writes
    size_t ebase = (size_t)inter * TAB * 256;
    int g = tid >> 2, o = tid & 3;
    g_tabh[ebase + (size_t)row * 256 + g * 8 + o] = v;            // first half of entry row
    if (row > 0)
        g_tabh[ebase + (size_t)(row - 1) * 256 + g * 8 + 4 + o] = v;  // second half of entry row-1
    if (row == TAB - 1)
        g_tabh[ebase + (size_t)row * 256 + g * 8 + 4 + o] = v;        // clamp
}

// ---------------------------------------------------------------------------
// Merged weight transpose + fp16 convert
// ---------------------------------------------------------------------------
__global__ void transpose_all_kernel(const float* __restrict__ lin1_w,
                                     const float* __restrict__ lin2_w,
                                     const float* __restrict__ lin_w,
                                     const float* __restrict__ out1_w,
                                     const float* __restrict__ out2_w,
                                     __half* __restrict__ wt) {
    int m = blockIdx.y;
    const float* src;
    size_t off;
    int K, N;
    switch (m) {
        case 0: src = lin1_w;          off = WT_LIN1(0); K = 128; N = 128; break;
        case 1: src = lin1_w + 16384;  off = WT_LIN1(1); K = 128; N = 128; break;
        case 2: src = lin2_w;          off = WT_LIN2(0); K = 128; N = 128; break;
        case 3: src = lin2_w + 16384;  off = WT_LIN2(1); K = 128; N = 128; break;
        case 4: src = lin_w;           off = WT_LIN(0);  K = 128; N = 128; break;
        case 5: src = lin_w + 16384;   off = WT_LIN(1);  K = 128; N = 128; break;
        case 6: src = out1_w;          off = WT_OUT1;    K = 128; N = 64;  break;
        default: src = out2_w;         off = WT_OUT2;    K = 64;  N = 128; break;
    }
    int i = blockIdx.x * blockDim.x + threadIdx.x;
    if (i >= K * N) return;
    int k = i / N, n = i % N;
    wt[off + (size_t)n * K + k] = __float2half_rn(src[i]);
}

// ---------------------------------------------------------------------------
// Fused prep: embedding gather (fp32 + fp16 shadow) + zero pooled
// ---------------------------------------------------------------------------
__global__ void prep_kernel(const int* __restrict__ z, const float* __restrict__ emb) {
    int idx = blockIdx.x * blockDim.x + threadIdx.x;
    if (idx < NN * (HH / 4)) {
        int n = idx >> 5;
        int c = idx & 31;
        float4 v = ((const float4*)emb)[(size_t)z[n] * (HH / 4) + c];
        ((float4*)g_h)[idx] = v;
        __half2 pk[2] = {__floats2half2_rn(v.x, v.y), __floats2half2_rn(v.z, v.w)};
        ((uint2*)g_hh)[idx] = *(uint2*)pk;
    }
    if (idx < BB * HH) g_pooled[idx] = 0.f;
}

// ---------------------------------------------------------------------------
// CSR construction (aux stream)
// ---------------------------------------------------------------------------
__global__ void zero_deg_kernel() {
    int i = blockIdx.x * blockDim.x + threadIdx.x;
    if (i < NN) g_deg[i] = 0;
}

__global__ void hist_kernel(const int* __restrict__ ei) {
    int i = blockIdx.x * blockDim.x + threadIdx.x;
    if (i >= EE / 4) return;
    int4 d4 = ((const int4*)(ei + EE))[i];
    atomicAdd(&g_deg[d4.x], 1);
    atomicAdd(&g_deg[d4.y], 1);
    atomicAdd(&g_deg[d4.z], 1);
    atomicAdd(&g_deg[d4.w], 1);
}

__global__ void scan1_kernel() {
    __shared__ int sm[SCAN_B];
    int idx = blockIdx.x * SCAN_B + threadIdx.x;
    int v = (idx < NN) ? g_deg[idx] : 0;
    sm[threadIdx.x] = v;
    __syncthreads();
    for (int off = SCAN_B / 2; off > 0; off >>= 1) {
        if (threadIdx.x < off) sm[threadIdx.x] += sm[threadIdx.x + off];
        __syncthreads();
    }
    if (threadIdx.x == 0) g_bsum[blockIdx.x] = sm[0];
}

// 3-level warp scan (2 barriers) + parallel cross-block offset
__global__ void scan3_kernel() {
    __shared__ int wsum[32];
    __shared__ int soff[2];
    int idx = blockIdx.x * SCAN_B + threadIdx.x;
    int lane = threadIdx.x & 31, wid = threadIdx.x >> 5;
    int v = (idx < NN) ? g_deg[idx] : 0;

    // inclusive warp scan
    int x = v;
    #pragma unroll
    for (int o = 1; o < 32; o <<= 1) {
        int y = __shfl_up_sync(0xffffffffu, x, o);
        if (lane >= o) x += y;
    }
    if (lane == 31) wsum[wid] = x;

    // cross-block offset (64 lanes load g_bsum concurrently)
    if (threadIdx.x < 64) {
        int t = threadIdx.x;
        int b = (t < NBLK && t < blockIdx.x) ? g_bsum[t] : 0;
        #pragma unroll
        for (int o = 16; o; o >>= 1) b += __shfl_down_sync(0xffffffffu, b, o);
        if ((t & 31) == 0) soff[t >> 5] = b;
    }
    __syncthreads();

    if (wid == 0) {
        int w = wsum[lane];
        #pragma unroll
        for (int o = 1; o < 32; o <<= 1) {
            int y = __shfl_up_sync(0xffffffffu, w, o);
            if (lane >= o) w += y;
        }
        wsum[lane] = w;
    }
    __syncthreads();

    int blockoff = soff[0] + soff[1];
    int warpoff = wid ? wsum[wid - 1] : 0;
    int incl = blockoff + warpoff + x;
    if (idx < NN) {
        g_ptr[idx] = incl - v;
        g_work[idx] = incl - v;
        if (idx == NN - 1) g_ptr[NN] = incl;
    }
}

// 8 edges/thread fill
__global__ void fill_kernel(const int* __restrict__ ei, const float* __restrict__ pos) {
    int i = blockIdx.x * blockDim.x + threadIdx.x;
    if (i >= EE / 8) return;
    int4 s4a = ((const int4*)ei)[2 * i];
    int4 s4b = ((const int4*)ei)[2 * i + 1];
    int4 d4a = ((const int4*)(ei + EE))[2 * i];
    int4 d4b = ((const int4*)(ei + EE))[2 * i + 1];
    int ss[8] = {s4a.x, s4a.y, s4a.z, s4a.w, s4b.x, s4b.y, s4b.z, s4b.w};
    int dd[8] = {d4a.x, d4a.y, d4a.z, d4a.w, d4b.x, d4b.y, d4b.z, d4b.w};
    const float INV_STEP = (float)(TAB - 1) / D_MAX;
    #pragma unroll
    for (int q = 0; q < 8; q++) {
        int s = ss[q], d = dd[q];
        float dx = pos[s * 3 + 0] - pos[d * 3 + 0];
        float dy = pos[s * 3 + 1] - pos[d * 3 + 1];
        float dz = pos[s * 3 + 2] - pos[d * 3 + 2];
        float dist = sqrtf(dx * dx + dy * dy + dz * dz);
        float t = dist * INV_STEP;
        int i0 = min((int)t, TAB - 2);
        float f = t - (float)i0;
        __half2 f2 = __float2half2_rn(f);
        int slot = atomicAdd(&g_work[d], 1);
        g_csr[slot] = make_int2(s | (i0 << 16), *(int*)&f2);
    }
}

// ---------------------------------------------------------------------------
// CSR edge aggregation: pair-interleaved fp16 table, half2 math, fp32 accum
// ---------------------------------------------------------------------------
#define EDGE_PROD(J, P0, P1) {                                                      \
    int cx  = __shfl_sync(0xffffffffu, c.x, (J));                                   \
    int cyi = __shfl_sync(0xffffffffu, c.y, (J));                                   \
    int s  = cx & 0xffff;                                                           \
    int i0 = cx >> 16;                                                              \
    __half2 f2 = *reinterpret_cast<__half2*>(&cyi);                                 \
    uint2 xw = *(const uint2*)(g_xjh + (size_t)s * HH + lane * 4);                  \
    __half2 x0 = *reinterpret_cast<__half2*>(&xw.x);                                \
    __half2 x1 = *reinterpret_cast<__half2*>(&xw.y);                                \
    uint4 wv = *(const uint4*)(tab + i0 * 256 + lane * 8);                          \
    __half2 w0a = *reinterpret_cast<__half2*>(&wv.x);                               \
    __half2 w0b = *reinterpret_cast<__half2*>(&wv.y);                               \
    __half2 w1a = *reinterpret_cast<__half2*>(&wv.z);                               \
    __half2 w1b = *reinterpret_cast<__half2*>(&wv.w);                               \
    P0 = __hmul2(__hfma2(__hsub2(w1a, w0a), f2, w0a), x0);                          \
    P1 = __hmul2(__hfma2(__hsub2(w1b, w0b), f2, w0b), x1);                          \
}

__global__ void __launch_bounds__(1024, 2) edge_conv_csr_kernel(int inter) {
    extern __shared__ __half tab[];
    // plain 48KB copy of pre-interleaved table
    const uint4* tsrc = (const uint4*)(g_tabh + (size_t)inter * TAB * 256);
    #pragma unroll
    for (int i = threadIdx.x; i < TAB * 32; i += 1024)
        ((uint4*)tab)[i] = tsrc[i];
    __syncthreads();

    int lane = threadIdx.x & 31;
    int gwarp = blockIdx.x * 32 + (threadIdx.x >> 5);
    int nwarp = gridDim.x * 32;

    for (int node = gwarp; node < NN; node += nwarp) {
        int beg = __ldg(&g_ptr[node]);
        int end = __ldg(&g_ptr[node + 1]);

        float4 acc = make_float4(0.f, 0.f, 0.f, 0.f);
        int base = beg;
        for (; base + 32 <= end; base += 32) {
            int2 c = __ldg(&g_csr[base + lane]);
            #pragma unroll 8
            for (int j = 0; j < 32; j += 2) {
                __half2 a0, a1, b0, b1;
                EDGE_PROD(j, a0, a1);
                EDGE_PROD(j + 1, b0, b1);
                __half2 s0 = __hadd2(a0, b0);
                __half2 s1 = __hadd2(a1, b1);
                float2 f0 = __half22float2(s0);
                float2 f1 = __half22float2(s1);
                acc.x += f0.x; acc.y += f0.y; acc.z += f1.x; acc.w += f1.y;
            }
        }
        if (base < end) {
            int k = base + lane;
            int2 c = (k < end) ? __ldg(&g_csr[k]) : make_int2(0, 0);
            int cnt = end - base;
            for (int j = 0; j < cnt; j++) {
                __half2 p0, p1;
                EDGE_PROD(j, p0, p1);
                float2 f0 = __half22float2(p0);
                float2 f1 = __half22float2(p1);
                acc.x += f0.x; acc.y += f0.y; acc.z += f1.x; acc.w += f1.y;
            }
        }
        __half2 o0 = __floats2half2_rn(acc.x, acc.y);
        __half2 o1 = __floats2half2_rn(acc.z, acc.w);
        __half2 op[2] = {o0, o1};
        *(uint2*)(g_aggh + (size_t)node * HH + lane * 4) = *(uint2*)op;
    }
}

// ---------------------------------------------------------------------------
// Pair epilogue
// ---------------------------------------------------------------------------
template <int NCOL, bool BIAS, bool ACT, bool RESID, bool POOL, bool OFP16, bool HHCOPY>
__device__ __forceinline__ void epi2(int row, int col, float v0, float v1,
                                     const float* __restrict__ bias, void* outv,
                                     const int* __restrict__ batch) {
    if (row >= NN) return;
    if (BIAS) { v0 += bias[col]; v1 += bias[col + 1]; }
    if (ACT)  { v0 = sspf(v0); v1 = sspf(v1); }
    if (POOL) {
        int b = batch[row];
        float* p = g_pooled + (size_t)b * NCOL + col;
        asm volatile("red.global.add.v2.f32 [%0], {%1,%2};" :: "l"(p), "f"(v0), "f"(v1) : "memory");
    } else if (OFP16) {
        __half2 pk = __floats2half2_rn(v0, v1);
        *(unsigned*)((__half*)outv + (size_t)row * NCOL + col) = *(unsigned*)&pk;
    } else {
        float* o = (float*)outv + (size_t)row * NCOL + col;
        if (RESID) {
            float2 h = *(float2*)o;
            v0 += h.x; v1 += h.y;
        }
        *(float2*)o = make_float2(v0, v1);
        if (HHCOPY) {
            __half2 pk = __floats2half2_rn(v0, v1);
            *(unsigned*)(g_hh + (size_t)row * NCOL + col) = *(unsigned*)&pk;
        }
    }
}

// ---------------------------------------------------------------------------
// fp16 tensor-core GEMM, single-stage K=128 (A already fp16): out = A @ Wt^T
// ---------------------------------------------------------------------------
template <int NCOL, bool OFP16>
__global__ void __launch_bounds__(256, 2)
mma_gemm16_kernel(const __half* __restrict__ A,
                  const __half* __restrict__ Wt,
                  void* outv) {
    constexpr int KDIM = 128;
    constexpr int WN = NCOL / 2;
    constexpr int NT = WN / 8;
    constexpr int PANEL = 16384;

    extern __shared__ char dynsm[];
    char* As = dynsm;
    char* Bs = dynsm + 2 * PANEL;

    int tid = threadIdx.x;
    int warp = tid >> 5, lane = tid & 31;
    int wm = warp & 3, wn = warp >> 2;
    int row0 = blockIdx.x * 128;

    float acc[2][NT][4];
    #pragma unroll
    for (int mt = 0; mt < 2; mt++)
        #pragma unroll
        for (int nt = 0; nt < NT; nt++)
            #pragma unroll
            for (int q = 0; q < 4; q++) acc[mt][nt][q] = 0.f;

    unsigned as_base = smem_u32(As);
    unsigned bs_base = smem_u32(Bs);

    #pragma unroll
    for (int i = tid; i < 128 * 16; i += 256) {
        int r = i >> 4, ch = i & 15;
        int grow = row0 + r;
        uint4 v = make_uint4(0, 0, 0, 0);
        if (grow < NN)
            v = *(const uint4*)(A + (size_t)grow * KDIM + ch * 8);
        *(uint4*)(As + (ch >> 3) * PANEL + SWZ(r * 128 + (ch & 7) * 16)) = v;
    }
    #pragma unroll
    for (int i = tid; i < NCOL * 16; i += 256) {
        int r = i >> 4, ch = i & 15;
        uint4 v = *(const uint4*)(Wt + (size_t)r * KDIM + ch * 8);
        *(uint4*)(Bs + (ch >> 3) * PANEL + SWZ(r * 128 + (ch & 7) * 16)) = v;
    }
    __syncthreads();

    #pragma unroll
    for (int ks = 0; ks < 8; ks++) {
        int poff = (ks >> 2) * PANEL;
        int koff = (ks & 3) * 32;
        unsigned a[2][4];
        #pragma unroll
        for (int mt = 0; mt < 2; mt++) {
            int r = wm * 32 + mt * 16 + (lane & 15);
            ldsm_x4(a[mt], as_base + poff + SWZ(r * 128 + koff + (lane >> 4) * 16));
        }
        #pragma unroll
        for (int nt = 0; nt < NT; nt++) {
            unsigned b[2];
            int l = lane & 15;
            int r = wn * WN + nt * 8 + (l & 7);
            ldsm_x2(b, bs_base + poff + SWZ(r * 128 + koff + ((l >> 3) & 1) * 16));
            mma_fp16(acc[0][nt], a[0], b);
            mma_fp16(acc[1][nt], a[1], b);
        }
    }

    #pragma unroll
    for (int mt = 0; mt < 2; mt++) {
        #pragma unroll
        for (int nt = 0; nt < NT; nt++) {
            int r = row0 + wm * 32 + mt * 16 + (lane >> 2);
            int c = wn * WN + nt * 8 + (lane & 3) * 2;
            epi2<NCOL, false, false, false, false, OFP16, false>(r, c, acc[mt][nt][0], acc[mt][nt][1], nullptr, outv, nullptr);
            epi2<NCOL, false, false, false, false, OFP16, false>(r + 8, c, acc[mt][nt][2], acc[mt][nt][3], nullptr, outv, nullptr);
        }
    }
}

// ---------------------------------------------------------------------------
// Fused two-GEMM chain: T = ssp(A@W1 + b1); out2 = T@W2 + b2
// ---------------------------------------------------------------------------
template <int K1, int N1, int N2, bool POOL2, bool AFP16>
__global__ void __launch_bounds__(256, 2)
fused2_kernel(const void* __restrict__ Av,
              const __half* __restrict__ W1, const float* __restrict__ b1,
              const __half* __restrict__ W2, const float* __restrict__ b2,
              float* __restrict__ outh, const int* __restrict__ batch) {
    constexpr int WN1 = N1 / 2, NT1 = WN1 / 8;
    constexpr int WN2 = N2 / 2, NT2 = WN2 / 8;
    constexpr int A_B = 128 * 64 * 2;
    constexpr int B_B = 16384;
    constexpr int PANEL = 128 * 64 * 2;

    extern __shared__ char dynsm[];
    char* As = dynsm;
    char* Bs = dynsm + A_B;
    char* Ts = dynsm + A_B + B_B;

    int tid = threadIdx.x;
    int warp = tid >> 5, lane = tid & 31;
    int wm = warp & 3, wn = warp >> 2;
    int row0 = blockIdx.x * 128;

    unsigned as_base = smem_u32(As);
    unsigned bs_base = smem_u32(Bs);
    unsigned ts_base = smem_u32(Ts);

    float acc1[2][NT1][4];
    #pragma unroll
    for (int mt = 0; mt < 2; mt++)
        #pragma unroll
        for (int nt = 0; nt < NT1; nt++)
            #pragma unroll
            for (int q = 0; q < 4; q++) acc1[mt][nt][q] = 0.f;

    for (int k0 = 0; k0 < K1; k0 += 64) {
        #pragma unroll
        for (int i = tid; i < 128 * 8; i += 256) {
            int r = i >> 3, ch = i & 7;
            int grow = row0 + r;
            if (AFP16) {
                uint4 v = make_uint4(0, 0, 0, 0);
                if (grow < NN)
                    v = *(const uint4*)((const __half*)Av + (size_t)grow * K1 + k0 + ch * 8);
                *(uint4*)(As + SWZ(r * 128 + ch * 16)) = v;
            } else {
                float v[8] = {0.f, 0.f, 0.f, 0.f, 0.f, 0.f, 0.f, 0.f};
                if (grow < NN) {
                    const float* gp = (const float*)Av + (size_t)grow * K1 + k0 + ch * 8;
                    float4 f0 = *(const float4*)gp;
                    float4 f1 = *(const float4*)(gp + 4);
                    v[0] = f0.x; v[1] = f0.y; v[2] = f0.z; v[3] = f0.w;
                    v[4] = f1.x; v[5] = f1.y; v[6] = f1.z; v[7] = f1.w;
                }
                __half2 hh[4];
                #pragma unroll
                for (int q = 0; q < 4; q++) hh[q] = __floats2half2_rn(v[2 * q], v[2 * q + 1]);
                *(uint4*)(As + SWZ(r * 128 + ch * 16)) = *(uint4*)hh;
            }
        }
        #pragma unroll
        for (int i = tid; i < N1 * 8; i += 256) {
            int r = i >> 3, ch = i & 7;
            uint4 w = *(const uint4*)(W1 + (size_t)r * K1 + k0 + ch * 8);
            *(uint4*)(Bs + SWZ(r * 128 + ch * 16)) = w;
        }
        __syncthreads();

        #pragma unroll
        for (int ks = 0; ks < 4; ks++) {
            unsigned a[2][4];
            #pragma unroll
            for (int mt = 0; mt < 2; mt++) {
                int r = wm * 32 + mt * 16 + (lane & 15);
                ldsm_x4(a[mt], as_base + SWZ(r * 128 + ks * 32 + (lane >> 4) * 16));
            }
            #pragma unroll
            for (int nt = 0; nt < NT1; nt++) {
                unsigned b[2];
                int l = lane & 15;
                int r = wn * WN1 + nt * 8 + (l & 7);
                ldsm_x2(b, bs_base + SWZ(r * 128 + ks * 32 + ((l >> 3) & 1) * 16));
                mma_fp16(acc1[0][nt], a[0], b);
                mma_fp16(acc1[1][nt], a[1], b);
            }
        }
        __syncthreads();
    }

    #pragma unroll
    for (int mt = 0; mt < 2; mt++) {
        #pragma unroll
        for (int nt = 0; nt < NT1; nt++) {
            int c = wn * WN1 + nt * 8 + (lane & 3) * 2;
            int panel_off = (c >> 6) * PANEL;
            int kk2 = (c & 63) * 2;
            #pragma unroll
            for (int half = 0; half < 2; half++) {
                int rl = wm * 32 + mt * 16 + (lane >> 2) + half * 8;
                float v0 = sspf(acc1[mt][nt][half * 2 + 0] + b1[c]);
                float v1 = sspf(acc1[mt][nt][half * 2 + 1] + b1[c + 1]);
                __half2 pk = __floats2half2_rn(v0, v1);
                *(unsigned*)(Ts + panel_off + SWZ(rl * 128 + kk2)) = *(unsigned*)&pk;
            }
        }
    }
    __syncthreads();

    float acc2[2][NT2][4];
    #pragma unroll
    for (int mt = 0; mt < 2; mt++)
        #pragma unroll
        for (int nt = 0; nt < NT2; nt++)
            #pragma unroll
            for (int q = 0; q < 4; q++) acc2[mt][nt][q] = 0.f;

    for (int k0 = 0; k0 < N1; k0 += 64) {
        #pragma unroll
        for (int i = tid; i < N2 * 8; i += 256) {
            int r = i >> 3, ch = i & 7;
            uint4 w = *(const uint4*)(W2 + (size_t)r * N1 + k0 + ch * 8);
            *(uint4*)(Bs + SWZ(r * 128 + ch * 16)) = w;
        }
        __syncthreads();

        int panel_off = (k0 >> 6) * PANEL;
        #pragma unroll
        for (int ks = 0; ks < 4; ks++) {
            unsigned a[2][4];
            #pragma unroll
            for (int mt = 0; mt < 2; mt++) {
                int r = wm * 32 + mt * 16 + (lane & 15);
                ldsm_x4(a[mt], ts_base + panel_off + SWZ(r * 128 + ks * 32 + (lane >> 4) * 16));
            }
            #pragma unroll
            for (int nt = 0; nt < NT2; nt++) {
                unsigned b[2];
                int l = lane & 15;
                int r = wn * WN2 + nt * 8 + (l & 7);
                ldsm_x2(b, bs_base + SWZ(r * 128 + ks * 32 + ((l >> 3) & 1) * 16));
                mma_fp16(acc2[0][nt], a[0], b);
                mma_fp16(acc2[1][nt], a[1], b);
            }
        }
        __syncthreads();
    }

    #pragma unroll
    for (int mt = 0; mt < 2; mt++) {
        #pragma unroll
        for (int nt = 0; nt < NT2; nt++) {
            int r = row0 + wm * 32 + mt * 16 + (lane >> 2);
            int c = wn * WN2 + nt * 8 + (lane & 3) * 2;
            epi2<N2, true, false, !POOL2, POOL2, false, !POOL2>(r, c, acc2[mt][nt][0], acc2[mt][nt][1], b2, outh, batch);
            epi2<N2, true, false, !POOL2, POOL2, false, !POOL2>(r + 8, c, acc2[mt][nt][2], acc2[mt][nt][3], b2, outh, batch);
        }
    }
}

// ---------------------------------------------------------------------------
// Fused THREE-GEMM chain (interaction i=0 path)
// ---------------------------------------------------------------------------
__global__ void __launch_bounds__(256, 2)
fused3_kernel(const __half* __restrict__ Av,
              const __half* __restrict__ W1, const float* __restrict__ b1,
              const __half* __restrict__ W2, const float* __restrict__ b2,
              const __half* __restrict__ W3,
              float* __restrict__ outh, __half* __restrict__ xjo) {
    constexpr int NT1 = 8, NT2 = 8, NT3 = 8;
    constexpr int A_B = 16384, B_B = 16384, PANEL = 16384;

    extern __shared__ char dynsm[];
    char* As = dynsm;
    char* Bs = dynsm + A_B;
    char* Ts = dynsm + A_B + B_B;

    int tid = threadIdx.x;
    int warp = tid >> 5, lane = tid & 31;
    int wm = warp & 3, wn = warp >> 2;
    int row0 = blockIdx.x * 128;

    unsigned as_base = smem_u32(As);
    unsigned bs_base = smem_u32(Bs);
    unsigned ts_base = smem_u32(Ts);

    float acc1[2][NT1][4];
    #pragma unroll
    for (int mt = 0; mt < 2; mt++)
        #pragma unroll
        for (int nt = 0; nt < NT1; nt++)
            #pragma unroll
            for (int q = 0; q < 4; q++) acc1[mt][nt][q] = 0.f;

    for (int k0 = 0; k0 < 128; k0 += 64) {
        #pragma unroll
        for (int i = tid; i < 128 * 8; i += 256) {
            int r = i >> 3, ch = i & 7;
            int grow = row0 + r;
            uint4 v = make_uint4(0, 0, 0, 0);
            if (grow < NN)
                v = *(const uint4*)(Av + (size_t)grow * 128 + k0 + ch * 8);
            *(uint4*)(As + SWZ(r * 128 + ch * 16)) = v;
        }
        #pragma unroll
        for (int i = tid; i < 128 * 8; i += 256) {
            int r = i >> 3, ch = i & 7;
            uint4 w = *(const uint4*)(W1 + (size_t)r * 128 + k0 + ch * 8);
            *(uint4*)(Bs + SWZ(r * 128 + ch * 16)) = w;
        }
        __syncthreads();
        #pragma unroll
        for (int ks = 0; ks < 4; ks++) {
            unsigned a[2][4];
            #pragma unroll
            for (int mt = 0; mt < 2; mt++) {
                int r = wm * 32 + mt * 16 + (lane & 15);
                ldsm_x4(a[mt], as_base + SWZ(r * 128 + ks * 32 + (lane >> 4) * 16));
            }
            #pragma unroll
            for (int nt = 0; nt < NT1; nt++) {
                unsigned b[2];
                int l = lane & 15;
                int r = wn * 64 + nt * 8 + (l & 7);
                ldsm_x2(b, bs_base + SWZ(r * 128 + ks * 32 + ((l >> 3) & 1) * 16));
                mma_fp16(acc1[0][nt], a[0], b);
                mma_fp16(acc1[1][nt], a[1], b);
            }
        }
        __syncthreads();
    }

    #pragma unroll
    for (int mt = 0; mt < 2; mt++) {
        #pragma unroll
        for (int nt = 0; nt < NT1; nt++) {
            int c = wn * 64 + nt * 8 + (lane & 3) * 2;
            int panel_off = (c >> 6) * PANEL;
            int kk2 = (c & 63) * 2;
            #pragma unroll
            for (int half = 0; half < 2; half++) {
                int rl = wm * 32 + mt * 16 + (lane >> 2) + half * 8;
                float v0 = sspf(acc1[mt][nt][half * 2 + 0] + b1[c]);
                float v1 = sspf(acc1[mt][nt][half * 2 + 1] + b1[c + 1]);
                __half2 pk = __floats2half2_rn(v0, v1);
                *(unsigned*)(Ts + panel_off + SWZ(rl * 128 + kk2)) = *(unsigned*)&pk;
            }
        }
    }
    __syncthreads();

    float acc2[2][NT2][4];
    #pragma unroll
    for (int mt = 0; mt < 2; mt++)
        #pragma unroll
        for (int nt = 0; nt < NT2; nt++)
            #pragma unroll
            for (int q = 0; q < 4; q++) acc2[mt][nt][q] = 0.f;

    for (int k0 = 0; k0 < 128; k0 += 64) {
        #pragma unroll
        for (int i = tid; i < 128 * 8; i += 256) {
            int r = i >> 3, ch = i & 7;
            uint4 w = *(const uint4*)(W2 + (size_t)r * 128 + k0 + ch * 8);
            *(uint4*)(Bs + SWZ(r * 128 + ch * 16)) = w;
        }
        __syncthreads();
        int panel_off = (k0 >> 6) * PANEL;
        #pragma unroll
        for (int ks = 0; ks < 4; ks++) {
            unsigned a[2][4];
            #pragma unroll
            for (int mt = 0; mt < 2; mt++) {
                int r = wm * 32 + mt * 16 + (lane & 15);
                ldsm_x4(a[mt], ts_base + panel_off + SWZ(r * 128 + ks * 32 + (lane >> 4) * 16));
            }
            #pragma unroll
            for (int nt = 0; nt < NT2; nt++) {
                unsigned b[2];
                int l = lane & 15;
                int r = wn * 64 + nt * 8 + (l & 7);
                ldsm_x2(b, bs_base + SWZ(r * 128 + ks * 32 + ((l >> 3) & 1) * 16));
                mma_fp16(acc2[0][nt], a[0], b);
                mma_fp16(acc2[1][nt], a[1], b);
            }
        }
        __syncthreads();
    }

    // epi 2: hn = h + acc2 + b2 -> write h fp32, stash hn fp16 in Ts
    #pragma unroll
    for (int mt = 0; mt < 2; mt++) {
        #pragma unroll
        for (int nt = 0; nt < NT2; nt++) {
            int c = wn * 64 + nt * 8 + (lane & 3) * 2;
            int panel_off = (c >> 6) * PANEL;
            int kk2 = (c & 63) * 2;
            #pragma unroll
            for (int half = 0; half < 2; half++) {
                int rl = wm * 32 + mt * 16 + (lane >> 2) + half * 8;
                int row = row0 + rl;
                float v0 = acc2[mt][nt][half * 2 + 0] + b2[c];
                float v1 = acc2[mt][nt][half * 2 + 1] + b2[c + 1];
                if (row < NN) {
                    float* o = outh + (size_t)row * 128 + c;
                    float2 hprev = *(float2*)o;
                    v0 += hprev.x; v1 += hprev.y;
                    *(float2*)o = make_float2(v0, v1);
                }
                __half2 pk = __floats2half2_rn(v0, v1);
                *(unsigned*)(Ts + panel_off + SWZ(rl * 128 + kk2)) = *(unsigned*)&pk;
            }
        }
    }
    __syncthreads();

    float acc3[2][NT3][4];
    #pragma unroll
    for (int mt = 0; mt < 2; mt++)
        #pragma unroll
        for (int nt = 0; nt < NT3; nt++)
            #pragma unroll
            for (int q = 0; q < 4; q++) acc3[mt][nt][q] = 0.f;

    for (int k0 = 0; k0 < 128; k0 += 64) {
        #pragma unroll
        for (int i = tid; i < 128 * 8; i += 256) {
            int r = i >> 3, ch = i & 7;
            uint4 w = *(const uint4*)(W3 + (size_t)r * 128 + k0 + ch * 8);
            *(uint4*)(Bs + SWZ(r * 128 + ch * 16)) = w;
        }
        __syncthreads();
        int panel_off = (k0 >> 6) * PANEL;
        #pragma unroll
        for (int ks = 0; ks < 4; ks++) {
            unsigned a[2][4];
            #pragma unroll
            for (int mt = 0; mt < 2; mt++) {
                int r = wm * 32 + mt * 16 + (lane & 15);
                ldsm_x4(a[mt], ts_base + panel_off + SWZ(r * 128 + ks * 32 + (lane >> 4) * 16));
            }
            #pragma unroll
            for (int nt = 0; nt < NT3; nt++) {
                unsigned b[2];
                int l = lane & 15;
                int r = wn * 64 + nt * 8 + (l & 7);
                ldsm_x2(b, bs_base + SWZ(r * 128 + ks * 32 + ((l >> 3) & 1) * 16));
                mma_fp16(acc3[0][nt], a[0], b);
                mma_fp16(acc3[1][nt], a[1], b);
            }
        }
        __syncthreads();
    }

    #pragma unroll
    for (int mt = 0; mt < 2; mt++) {
        #pragma unroll
        for (int nt = 0; nt < NT3; nt++) {
            int r = row0 + wm * 32 + mt * 16 + (lane >> 2);
            int c = wn * 64 + nt * 8 + (lane & 3) * 2;
            #pragma unroll
            for (int half = 0; half < 2; half++) {
                int row = r + half * 8;
                if (row < NN) {
                    __half2 pk = __floats2half2_rn(acc3[mt][nt][half * 2], acc3[mt][nt][half * 2 + 1]);
                    *(unsigned*)(xjo + (size_t)row * 128 + c) = *(unsigned*)&pk;
                }
            }
        }
    }
}

// ---------------------------------------------------------------------------
// Final tiny GEMM
// ---------------------------------------------------------------------------
__global__ void final_kernel(const float* __restrict__ pw, const float* __restrict__ pb,
                             float* __restrict__ out) {
    int tid = threadIdx.x;
    int b = tid >> 2;
    int t = tid & 3;
    float acc = pb[t];
    for (int k = 0; k < HH; k++)
        acc = fmaf(g_pooled[b * HH + k], pw[k * TT + t], acc);
    out[b * TT + t] = acc;
}

// ---------------------------------------------------------------------------
extern "C" void kernel_launch(void* const* d_in, const int* in_sizes, int n_in,
                              void* d_out, int out_size) {
    const int*   z       = (const int*)d_in[0];
    const float* pos     = (const float*)d_in[1];
    const int*   batch   = (const int*)d_in[2];
    const int*   ei      = (const int*)d_in[3];
    const float* emb     = (const float*)d_in[4];
    const float* mlp_w1  = (const float*)d_in[5];
    const float* mlp_b1  = (const float*)d_in[6];
    const float* mlp_w2  = (const float*)d_in[7];
    const float* mlp_b2  = (const float*)d_in[8];
    const float* lin1_w  = (const float*)d_in[9];
    const float* lin2_w  = (const float*)d_in[10];
    const float* lin2_b  = (const float*)d_in[11];
    const float* lin_w   = (const float*)d_in[12];
    const float* lin_b   = (const float*)d_in[13];
    const float* out1_w  = (const float*)d_in[14];
    const float* out1_b  = (const float*)d_in[15];
    const float* out2_w  = (const float*)d_in[16];
    const float* out2_b  = (const float*)d_in[17];
    const float* pred_w  = (const float*)d_in[18];
    const float* pred_b  = (const float*)d_in[19];
    float* out = (float*)d_out;

    float* p_h;
    void *p_xjh, *p_hh, *p_aggh;
    __half* p_wt;
    cudaGetSymbolAddress((void**)&p_h, g_h);
    cudaGetSymbolAddress(&p_hh, g_hh);
    cudaGetSymbolAddress(&p_xjh, g_xjh);
    cudaGetSymbolAddress(&p_aggh, g_aggh);
    cudaGetSymbolAddress((void**)&p_wt, g_wt);

    int dev = 0, smCount = 148;
    cudaGetDevice(&dev);
    cudaDeviceGetAttribute(&smCount, cudaDevAttrMultiProcessorCount, dev);

    static cudaStream_t s_aux = nullptr;
    static cudaEvent_t ev_fork = nullptr, ev_join = nullptr;
    if (!s_aux) {
        cudaStreamCreateWithFlags(&s_aux, cudaStreamNonBlocking);
        cudaEventCreateWithFlags(&ev_fork, cudaEventDisableTiming);
        cudaEventCreateWithFlags(&ev_join, cudaEventDisableTiming);
    }

    const int TAB_SMEM = TAB * 512;                 // 49152
    cudaFuncSetAttribute(edge_conv_csr_kernel, cudaFuncAttributeMaxDynamicSharedMemorySize, TAB_SMEM);

    const int SM_G16 = 65536;
    const int SM_FA  = 16384 + 16384 + 32768;       // 65536
    const int SM_FB  = 16384 + 16384 + 16384;       // 49152
    cudaFuncSetAttribute(mma_gemm16_kernel<128, true>,
                         cudaFuncAttributeMaxDynamicSharedMemorySize, SM_G16);
    cudaFuncSetAttribute(fused3_kernel,
                         cudaFuncAttributeMaxDynamicSharedMemorySize, SM_FA);
    cudaFuncSetAttribute(fused2_kernel<128, 128, 128, false, true>,
                         cudaFuncAttributeMaxDynamicSharedMemorySize, SM_FA);
    cudaFuncSetAttribute(fused2_kernel<128, 64, 128, true, true>,
                         cudaFuncAttributeMaxDynamicSharedMemorySize, SM_FB);

    int gblocks = (NN + 127) / 128;

    // ---- fork: CSR build on aux stream
    cudaEventRecord(ev_fork, 0);
    cudaStreamWaitEvent(s_aux, ev_fork, 0);
    zero_deg_kernel<<<(NN + 255) / 256, 256, 0, s_aux>>>();
    hist_kernel<<<(EE / 4 + 255) / 256, 256, 0, s_aux>>>(ei);
    scan1_kernel<<<NBLK, SCAN_B, 0, s_aux>>>();
    scan3_kernel<<<NBLK, SCAN_B, 0, s_aux>>>();
    fill_kernel<<<(EE / 8 + 255) / 256, 256, 0, s_aux>>>(ei, pos);
    cudaEventRecord(ev_join, s_aux);

    // ---- main stream: prep chain
    dim3 tg(64, 8);
    transpose_all_kernel<<<tg, 256>>>(lin1_w, lin2_w, lin_w, out1_w, out2_w, p_wt);
    prep_kernel<<<(NN * 32 + 255) / 256, 256>>>(z, emb);
    dim3 tb(TAB, 2);
    build_table_kernel<<<tb, HH>>>(mlp_w1, mlp_b1, mlp_w2, mlp_b2);
    mma_gemm16_kernel<128, true><<<gblocks, 256, SM_G16>>>(
        (const __half*)p_hh, p_wt + WT_LIN1(0), p_xjh);

    // ---- join
    cudaStreamWaitEvent(0, ev_join, 0);

    // interaction 0: edge conv + 3-GEMM chain (includes lin1 for interaction 1)
    edge_conv_csr_kernel<<<2 * smCount, 1024, TAB_SMEM>>>(0);
    fused3_kernel<<<gblocks, 256, SM_FA>>>(
        (const __half*)p_aggh,
        p_wt + WT_LIN2(0), lin2_b,
        p_wt + WT_LIN(0),  lin_b,
        p_wt + WT_LIN1(1),
        p_h, (__half*)p_xjh);

    // interaction 1: edge conv + 2-GEMM chain (h update + hh mirror)
    edge_conv_csr_kernel<<<2 * smCount, 1024, TAB_SMEM>>>(1);
    fused2_kernel<128, 128, 128, false, true><<<gblocks, 256, SM_FA>>>(
        p_aggh,
        p_wt + WT_LIN2(1), lin2_b + HH,
        p_wt + WT_LIN(1),  lin_b + HH,
        p_h, nullptr);

    // readout
    fused2_kernel<128, 64, 128, true, true><<<gblocks, 256, SM_FB>>>(
        p_hh,
        p_wt + WT_OUT1, out1_b,
        p_wt + WT_OUT2, out2_b,
        nullptr, batch);
    final_kernel<<<1, 256>>>(pred_w, pred_b, out);
}